// round 5
// baseline (speedup 1.0000x reference)
#include <cuda_runtime.h>
#include <cuda_bf16.h>
#include <math.h>
#include <float.h>
#include <stdint.h>

// Problem constants (fixed by the dataset)
#define NROWS 16384   // B*K = 256*64
#define D_IN  256
#define DB    512
#define NC    1024
#define KTOP  8
#define KSEL  12      // refine candidates
#define TEMP  0.1f

// ---------------- scratch (static device globals; no allocation) -------------
// GEMM1 (z = slots@W): 3-way split, 6 terms -> K' = 1536
// GEMM2 (S = z@E^T):   2-way split, 3 terms -> K' = 1536
__device__ __align__(1024) __nv_bfloat16 g_as[(size_t)NROWS * 1536];
__device__ __align__(1024) __nv_bfloat16 g_wb[(size_t)DB * 1536];
__device__ __align__(1024) __nv_bfloat16 g_zs[(size_t)NROWS * 1536];
__device__ __align__(1024) __nv_bfloat16 g_eb[(size_t)NC * 1536];
__device__ __align__(1024) float g_z[(size_t)NROWS * DB];   // fp32 z (fp32-faithful)
__device__ __align__(1024) float g_S[(size_t)NROWS * NC];   // approx z @ E^T
__device__ float g_enorm[NC];
__device__ float g_usage[NC];
__device__ float g_vq;

// ---------------- helpers -----------------------------------------------------
__device__ __forceinline__ void cp16(void* dst, const void* src) {
    uint32_t d = (uint32_t)__cvta_generic_to_shared(dst);
    asm volatile("cp.async.cg.shared.global [%0], [%1], 16;" :: "r"(d), "l"(src));
}
__device__ __forceinline__ void cp_commit() {
    asm volatile("cp.async.commit_group;" ::: "memory");
}
__device__ __forceinline__ void split2(float v, __nv_bfloat16& hi, __nv_bfloat16& lo) {
    hi = __float2bfloat16(v);
    lo = __float2bfloat16(v - __bfloat162float(hi));
}
__device__ __forceinline__ void split3(float v, __nv_bfloat16& hi, __nv_bfloat16& mid,
                                       __nv_bfloat16& lo) {
    hi = __float2bfloat16(v);
    float r1 = v - __bfloat162float(hi);
    mid = __float2bfloat16(r1);
    lo = __float2bfloat16(r1 - __bfloat162float(mid));
}
__device__ __forceinline__ void mma16816(float* c, const uint32_t* a,
                                         uint32_t b0, uint32_t b1) {
    asm volatile(
        "mma.sync.aligned.m16n8k16.row.col.f32.bf16.bf16.f32 "
        "{%0,%1,%2,%3}, {%4,%5,%6,%7}, {%8,%9}, {%0,%1,%2,%3};"
        : "+f"(c[0]), "+f"(c[1]), "+f"(c[2]), "+f"(c[3])
        : "r"(a[0]), "r"(a[1]), "r"(a[2]), "r"(a[3]), "r"(b0), "r"(b1));
}

// ---------------- pre-kernels: splits + norms ---------------------------------
__global__ void split_slots_kernel(const float* __restrict__ slots) {
    int idx = blockIdx.x * 256 + threadIdx.x;       // < NROWS*D_IN
    int row = idx >> 8, k = idx & 255;
    __nv_bfloat16 hi, mid, lo;
    split3(slots[idx], hi, mid, lo);
    __nv_bfloat16* dst = g_as + (size_t)row * 1536;
    dst[k] = hi;  dst[256 + k] = hi;  dst[512 + k] = mid;
    dst[768 + k] = hi;  dst[1024 + k] = mid;  dst[1280 + k] = lo;
}

__global__ void split_w_kernel(const float* __restrict__ W) {
    int idx = blockIdx.x * 256 + threadIdx.x;       // < D_IN*DB
    int k = idx >> 9, n = idx & 511;                // W[k,n] row-major
    __nv_bfloat16 hi, mid, lo;
    split3(W[idx], hi, mid, lo);
    __nv_bfloat16* dst = g_wb + (size_t)n * 1536;
    dst[k] = hi;  dst[256 + k] = mid;  dst[512 + k] = hi;
    dst[768 + k] = lo;  dst[1024 + k] = mid;  dst[1280 + k] = hi;
}

__global__ void init_kernel(const float* __restrict__ embed) {
    int w = threadIdx.x >> 5, lane = threadIdx.x & 31;
    int code = blockIdx.x * 8 + w;
    if (code < NC) {
        const float* e = embed + (size_t)code * DB;
        __nv_bfloat16* dst = g_eb + (size_t)code * 1536;
        float s = 0.f;
        #pragma unroll
        for (int i = lane; i < DB; i += 32) {
            float v = e[i];
            s += v * v;
            __nv_bfloat16 hi, lo;
            split2(v, hi, lo);
            dst[i] = hi; dst[512 + i] = lo; dst[1024 + i] = hi;
        }
        #pragma unroll
        for (int o = 16; o; o >>= 1) s += __shfl_down_sync(0xffffffffu, s, o);
        if (lane == 0) g_enorm[code] = s;
    }
    if (blockIdx.x == 0) {
        for (int i = threadIdx.x; i < NC; i += blockDim.x) g_usage[i] = 0.f;
        if (threadIdx.x == 0) g_vq = 0.f;
    }
}

// ---------------- bf16 mma.sync GEMM: C[M,N] = A[M,K] * B[N,K]^T ---------------
// Block 128x128, 8 warps (4m x 2n), warp tile 32x64, K-chunk 32, 3-stage cp.async.
// __launch_bounds__(256,2) -> 2 CTAs/SM (occupancy fix for HMMA latency hiding).
// EPI=0: fp32 C. EPI=1: +bias, fp32 C, and bf16 [hi|hi|lo] split rows into Csplit.
#define SM_PITCH 40
#define A_BYTES  (128 * SM_PITCH * 2)    // 10240
#define B_BYTES  (128 * SM_PITCH * 2)    // 10240
#define STAGE    (A_BYTES + B_BYTES)     // 20480
#define NSTAGE   3
#define GEMM_SMEM (NSTAGE * STAGE)       // 61440

template<int KCH, int EPI>
__global__ void __launch_bounds__(256, 2)
tc_gemm(const __nv_bfloat16* __restrict__ A, int lda,
        const __nv_bfloat16* __restrict__ B, int ldb,
        const float* __restrict__ bias,
        float* __restrict__ C, int ldc,
        __nv_bfloat16* __restrict__ Csplit) {
    extern __shared__ __align__(128) char smem[];
    const int tid  = threadIdx.x;
    const int wid  = tid >> 5;
    const int lane = tid & 31;
    const int g    = lane >> 2;      // 0..7
    const int t    = lane & 3;       // 0..3
    const int wm   = wid & 3;        // 0..3  (M: 4 x 32)
    const int wn   = wid >> 2;       // 0..1  (N: 2 x 64)
    const int row0 = blockIdx.y * 128;
    const int col0 = blockIdx.x * 128;

    float acc[2][8][4];
    #pragma unroll
    for (int mi = 0; mi < 2; mi++)
        #pragma unroll
        for (int nj = 0; nj < 8; nj++)
            #pragma unroll
            for (int q = 0; q < 4; q++) acc[mi][nj][q] = 0.f;

    // copy one K-chunk (A: 128x32, B: 128x32) into stage s
    auto do_copy = [&](int c, int s) {
        char* sA = smem + s * STAGE;
        char* sB = sA + A_BYTES;
        const int k0 = c * 32;
        {   // A: 128 rows x 4 x 16B  (512 cp ops, 256 threads x 2)
            int r = tid >> 2, kc = tid & 3;
            cp16(sA + r * (SM_PITCH * 2) + kc * 16,
                 A + (size_t)(row0 + r) * lda + k0 + kc * 8);
            cp16(sB + r * (SM_PITCH * 2) + kc * 16,
                 B + (size_t)(col0 + r) * ldb + k0 + kc * 8);
            int tt = tid + 256;
            int r2 = tt >> 2, kc2 = tt & 3;
            cp16(sA + r2 * (SM_PITCH * 2) + kc2 * 16,
                 A + (size_t)(row0 + r2) * lda + k0 + kc2 * 8);
            cp16(sB + r2 * (SM_PITCH * 2) + kc2 * 16,
                 B + (size_t)(col0 + r2) * ldb + k0 + kc2 * 8);
        }
        cp_commit();
    };

    do_copy(0, 0);
    do_copy(1, 1);
    for (int c = 0; c < KCH; c++) {
        const int s = c % NSTAGE;
        if (c + 2 < KCH) {
            do_copy(c + 2, (c + 2) % NSTAGE);
            asm volatile("cp.async.wait_group 2;" ::: "memory");
        } else if (c + 1 < KCH) {
            asm volatile("cp.async.wait_group 1;" ::: "memory");
        } else {
            asm volatile("cp.async.wait_group 0;" ::: "memory");
        }
        __syncthreads();

        const char* sA = smem + s * STAGE;
        const char* sB = sA + A_BYTES;
        #pragma unroll
        for (int k16 = 0; k16 < 2; k16++) {
            const int kc = k16 * 16 + t * 2;
            uint32_t af[2][4];
            #pragma unroll
            for (int mi = 0; mi < 2; mi++) {
                int row = wm * 32 + mi * 16 + g;
                af[mi][0] = *(const uint32_t*)(sA + (row * SM_PITCH + kc) * 2);
                af[mi][1] = *(const uint32_t*)(sA + ((row + 8) * SM_PITCH + kc) * 2);
                af[mi][2] = *(const uint32_t*)(sA + (row * SM_PITCH + kc + 8) * 2);
                af[mi][3] = *(const uint32_t*)(sA + ((row + 8) * SM_PITCH + kc + 8) * 2);
            }
            #pragma unroll
            for (int nj = 0; nj < 8; nj++) {
                int n = wn * 64 + nj * 8 + g;
                uint32_t b0 = *(const uint32_t*)(sB + (n * SM_PITCH + kc) * 2);
                uint32_t b1 = *(const uint32_t*)(sB + (n * SM_PITCH + kc + 8) * 2);
                #pragma unroll
                for (int mi = 0; mi < 2; mi++)
                    mma16816(acc[mi][nj], af[mi], b0, b1);
            }
        }
        __syncthreads();
    }

    // epilogue
    #pragma unroll
    for (int mi = 0; mi < 2; mi++) {
        #pragma unroll
        for (int nj = 0; nj < 8; nj++) {
            const float* cr = acc[mi][nj];
            int row = row0 + wm * 32 + mi * 16 + g;
            int col = col0 + wn * 64 + nj * 8 + t * 2;
            if (EPI == 0) {
                *(float2*)(C + (size_t)row * ldc + col)       = make_float2(cr[0], cr[1]);
                *(float2*)(C + (size_t)(row + 8) * ldc + col) = make_float2(cr[2], cr[3]);
            } else {
                float bx = bias[col], by = bias[col + 1];
                float v0 = cr[0] + bx, v1 = cr[1] + by;
                float v2 = cr[2] + bx, v3 = cr[3] + by;
                *(float2*)(C + (size_t)row * ldc + col)       = make_float2(v0, v1);
                *(float2*)(C + (size_t)(row + 8) * ldc + col) = make_float2(v2, v3);
                __nv_bfloat16 h0, l0, h1, l1, h2, l2, h3, l3;
                split2(v0, h0, l0); split2(v1, h1, l1);
                split2(v2, h2, l2); split2(v3, h3, l3);
                __nv_bfloat162 hp0 = {h0, h1}, lp0 = {l0, l1};
                __nv_bfloat162 hp1 = {h2, h3}, lp1 = {l2, l3};
                __nv_bfloat16* d0 = Csplit + (size_t)row * 1536 + col;
                __nv_bfloat16* d1 = Csplit + (size_t)(row + 8) * 1536 + col;
                *(__nv_bfloat162*)(d0)        = hp0;
                *(__nv_bfloat162*)(d0 + 512)  = hp0;
                *(__nv_bfloat162*)(d0 + 1024) = lp0;
                *(__nv_bfloat162*)(d1)        = hp1;
                *(__nv_bfloat162*)(d1 + 512)  = hp1;
                *(__nv_bfloat162*)(d1 + 1024) = lp1;
            }
        }
    }
}

// ---------------- per-row: approx select -> exact refine -> outputs ------------
__global__ void __launch_bounds__(256)
topk_kernel(const float* __restrict__ embed, float* __restrict__ out) {
    int w = threadIdx.x >> 5, lane = threadIdx.x & 31;
    int r = blockIdx.x * 8 + w;

    const float4* zr4 = (const float4*)(g_z + (size_t)r * DB);
    float4 zreg[4];
    float zn = 0.f;
    #pragma unroll
    for (int i = 0; i < 4; i++) {
        float4 v = zr4[lane + 32 * i];
        zreg[i] = v;
        zn += v.x * v.x + v.y * v.y + v.z * v.z + v.w * v.w;
    }
    #pragma unroll
    for (int o = 16; o; o >>= 1) zn += __shfl_xor_sync(0xffffffffu, zn, o);

    // --- approx per-lane top-KSEL over d2_approx ---
    float td[KSEL]; int ti[KSEL];
    #pragma unroll
    for (int j = 0; j < KSEL; j++) { td[j] = FLT_MAX; ti[j] = 0x7fffffff; }

    auto insert = [&](float dv, int iv) {
        if (dv < td[KSEL - 1]) {
            #pragma unroll
            for (int j = KSEL - 1; j >= 0; j--) {
                bool shift = (j > 0) && (td[j - 1] > dv);
                if (shift) { td[j] = td[j - 1]; ti[j] = ti[j - 1]; }
                else       { td[j] = dv; ti[j] = iv; break; }
            }
        }
    };

    const float4* Sr4 = (const float4*)(g_S + (size_t)r * NC);
    const float4* en4 = (const float4*)g_enorm;
    #pragma unroll
    for (int it = 0; it < 8; it++) {
        int idx = lane + 32 * it;
        float4 s4 = Sr4[idx];
        float4 e4 = en4[idx];
        int c0 = idx * 4;
        insert(zn + e4.x - 2.f * s4.x, c0 + 0);
        insert(zn + e4.y - 2.f * s4.y, c0 + 1);
        insert(zn + e4.z - 2.f * s4.z, c0 + 2);
        insert(zn + e4.w - 2.f * s4.w, c0 + 3);
    }

    // --- warp merge to KSEL approx candidates (broadcast to all lanes) ---
    int ci[KSEL];
    int pos = 0;
    #pragma unroll
    for (int j = 0; j < KSEL; j++) {
        float cd = (pos < KSEL) ? td[pos] : FLT_MAX;
        int   cc = (pos < KSEL) ? ti[pos] : 0x7fffffff;
        float bd = cd; int bi = cc; int bl = lane;
        #pragma unroll
        for (int o = 16; o; o >>= 1) {
            float od = __shfl_xor_sync(0xffffffffu, bd, o);
            int   oi = __shfl_xor_sync(0xffffffffu, bi, o);
            int   ol = __shfl_xor_sync(0xffffffffu, bl, o);
            if (od < bd || (od == bd && oi < bi)) { bd = od; bi = oi; bl = ol; }
        }
        ci[j] = bi;
        if (lane == bl) pos++;
    }

    // --- exact fp32 refine: d2 = ||z||^2 + ||e||^2 - 2 z.e ---
    float xd[KSEL];
    #pragma unroll
    for (int j = 0; j < KSEL; j++) {
        const float4* ev = (const float4*)(embed + (size_t)ci[j] * DB);
        float dot = 0.f;
        #pragma unroll
        for (int i = 0; i < 4; i++) {
            float4 f = ev[lane + 32 * i];
            dot += zreg[i].x * f.x + zreg[i].y * f.y
                 + zreg[i].z * f.z + zreg[i].w * f.w;
        }
        #pragma unroll
        for (int o = 16; o; o >>= 1) dot += __shfl_xor_sync(0xffffffffu, dot, o);
        xd[j] = zn + g_enorm[ci[j]] - 2.f * dot;
    }

    // --- bubble sort (all lanes identical) ---
    #pragma unroll
    for (int a = 0; a < KSEL - 1; a++) {
        #pragma unroll
        for (int b = 0; b < KSEL - 1 - a; b++) {
            bool sw = (xd[b + 1] < xd[b]) ||
                      (xd[b + 1] == xd[b] && ci[b + 1] < ci[b]);
            if (sw) {
                float tf = xd[b]; xd[b] = xd[b + 1]; xd[b + 1] = tf;
                int   tn = ci[b]; ci[b] = ci[b + 1]; ci[b + 1] = tn;
            }
        }
    }

    // --- softmax over exact sqrt(d2) of top-8 ---
    float wj[KTOP];
    float vmin = sqrtf(fmaxf(xd[0], 0.f));
    float wsum = 0.f;
    #pragma unroll
    for (int j = 0; j < KTOP; j++) {
        float v = sqrtf(fmaxf(xd[j], 0.f));
        wj[j] = expf(-(v - vmin) / TEMP);
        wsum += wj[j];
    }
    float inv = 1.f / wsum;
    #pragma unroll
    for (int j = 0; j < KTOP; j++) wj[j] *= inv;

    // --- q gather + vq partial ---
    float vql = 0.f;
    #pragma unroll
    for (int i = 0; i < 4; i++) {
        int c4 = lane + 32 * i;
        float4 a = make_float4(0.f, 0.f, 0.f, 0.f);
        #pragma unroll
        for (int j = 0; j < KTOP; j++) {
            const float4* ev = (const float4*)(embed + (size_t)ci[j] * DB);
            float4 f = ev[c4];
            a.x += wj[j] * f.x; a.y += wj[j] * f.y;
            a.z += wj[j] * f.z; a.w += wj[j] * f.w;
        }
        ((float4*)(out + (size_t)r * DB))[c4] = a;
        float dx = zreg[i].x - a.x, dy = zreg[i].y - a.y;
        float dz = zreg[i].z - a.z, dw = zreg[i].w - a.w;
        vql += dx * dx + dy * dy + dz * dz + dw * dw;
    }
    #pragma unroll
    for (int o = 16; o; o >>= 1) vql += __shfl_down_sync(0xffffffffu, vql, o);
    if (lane == 0) atomicAdd(&g_vq, vql);
    if (lane < KTOP) atomicAdd(&g_usage[ci[lane]], wj[lane]);
    if (lane == 0) out[(size_t)NROWS * DB + r] = (float)ci[0];
}

// ---------------- finalize scalars --------------------------------------------
__global__ void finalize_kernel(float* __restrict__ out) {
    __shared__ float sh[256];
    float s = 0.f;
    for (int c = threadIdx.x; c < NC; c += 256) {
        float u = g_usage[c] * (1.f / (float)NROWS);
        s += u * logf(u + 1e-8f);
    }
    sh[threadIdx.x] = s;
    __syncthreads();
    for (int o = 128; o; o >>= 1) {
        if (threadIdx.x < o) sh[threadIdx.x] += sh[threadIdx.x + o];
        __syncthreads();
    }
    if (threadIdx.x == 0) {
        size_t base = (size_t)NROWS * DB + NROWS;
        out[base + 0] = g_vq * (1.f / (float)((size_t)NROWS * DB));
        out[base + 1] = -sh[0];
    }
}

// ---------------- launch --------------------------------------------------------
extern "C" void kernel_launch(void* const* d_in, const int* in_sizes, int n_in,
                              void* d_out, int out_size) {
    const float* slots = (const float*)d_in[0];
    const float* W     = (const float*)d_in[1];
    const float* bias  = (const float*)d_in[2];
    const float* embed = (const float*)d_in[3];
    float* out = (float*)d_out;

    float *zp = nullptr, *Sp = nullptr;
    __nv_bfloat16 *asp = nullptr, *wbp = nullptr, *zsp = nullptr, *ebp = nullptr;
    cudaGetSymbolAddress((void**)&zp,  g_z);
    cudaGetSymbolAddress((void**)&Sp,  g_S);
    cudaGetSymbolAddress((void**)&asp, g_as);
    cudaGetSymbolAddress((void**)&wbp, g_wb);
    cudaGetSymbolAddress((void**)&zsp, g_zs);
    cudaGetSymbolAddress((void**)&ebp, g_eb);

    cudaFuncSetAttribute(tc_gemm<48, 1>,
                         cudaFuncAttributeMaxDynamicSharedMemorySize, GEMM_SMEM);
    cudaFuncSetAttribute(tc_gemm<48, 0>,
                         cudaFuncAttributeMaxDynamicSharedMemorySize, GEMM_SMEM);

    split_slots_kernel<<<(NROWS * D_IN) / 256, 256>>>(slots);
    split_w_kernel<<<(D_IN * DB) / 256, 256>>>(W);
    init_kernel<<<128, 256>>>(embed);

    // z = slots @ W + b : A'=[16384,1536], B'=[512,1536] -> fp32 z + split z
    tc_gemm<48, 1><<<dim3(4, 128), 256, GEMM_SMEM>>>(
        asp, 1536, wbp, 1536, bias, zp, 512, zsp);

    // S ~= z @ E^T : A'=[16384,1536], B'=[1024,1536] -> approx fp32 S
    tc_gemm<48, 0><<<dim3(8, 128), 256, GEMM_SMEM>>>(
        zsp, 1536, ebp, 1536, nullptr, Sp, 1024, nullptr);

    topk_kernel<<<NROWS / 8, 256>>>(embed, out);
    finalize_kernel<<<1, 256>>>(out);
}

// round 6
// speedup vs baseline: 1.4998x; 1.4998x over previous
#include <cuda_runtime.h>
#include <cuda_bf16.h>
#include <math.h>
#include <float.h>
#include <stdint.h>

// Problem constants (fixed by the dataset)
#define NROWS 16384   // B*K = 256*64
#define D_IN  256
#define DB    512
#define NC    1024
#define KTOP  8
#define KSEL  12      // refine candidates
#define TEMP  0.1f

// ---------------- scratch (static device globals; no allocation) -------------
// GEMM1 (z = slots@W): 3-way split, 6 terms -> K' = 1536
// GEMM2 (S = z@E^T):   2-way split, 3 terms -> K' = 1536
__device__ __align__(1024) __nv_bfloat16 g_as[(size_t)NROWS * 1536];
__device__ __align__(1024) __nv_bfloat16 g_wb[(size_t)DB * 1536];
__device__ __align__(1024) __nv_bfloat16 g_zs[(size_t)NROWS * 1536];
__device__ __align__(1024) __nv_bfloat16 g_eb[(size_t)NC * 1536];
__device__ __align__(1024) float g_z[(size_t)NROWS * DB];   // fp32 z (fp32-faithful)
__device__ __align__(1024) float g_S[(size_t)NROWS * NC];   // approx z @ E^T
__device__ float g_enorm[NC];
__device__ float g_usage[NC];
__device__ float g_vq;

// ---------------- helpers -----------------------------------------------------
__device__ __forceinline__ void cp16(void* dst, const void* src) {
    uint32_t d = (uint32_t)__cvta_generic_to_shared(dst);
    asm volatile("cp.async.cg.shared.global [%0], [%1], 16;" :: "r"(d), "l"(src));
}
__device__ __forceinline__ void cp_commit() {
    asm volatile("cp.async.commit_group;" ::: "memory");
}
__device__ __forceinline__ void split2(float v, __nv_bfloat16& hi, __nv_bfloat16& lo) {
    hi = __float2bfloat16(v);
    lo = __float2bfloat16(v - __bfloat162float(hi));
}
__device__ __forceinline__ void split3(float v, __nv_bfloat16& hi, __nv_bfloat16& mid,
                                       __nv_bfloat16& lo) {
    hi = __float2bfloat16(v);
    float r1 = v - __bfloat162float(hi);
    mid = __float2bfloat16(r1);
    lo = __float2bfloat16(r1 - __bfloat162float(mid));
}
__device__ __forceinline__ void mma16816(float* c, const uint32_t* a,
                                         uint32_t b0, uint32_t b1) {
    asm volatile(
        "mma.sync.aligned.m16n8k16.row.col.f32.bf16.bf16.f32 "
        "{%0,%1,%2,%3}, {%4,%5,%6,%7}, {%8,%9}, {%0,%1,%2,%3};"
        : "+f"(c[0]), "+f"(c[1]), "+f"(c[2]), "+f"(c[3])
        : "r"(a[0]), "r"(a[1]), "r"(a[2]), "r"(a[3]), "r"(b0), "r"(b1));
}
__device__ __forceinline__ void ldsm4(uint32_t* r, uint32_t addr) {
    asm volatile("ldmatrix.sync.aligned.m8n8.x4.shared.b16 {%0,%1,%2,%3}, [%4];"
        : "=r"(r[0]), "=r"(r[1]), "=r"(r[2]), "=r"(r[3]) : "r"(addr));
}

// ---------------- pre-kernels: splits + norms ---------------------------------
__global__ void split_slots_kernel(const float* __restrict__ slots) {
    int idx = blockIdx.x * 256 + threadIdx.x;       // < NROWS*D_IN
    int row = idx >> 8, k = idx & 255;
    __nv_bfloat16 hi, mid, lo;
    split3(slots[idx], hi, mid, lo);
    __nv_bfloat16* dst = g_as + (size_t)row * 1536;
    dst[k] = hi;  dst[256 + k] = hi;  dst[512 + k] = mid;
    dst[768 + k] = hi;  dst[1024 + k] = mid;  dst[1280 + k] = lo;
}

__global__ void split_w_kernel(const float* __restrict__ W) {
    int idx = blockIdx.x * 256 + threadIdx.x;       // < D_IN*DB
    int k = idx >> 9, n = idx & 511;                // W[k,n] row-major
    __nv_bfloat16 hi, mid, lo;
    split3(W[idx], hi, mid, lo);
    __nv_bfloat16* dst = g_wb + (size_t)n * 1536;
    dst[k] = hi;  dst[256 + k] = mid;  dst[512 + k] = hi;
    dst[768 + k] = lo;  dst[1024 + k] = mid;  dst[1280 + k] = hi;
}

__global__ void init_kernel(const float* __restrict__ embed) {
    int w = threadIdx.x >> 5, lane = threadIdx.x & 31;
    int code = blockIdx.x * 8 + w;
    if (code < NC) {
        const float* e = embed + (size_t)code * DB;
        __nv_bfloat16* dst = g_eb + (size_t)code * 1536;
        float s = 0.f;
        #pragma unroll
        for (int i = lane; i < DB; i += 32) {
            float v = e[i];
            s += v * v;
            __nv_bfloat16 hi, lo;
            split2(v, hi, lo);
            dst[i] = hi; dst[512 + i] = lo; dst[1024 + i] = hi;
        }
        #pragma unroll
        for (int o = 16; o; o >>= 1) s += __shfl_down_sync(0xffffffffu, s, o);
        if (lane == 0) g_enorm[code] = s;
    }
    if (blockIdx.x == 0) {
        for (int i = threadIdx.x; i < NC; i += blockDim.x) g_usage[i] = 0.f;
        if (threadIdx.x == 0) g_vq = 0.f;
    }
}

// ---------------- bf16 mma.sync GEMM: C[M,N] = A[M,K] * B[N,K]^T ---------------
// Block 128x256, 8 warps (2m x 4n), warp tile 64x64, K-chunk 32, double buffer.
// Fragments loaded via ldmatrix.x4 (16 LDSM per chunk vs 64 scalar LDS).
// smem pitch 40 bf16 (80B): LDSM atom rows hit disjoint bank quads.
// EPI=0: fp32 C. EPI=1: +bias, fp32 C, and bf16 [hi|hi|lo] split rows into Csplit.
#define SM_PITCH 40
#define A_BYTES  (128 * SM_PITCH * 2)    // 10240
#define B_BYTES  (256 * SM_PITCH * 2)    // 20480
#define STAGE    (A_BYTES + B_BYTES)     // 30720
#define GEMM_SMEM (2 * STAGE)            // 61440

template<int KCH, int EPI>
__global__ void __launch_bounds__(256)
tc_gemm(const __nv_bfloat16* __restrict__ A, int lda,
        const __nv_bfloat16* __restrict__ B, int ldb,
        const float* __restrict__ bias,
        float* __restrict__ C, int ldc,
        __nv_bfloat16* __restrict__ Csplit) {
    extern __shared__ __align__(128) char smem[];
    const uint32_t sbase = (uint32_t)__cvta_generic_to_shared(smem);
    const int tid  = threadIdx.x;
    const int wid  = tid >> 5;
    const int lane = tid & 31;
    const int g    = lane >> 2;      // 0..7
    const int t    = lane & 3;       // 0..3
    const int wm   = wid & 1;        // 0..1 (M: 2 x 64)
    const int wn   = wid >> 1;       // 0..3 (N: 4 x 64)
    const int row0 = blockIdx.y * 128;
    const int col0 = blockIdx.x * 256;
    const int r8   = lane & 7;       // ldmatrix row within atom
    const int sub  = lane >> 3;      // ldmatrix atom id 0..3

    float acc[4][8][4];
    #pragma unroll
    for (int mi = 0; mi < 4; mi++)
        #pragma unroll
        for (int nj = 0; nj < 8; nj++)
            #pragma unroll
            for (int q = 0; q < 4; q++) acc[mi][nj][q] = 0.f;

    auto do_copy = [&](int c, int s) {
        char* sA = smem + s * STAGE;
        char* sB = sA + A_BYTES;
        const int k0 = c * 32;
        #pragma unroll
        for (int i = 0; i < 6; i++) {
            int tt = tid + 256 * i;
            if (tt < 512) {                       // A: 128 rows x 4 x 16B
                int r = tt >> 2, kc = tt & 3;
                cp16(sA + r * (SM_PITCH * 2) + kc * 16,
                     A + (size_t)(row0 + r) * lda + k0 + kc * 8);
            } else {                              // B: 256 rows x 4 x 16B
                int u = tt - 512;
                int r = u >> 2, kc = u & 3;
                cp16(sB + r * (SM_PITCH * 2) + kc * 16,
                     B + (size_t)(col0 + r) * ldb + k0 + kc * 8);
            }
        }
        cp_commit();
    };

    do_copy(0, 0);
    for (int c = 0; c < KCH; c++) {
        const int s = c & 1;
        if (c + 1 < KCH) {
            do_copy(c + 1, s ^ 1);
            asm volatile("cp.async.wait_group 1;" ::: "memory");
        } else {
            asm volatile("cp.async.wait_group 0;" ::: "memory");
        }
        __syncthreads();

        const uint32_t sAu = sbase + s * STAGE;
        const uint32_t sBu = sAu + A_BYTES;
        #pragma unroll
        for (int k16 = 0; k16 < 2; k16++) {
            // A fragments: 4 x 16x16 tiles via ldmatrix.x4
            // atoms: 0=(r,k) 1=(r+8,k) 2=(r,k+8) 3=(r+8,k+8) -> matches mma a-frag
            uint32_t af[4][4];
            {
                int arow = wm * 64 + (sub & 1) * 8 + r8;
                int akc  = k16 * 16 + (sub >> 1) * 8;
                #pragma unroll
                for (int mi = 0; mi < 4; mi++)
                    ldsm4(af[mi], sAu + ((arow + mi * 16) * SM_PITCH + akc) * 2);
            }
            // B fragments: 4 x (16n x 16k) tiles; atoms 0=(n,k) 1=(n,k+8)
            // 2=(n+8,k) 3=(n+8,k+8) -> (r0,r1)=frag nj even, (r2,r3)=frag nj odd
            uint32_t bf[4][4];
            {
                int bn  = wn * 64 + (sub >> 1) * 8 + r8;
                int bkc = k16 * 16 + (sub & 1) * 8;
                #pragma unroll
                for (int nj2 = 0; nj2 < 4; nj2++)
                    ldsm4(bf[nj2], sBu + ((bn + nj2 * 16) * SM_PITCH + bkc) * 2);
            }
            #pragma unroll
            for (int nj2 = 0; nj2 < 4; nj2++) {
                #pragma unroll
                for (int mi = 0; mi < 4; mi++) {
                    mma16816(acc[mi][2 * nj2],     af[mi], bf[nj2][0], bf[nj2][1]);
                    mma16816(acc[mi][2 * nj2 + 1], af[mi], bf[nj2][2], bf[nj2][3]);
                }
            }
        }
        __syncthreads();
    }

    // epilogue
    #pragma unroll
    for (int mi = 0; mi < 4; mi++) {
        #pragma unroll
        for (int nj = 0; nj < 8; nj++) {
            const float* cr = acc[mi][nj];
            int row = row0 + wm * 64 + mi * 16 + g;
            int col = col0 + wn * 64 + nj * 8 + t * 2;
            if (EPI == 0) {
                *(float2*)(C + (size_t)row * ldc + col)       = make_float2(cr[0], cr[1]);
                *(float2*)(C + (size_t)(row + 8) * ldc + col) = make_float2(cr[2], cr[3]);
            } else {
                float bx = bias[col], by = bias[col + 1];
                float v0 = cr[0] + bx, v1 = cr[1] + by;
                float v2 = cr[2] + bx, v3 = cr[3] + by;
                *(float2*)(C + (size_t)row * ldc + col)       = make_float2(v0, v1);
                *(float2*)(C + (size_t)(row + 8) * ldc + col) = make_float2(v2, v3);
                __nv_bfloat16 h0, l0, h1, l1, h2, l2, h3, l3;
                split2(v0, h0, l0); split2(v1, h1, l1);
                split2(v2, h2, l2); split2(v3, h3, l3);
                __nv_bfloat162 hp0 = {h0, h1}, lp0 = {l0, l1};
                __nv_bfloat162 hp1 = {h2, h3}, lp1 = {l2, l3};
                __nv_bfloat16* d0 = Csplit + (size_t)row * 1536 + col;
                __nv_bfloat16* d1 = Csplit + (size_t)(row + 8) * 1536 + col;
                *(__nv_bfloat162*)(d0)        = hp0;
                *(__nv_bfloat162*)(d0 + 512)  = hp0;
                *(__nv_bfloat162*)(d0 + 1024) = lp0;
                *(__nv_bfloat162*)(d1)        = hp1;
                *(__nv_bfloat162*)(d1 + 512)  = hp1;
                *(__nv_bfloat162*)(d1 + 1024) = lp1;
            }
        }
    }
}

// ---------------- per-row: approx select -> exact refine -> outputs ------------
__global__ void __launch_bounds__(256)
topk_kernel(const float* __restrict__ embed, float* __restrict__ out) {
    int w = threadIdx.x >> 5, lane = threadIdx.x & 31;
    int r = blockIdx.x * 8 + w;

    const float4* zr4 = (const float4*)(g_z + (size_t)r * DB);
    float4 zreg[4];
    float zn = 0.f;
    #pragma unroll
    for (int i = 0; i < 4; i++) {
        float4 v = zr4[lane + 32 * i];
        zreg[i] = v;
        zn += v.x * v.x + v.y * v.y + v.z * v.z + v.w * v.w;
    }
    #pragma unroll
    for (int o = 16; o; o >>= 1) zn += __shfl_xor_sync(0xffffffffu, zn, o);

    // --- approx per-lane top-KSEL over d2_approx ---
    float td[KSEL]; int ti[KSEL];
    #pragma unroll
    for (int j = 0; j < KSEL; j++) { td[j] = FLT_MAX; ti[j] = 0x7fffffff; }

    auto insert = [&](float dv, int iv) {
        if (dv < td[KSEL - 1]) {
            #pragma unroll
            for (int j = KSEL - 1; j >= 0; j--) {
                bool shift = (j > 0) && (td[j - 1] > dv);
                if (shift) { td[j] = td[j - 1]; ti[j] = ti[j - 1]; }
                else       { td[j] = dv; ti[j] = iv; break; }
            }
        }
    };

    const float4* Sr4 = (const float4*)(g_S + (size_t)r * NC);
    const float4* en4 = (const float4*)g_enorm;
    #pragma unroll
    for (int it = 0; it < 8; it++) {
        int idx = lane + 32 * it;
        float4 s4 = Sr4[idx];
        float4 e4 = en4[idx];
        int c0 = idx * 4;
        insert(zn + e4.x - 2.f * s4.x, c0 + 0);
        insert(zn + e4.y - 2.f * s4.y, c0 + 1);
        insert(zn + e4.z - 2.f * s4.z, c0 + 2);
        insert(zn + e4.w - 2.f * s4.w, c0 + 3);
    }

    // --- warp merge to KSEL approx candidates (broadcast to all lanes) ---
    int ci[KSEL];
    int pos = 0;
    #pragma unroll
    for (int j = 0; j < KSEL; j++) {
        float cd = (pos < KSEL) ? td[pos] : FLT_MAX;
        int   cc = (pos < KSEL) ? ti[pos] : 0x7fffffff;
        float bd = cd; int bi = cc; int bl = lane;
        #pragma unroll
        for (int o = 16; o; o >>= 1) {
            float od = __shfl_xor_sync(0xffffffffu, bd, o);
            int   oi = __shfl_xor_sync(0xffffffffu, bi, o);
            int   ol = __shfl_xor_sync(0xffffffffu, bl, o);
            if (od < bd || (od == bd && oi < bi)) { bd = od; bi = oi; bl = ol; }
        }
        ci[j] = bi;
        if (lane == bl) pos++;
    }

    // --- exact fp32 refine: d2 = ||z||^2 + ||e||^2 - 2 z.e ---
    float xd[KSEL];
    #pragma unroll
    for (int j = 0; j < KSEL; j++) {
        const float4* ev = (const float4*)(embed + (size_t)ci[j] * DB);
        float dot = 0.f;
        #pragma unroll
        for (int i = 0; i < 4; i++) {
            float4 f = ev[lane + 32 * i];
            dot += zreg[i].x * f.x + zreg[i].y * f.y
                 + zreg[i].z * f.z + zreg[i].w * f.w;
        }
        #pragma unroll
        for (int o = 16; o; o >>= 1) dot += __shfl_xor_sync(0xffffffffu, dot, o);
        xd[j] = zn + g_enorm[ci[j]] - 2.f * dot;
    }

    // --- bubble sort (all lanes identical) ---
    #pragma unroll
    for (int a = 0; a < KSEL - 1; a++) {
        #pragma unroll
        for (int b = 0; b < KSEL - 1 - a; b++) {
            bool sw = (xd[b + 1] < xd[b]) ||
                      (xd[b + 1] == xd[b] && ci[b + 1] < ci[b]);
            if (sw) {
                float tf = xd[b]; xd[b] = xd[b + 1]; xd[b + 1] = tf;
                int   tn = ci[b]; ci[b] = ci[b + 1]; ci[b + 1] = tn;
            }
        }
    }

    // --- softmax over exact sqrt(d2) of top-8 ---
    float wj[KTOP];
    float vmin = sqrtf(fmaxf(xd[0], 0.f));
    float wsum = 0.f;
    #pragma unroll
    for (int j = 0; j < KTOP; j++) {
        float v = sqrtf(fmaxf(xd[j], 0.f));
        wj[j] = expf(-(v - vmin) / TEMP);
        wsum += wj[j];
    }
    float inv = 1.f / wsum;
    #pragma unroll
    for (int j = 0; j < KTOP; j++) wj[j] *= inv;

    // --- q gather + vq partial ---
    float vql = 0.f;
    #pragma unroll
    for (int i = 0; i < 4; i++) {
        int c4 = lane + 32 * i;
        float4 a = make_float4(0.f, 0.f, 0.f, 0.f);
        #pragma unroll
        for (int j = 0; j < KTOP; j++) {
            const float4* ev = (const float4*)(embed + (size_t)ci[j] * DB);
            float4 f = ev[c4];
            a.x += wj[j] * f.x; a.y += wj[j] * f.y;
            a.z += wj[j] * f.z; a.w += wj[j] * f.w;
        }
        ((float4*)(out + (size_t)r * DB))[c4] = a;
        float dx = zreg[i].x - a.x, dy = zreg[i].y - a.y;
        float dz = zreg[i].z - a.z, dw = zreg[i].w - a.w;
        vql += dx * dx + dy * dy + dz * dz + dw * dw;
    }
    #pragma unroll
    for (int o = 16; o; o >>= 1) vql += __shfl_down_sync(0xffffffffu, vql, o);
    if (lane == 0) atomicAdd(&g_vq, vql);
    if (lane < KTOP) atomicAdd(&g_usage[ci[lane]], wj[lane]);
    if (lane == 0) out[(size_t)NROWS * DB + r] = (float)ci[0];
}

// ---------------- finalize scalars --------------------------------------------
__global__ void finalize_kernel(float* __restrict__ out) {
    __shared__ float sh[256];
    float s = 0.f;
    for (int c = threadIdx.x; c < NC; c += 256) {
        float u = g_usage[c] * (1.f / (float)NROWS);
        s += u * logf(u + 1e-8f);
    }
    sh[threadIdx.x] = s;
    __syncthreads();
    for (int o = 128; o; o >>= 1) {
        if (threadIdx.x < o) sh[threadIdx.x] += sh[threadIdx.x + o];
        __syncthreads();
    }
    if (threadIdx.x == 0) {
        size_t base = (size_t)NROWS * DB + NROWS;
        out[base + 0] = g_vq * (1.f / (float)((size_t)NROWS * DB));
        out[base + 1] = -sh[0];
    }
}

// ---------------- launch --------------------------------------------------------
extern "C" void kernel_launch(void* const* d_in, const int* in_sizes, int n_in,
                              void* d_out, int out_size) {
    const float* slots = (const float*)d_in[0];
    const float* W     = (const float*)d_in[1];
    const float* bias  = (const float*)d_in[2];
    const float* embed = (const float*)d_in[3];
    float* out = (float*)d_out;

    float *zp = nullptr, *Sp = nullptr;
    __nv_bfloat16 *asp = nullptr, *wbp = nullptr, *zsp = nullptr, *ebp = nullptr;
    cudaGetSymbolAddress((void**)&zp,  g_z);
    cudaGetSymbolAddress((void**)&Sp,  g_S);
    cudaGetSymbolAddress((void**)&asp, g_as);
    cudaGetSymbolAddress((void**)&wbp, g_wb);
    cudaGetSymbolAddress((void**)&zsp, g_zs);
    cudaGetSymbolAddress((void**)&ebp, g_eb);

    cudaFuncSetAttribute(tc_gemm<48, 1>,
                         cudaFuncAttributeMaxDynamicSharedMemorySize, GEMM_SMEM);
    cudaFuncSetAttribute(tc_gemm<48, 0>,
                         cudaFuncAttributeMaxDynamicSharedMemorySize, GEMM_SMEM);

    split_slots_kernel<<<(NROWS * D_IN) / 256, 256>>>(slots);
    split_w_kernel<<<(D_IN * DB) / 256, 256>>>(W);
    init_kernel<<<128, 256>>>(embed);

    // z = slots @ W + b : A'=[16384,1536], B'=[512,1536] -> fp32 z + split z
    tc_gemm<48, 1><<<dim3(2, 128), 256, GEMM_SMEM>>>(
        asp, 1536, wbp, 1536, bias, zp, 512, zsp);

    // S ~= z @ E^T : A'=[16384,1536], B'=[1024,1536] -> approx fp32 S
    tc_gemm<48, 0><<<dim3(4, 128), 256, GEMM_SMEM>>>(
        zsp, 1536, ebp, 1536, nullptr, Sp, 1024, nullptr);

    topk_kernel<<<NROWS / 8, 256>>>(embed, out);
    finalize_kernel<<<1, 256>>>(out);
}

// round 7
// speedup vs baseline: 1.7507x; 1.1673x over previous
#include <cuda_runtime.h>
#include <cuda_bf16.h>
#include <math.h>
#include <float.h>
#include <stdint.h>

// Problem constants (fixed by the dataset)
#define NROWS 16384   // B*K = 256*64
#define D_IN  256
#define DB    512
#define NC    1024
#define KTOP  8
#define KSEL  12      // refine candidates
#define TEMP  0.1f

// ---------------- scratch (static device globals; no allocation) -------------
// GEMM1 (z = slots@W): 3-way split, 6 terms -> K' = 1536 (fp32-faithful z)
// GEMM2 (S ~= z@E^T):  2 terms -> K' = 1024 (selection only; refined exactly)
__device__ __align__(1024) __nv_bfloat16 g_as[(size_t)NROWS * 1536];
__device__ __align__(1024) __nv_bfloat16 g_wb[(size_t)DB * 1536];
__device__ __align__(1024) __nv_bfloat16 g_zs[(size_t)NROWS * 1024];  // [z_hi|z_lo]
__device__ __align__(1024) __nv_bfloat16 g_eb[(size_t)NC * 1024];     // [e_hi|e_hi]
__device__ __align__(1024) float g_z[(size_t)NROWS * DB];   // fp32 z
__device__ __align__(1024) float g_S[(size_t)NROWS * NC];   // approx z @ E^T
__device__ float g_enorm[NC];
__device__ float g_usage[NC];
__device__ float g_vq;

// ---------------- helpers -----------------------------------------------------
__device__ __forceinline__ void cp16(void* dst, const void* src) {
    uint32_t d = (uint32_t)__cvta_generic_to_shared(dst);
    asm volatile("cp.async.cg.shared.global [%0], [%1], 16;" :: "r"(d), "l"(src));
}
__device__ __forceinline__ void cp_commit() {
    asm volatile("cp.async.commit_group;" ::: "memory");
}
__device__ __forceinline__ void split2(float v, __nv_bfloat16& hi, __nv_bfloat16& lo) {
    hi = __float2bfloat16(v);
    lo = __float2bfloat16(v - __bfloat162float(hi));
}
__device__ __forceinline__ void split3(float v, __nv_bfloat16& hi, __nv_bfloat16& mid,
                                       __nv_bfloat16& lo) {
    hi = __float2bfloat16(v);
    float r1 = v - __bfloat162float(hi);
    mid = __float2bfloat16(r1);
    lo = __float2bfloat16(r1 - __bfloat162float(mid));
}
__device__ __forceinline__ void mma16816(float* c, const uint32_t* a,
                                         uint32_t b0, uint32_t b1) {
    asm volatile(
        "mma.sync.aligned.m16n8k16.row.col.f32.bf16.bf16.f32 "
        "{%0,%1,%2,%3}, {%4,%5,%6,%7}, {%8,%9}, {%0,%1,%2,%3};"
        : "+f"(c[0]), "+f"(c[1]), "+f"(c[2]), "+f"(c[3])
        : "r"(a[0]), "r"(a[1]), "r"(a[2]), "r"(a[3]), "r"(b0), "r"(b1));
}
__device__ __forceinline__ void ldsm4(uint32_t* r, uint32_t addr) {
    asm volatile("ldmatrix.sync.aligned.m8n8.x4.shared.b16 {%0,%1,%2,%3}, [%4];"
        : "=r"(r[0]), "=r"(r[1]), "=r"(r[2]), "=r"(r[3]) : "r"(addr));
}

// ---------------- pre-kernels: splits + norms ---------------------------------
__global__ void split_slots_kernel(const float* __restrict__ slots) {
    int idx = blockIdx.x * 256 + threadIdx.x;       // < NROWS*D_IN
    int row = idx >> 8, k = idx & 255;
    __nv_bfloat16 hi, mid, lo;
    split3(slots[idx], hi, mid, lo);
    __nv_bfloat16* dst = g_as + (size_t)row * 1536;
    dst[k] = hi;  dst[256 + k] = hi;  dst[512 + k] = mid;
    dst[768 + k] = hi;  dst[1024 + k] = mid;  dst[1280 + k] = lo;
}

__global__ void split_w_kernel(const float* __restrict__ W) {
    int idx = blockIdx.x * 256 + threadIdx.x;       // < D_IN*DB
    int k = idx >> 9, n = idx & 511;                // W[k,n] row-major
    __nv_bfloat16 hi, mid, lo;
    split3(W[idx], hi, mid, lo);
    __nv_bfloat16* dst = g_wb + (size_t)n * 1536;
    dst[k] = hi;  dst[256 + k] = mid;  dst[512 + k] = hi;
    dst[768 + k] = lo;  dst[1024 + k] = mid;  dst[1280 + k] = hi;
}

__global__ void init_kernel(const float* __restrict__ embed) {
    int w = threadIdx.x >> 5, lane = threadIdx.x & 31;
    int code = blockIdx.x * 8 + w;
    if (code < NC) {
        const float* e = embed + (size_t)code * DB;
        __nv_bfloat16* dst = g_eb + (size_t)code * 1024;
        float s = 0.f;
        #pragma unroll
        for (int i = lane; i < DB; i += 32) {
            float v = e[i];
            s += v * v;
            __nv_bfloat16 hi = __float2bfloat16(v);
            dst[i] = hi; dst[512 + i] = hi;
        }
        #pragma unroll
        for (int o = 16; o; o >>= 1) s += __shfl_down_sync(0xffffffffu, s, o);
        if (lane == 0) g_enorm[code] = s;
    }
    if (blockIdx.x == 0) {
        for (int i = threadIdx.x; i < NC; i += blockDim.x) g_usage[i] = 0.f;
        if (threadIdx.x == 0) g_vq = 0.f;
    }
}

// ---------------- bf16 mma.sync GEMM: C[M,N] = A[M,K] * B[N,K]^T ---------------
// Block 128x256, 8 warps (2m x 4n), warp tile 64x64, K-chunk 32, double buffer.
// Fragments via ldmatrix.x4; smem pitch 40 bf16 -> conflict-free LDSM.
// EPI=0: fp32 C. EPI=1: +bias, fp32 C, and bf16 [hi|lo] split rows into Csplit.
#define SM_PITCH 40
#define A_BYTES  (128 * SM_PITCH * 2)    // 10240
#define B_BYTES  (256 * SM_PITCH * 2)    // 20480
#define STAGE    (A_BYTES + B_BYTES)     // 30720
#define GEMM_SMEM (2 * STAGE)            // 61440

template<int KCH, int EPI>
__global__ void __launch_bounds__(256)
tc_gemm(const __nv_bfloat16* __restrict__ A, int lda,
        const __nv_bfloat16* __restrict__ B, int ldb,
        const float* __restrict__ bias,
        float* __restrict__ C, int ldc,
        __nv_bfloat16* __restrict__ Csplit) {
    extern __shared__ __align__(128) char smem[];
    const uint32_t sbase = (uint32_t)__cvta_generic_to_shared(smem);
    const int tid  = threadIdx.x;
    const int wid  = tid >> 5;
    const int lane = tid & 31;
    const int g    = lane >> 2;      // 0..7
    const int t    = lane & 3;       // 0..3
    const int wm   = wid & 1;        // 0..1 (M: 2 x 64)
    const int wn   = wid >> 1;       // 0..3 (N: 4 x 64)
    const int row0 = blockIdx.y * 128;
    const int col0 = blockIdx.x * 256;
    const int r8   = lane & 7;       // ldmatrix row within atom
    const int sub  = lane >> 3;      // ldmatrix atom id 0..3

    float acc[4][8][4];
    #pragma unroll
    for (int mi = 0; mi < 4; mi++)
        #pragma unroll
        for (int nj = 0; nj < 8; nj++)
            #pragma unroll
            for (int q = 0; q < 4; q++) acc[mi][nj][q] = 0.f;

    auto do_copy = [&](int c, int s) {
        char* sA = smem + s * STAGE;
        char* sB = sA + A_BYTES;
        const int k0 = c * 32;
        #pragma unroll
        for (int i = 0; i < 6; i++) {
            int tt = tid + 256 * i;
            if (tt < 512) {                       // A: 128 rows x 4 x 16B
                int r = tt >> 2, kc = tt & 3;
                cp16(sA + r * (SM_PITCH * 2) + kc * 16,
                     A + (size_t)(row0 + r) * lda + k0 + kc * 8);
            } else {                              // B: 256 rows x 4 x 16B
                int u = tt - 512;
                int r = u >> 2, kc = u & 3;
                cp16(sB + r * (SM_PITCH * 2) + kc * 16,
                     B + (size_t)(col0 + r) * ldb + k0 + kc * 8);
            }
        }
        cp_commit();
    };

    do_copy(0, 0);
    for (int c = 0; c < KCH; c++) {
        const int s = c & 1;
        if (c + 1 < KCH) {
            do_copy(c + 1, s ^ 1);
            asm volatile("cp.async.wait_group 1;" ::: "memory");
        } else {
            asm volatile("cp.async.wait_group 0;" ::: "memory");
        }
        __syncthreads();

        const uint32_t sAu = sbase + s * STAGE;
        const uint32_t sBu = sAu + A_BYTES;
        #pragma unroll
        for (int k16 = 0; k16 < 2; k16++) {
            uint32_t af[4][4];
            {
                int arow = wm * 64 + (sub & 1) * 8 + r8;
                int akc  = k16 * 16 + (sub >> 1) * 8;
                #pragma unroll
                for (int mi = 0; mi < 4; mi++)
                    ldsm4(af[mi], sAu + ((arow + mi * 16) * SM_PITCH + akc) * 2);
            }
            uint32_t bf[4][4];
            {
                int bn  = wn * 64 + (sub >> 1) * 8 + r8;
                int bkc = k16 * 16 + (sub & 1) * 8;
                #pragma unroll
                for (int nj2 = 0; nj2 < 4; nj2++)
                    ldsm4(bf[nj2], sBu + ((bn + nj2 * 16) * SM_PITCH + bkc) * 2);
            }
            #pragma unroll
            for (int nj2 = 0; nj2 < 4; nj2++) {
                #pragma unroll
                for (int mi = 0; mi < 4; mi++) {
                    mma16816(acc[mi][2 * nj2],     af[mi], bf[nj2][0], bf[nj2][1]);
                    mma16816(acc[mi][2 * nj2 + 1], af[mi], bf[nj2][2], bf[nj2][3]);
                }
            }
        }
        __syncthreads();
    }

    // epilogue
    #pragma unroll
    for (int mi = 0; mi < 4; mi++) {
        #pragma unroll
        for (int nj = 0; nj < 8; nj++) {
            const float* cr = acc[mi][nj];
            int row = row0 + wm * 64 + mi * 16 + g;
            int col = col0 + wn * 64 + nj * 8 + t * 2;
            if (EPI == 0) {
                *(float2*)(C + (size_t)row * ldc + col)       = make_float2(cr[0], cr[1]);
                *(float2*)(C + (size_t)(row + 8) * ldc + col) = make_float2(cr[2], cr[3]);
            } else {
                float bx = bias[col], by = bias[col + 1];
                float v0 = cr[0] + bx, v1 = cr[1] + by;
                float v2 = cr[2] + bx, v3 = cr[3] + by;
                *(float2*)(C + (size_t)row * ldc + col)       = make_float2(v0, v1);
                *(float2*)(C + (size_t)(row + 8) * ldc + col) = make_float2(v2, v3);
                __nv_bfloat16 h0, l0, h1, l1, h2, l2, h3, l3;
                split2(v0, h0, l0); split2(v1, h1, l1);
                split2(v2, h2, l2); split2(v3, h3, l3);
                __nv_bfloat162 hp0 = {h0, h1}, lp0 = {l0, l1};
                __nv_bfloat162 hp1 = {h2, h3}, lp1 = {l2, l3};
                __nv_bfloat16* d0 = Csplit + (size_t)row * 1024 + col;
                __nv_bfloat16* d1 = Csplit + (size_t)(row + 8) * 1024 + col;
                *(__nv_bfloat162*)(d0)       = hp0;
                *(__nv_bfloat162*)(d0 + 512) = lp0;
                *(__nv_bfloat162*)(d1)       = hp1;
                *(__nv_bfloat162*)(d1 + 512) = lp1;
            }
        }
    }
}

// ---------------- per-row: approx select -> exact refine -> outputs ------------
__global__ void __launch_bounds__(256)
topk_kernel(const float* __restrict__ embed, float* __restrict__ out) {
    int w = threadIdx.x >> 5, lane = threadIdx.x & 31;
    int r = blockIdx.x * 8 + w;

    const float4* zr4 = (const float4*)(g_z + (size_t)r * DB);
    float4 zreg[4];
    float zn = 0.f;
    #pragma unroll
    for (int i = 0; i < 4; i++) {
        float4 v = zr4[lane + 32 * i];
        zreg[i] = v;
        zn += v.x * v.x + v.y * v.y + v.z * v.z + v.w * v.w;
    }
    #pragma unroll
    for (int o = 16; o; o >>= 1) zn += __shfl_xor_sync(0xffffffffu, zn, o);

    // --- approx per-lane top-KSEL; packed key = (f32bits(d2) << 32) | idx ---
    unsigned long long td[KSEL];
    #pragma unroll
    for (int j = 0; j < KSEL; j++) td[j] = ~0ULL;

    auto insert = [&](float dv, int iv) {
        unsigned long long key =
            ((unsigned long long)__float_as_uint(dv) << 32) | (unsigned)iv;
        if (key < td[KSEL - 1]) {
            #pragma unroll
            for (int j = KSEL - 1; j >= 0; j--) {
                bool shift = (j > 0) && (td[j - 1] > key);
                if (shift) td[j] = td[j - 1];
                else       { td[j] = key; break; }
            }
        }
    };

    const float4* Sr4 = (const float4*)(g_S + (size_t)r * NC);
    const float4* en4 = (const float4*)g_enorm;
    #pragma unroll
    for (int it = 0; it < 8; it++) {
        int idx = lane + 32 * it;
        float4 s4 = Sr4[idx];
        float4 e4 = en4[idx];
        int c0 = idx * 4;
        insert(zn + e4.x - 2.f * s4.x, c0 + 0);
        insert(zn + e4.y - 2.f * s4.y, c0 + 1);
        insert(zn + e4.z - 2.f * s4.z, c0 + 2);
        insert(zn + e4.w - 2.f * s4.w, c0 + 3);
    }

    // --- warp merge: 12 rounds of packed u64 min (keys unique via idx) ---
    int ci[KSEL];
    int pos = 0;
    #pragma unroll
    for (int j = 0; j < KSEL; j++) {
        unsigned long long cur = (pos < KSEL) ? td[pos] : ~0ULL;
        unsigned long long best = cur;
        #pragma unroll
        for (int o = 16; o; o >>= 1) {
            unsigned long long ob = __shfl_xor_sync(0xffffffffu, best, o);
            best = (ob < best) ? ob : best;
        }
        ci[j] = (int)(best & 0xFFFFFFFFu);
        if (cur == best) pos++;
    }

    // --- exact fp32 refine: accumulate all 12 dots, then reduce (12-way ILP) ---
    float dot[KSEL];
    #pragma unroll
    for (int j = 0; j < KSEL; j++) dot[j] = 0.f;
    #pragma unroll
    for (int i = 0; i < 4; i++) {
        int c4 = lane + 32 * i;
        float4 zv = zreg[i];
        #pragma unroll
        for (int j = 0; j < KSEL; j++) {
            float4 f = ((const float4*)(embed + (size_t)ci[j] * DB))[c4];
            dot[j] += zv.x * f.x + zv.y * f.y + zv.z * f.z + zv.w * f.w;
        }
    }
    #pragma unroll
    for (int o = 16; o; o >>= 1) {
        #pragma unroll
        for (int j = 0; j < KSEL; j++)
            dot[j] += __shfl_xor_sync(0xffffffffu, dot[j], o);
    }
    float xd[KSEL];
    #pragma unroll
    for (int j = 0; j < KSEL; j++) xd[j] = zn + g_enorm[ci[j]] - 2.f * dot[j];

    // --- bubble sort (all lanes identical; tie -> smaller index) ---
    #pragma unroll
    for (int a = 0; a < KSEL - 1; a++) {
        #pragma unroll
        for (int b = 0; b < KSEL - 1 - a; b++) {
            bool sw = (xd[b + 1] < xd[b]) ||
                      (xd[b + 1] == xd[b] && ci[b + 1] < ci[b]);
            if (sw) {
                float tf = xd[b]; xd[b] = xd[b + 1]; xd[b + 1] = tf;
                int   tn = ci[b]; ci[b] = ci[b + 1]; ci[b + 1] = tn;
            }
        }
    }

    // --- softmax over exact sqrt(d2) of top-8 ---
    float wj[KTOP];
    float vmin = sqrtf(fmaxf(xd[0], 0.f));
    float wsum = 0.f;
    #pragma unroll
    for (int j = 0; j < KTOP; j++) {
        float v = sqrtf(fmaxf(xd[j], 0.f));
        wj[j] = expf(-(v - vmin) / TEMP);
        wsum += wj[j];
    }
    float inv = 1.f / wsum;
    #pragma unroll
    for (int j = 0; j < KTOP; j++) wj[j] *= inv;

    // --- q gather + vq partial ---
    float vql = 0.f;
    #pragma unroll
    for (int i = 0; i < 4; i++) {
        int c4 = lane + 32 * i;
        float4 a = make_float4(0.f, 0.f, 0.f, 0.f);
        #pragma unroll
        for (int j = 0; j < KTOP; j++) {
            const float4* ev = (const float4*)(embed + (size_t)ci[j] * DB);
            float4 f = ev[c4];
            a.x += wj[j] * f.x; a.y += wj[j] * f.y;
            a.z += wj[j] * f.z; a.w += wj[j] * f.w;
        }
        ((float4*)(out + (size_t)r * DB))[c4] = a;
        float dx = zreg[i].x - a.x, dy = zreg[i].y - a.y;
        float dz = zreg[i].z - a.z, dw = zreg[i].w - a.w;
        vql += dx * dx + dy * dy + dz * dz + dw * dw;
    }
    #pragma unroll
    for (int o = 16; o; o >>= 1) vql += __shfl_down_sync(0xffffffffu, vql, o);
    if (lane == 0) atomicAdd(&g_vq, vql);
    if (lane < KTOP) atomicAdd(&g_usage[ci[lane]], wj[lane]);
    if (lane == 0) out[(size_t)NROWS * DB + r] = (float)ci[0];
}

// ---------------- finalize scalars --------------------------------------------
__global__ void finalize_kernel(float* __restrict__ out) {
    __shared__ float sh[256];
    float s = 0.f;
    for (int c = threadIdx.x; c < NC; c += 256) {
        float u = g_usage[c] * (1.f / (float)NROWS);
        s += u * logf(u + 1e-8f);
    }
    sh[threadIdx.x] = s;
    __syncthreads();
    for (int o = 128; o; o >>= 1) {
        if (threadIdx.x < o) sh[threadIdx.x] += sh[threadIdx.x + o];
        __syncthreads();
    }
    if (threadIdx.x == 0) {
        size_t base = (size_t)NROWS * DB + NROWS;
        out[base + 0] = g_vq * (1.f / (float)((size_t)NROWS * DB));
        out[base + 1] = -sh[0];
    }
}

// ---------------- launch --------------------------------------------------------
extern "C" void kernel_launch(void* const* d_in, const int* in_sizes, int n_in,
                              void* d_out, int out_size) {
    const float* slots = (const float*)d_in[0];
    const float* W     = (const float*)d_in[1];
    const float* bias  = (const float*)d_in[2];
    const float* embed = (const float*)d_in[3];
    float* out = (float*)d_out;

    float *zp = nullptr, *Sp = nullptr;
    __nv_bfloat16 *asp = nullptr, *wbp = nullptr, *zsp = nullptr, *ebp = nullptr;
    cudaGetSymbolAddress((void**)&zp,  g_z);
    cudaGetSymbolAddress((void**)&Sp,  g_S);
    cudaGetSymbolAddress((void**)&asp, g_as);
    cudaGetSymbolAddress((void**)&wbp, g_wb);
    cudaGetSymbolAddress((void**)&zsp, g_zs);
    cudaGetSymbolAddress((void**)&ebp, g_eb);

    cudaFuncSetAttribute(tc_gemm<48, 1>,
                         cudaFuncAttributeMaxDynamicSharedMemorySize, GEMM_SMEM);
    cudaFuncSetAttribute(tc_gemm<32, 0>,
                         cudaFuncAttributeMaxDynamicSharedMemorySize, GEMM_SMEM);

    split_slots_kernel<<<(NROWS * D_IN) / 256, 256>>>(slots);
    split_w_kernel<<<(D_IN * DB) / 256, 256>>>(W);
    init_kernel<<<128, 256>>>(embed);

    // z = slots @ W + b : A'=[16384,1536], B'=[512,1536] -> fp32 z + split2 z
    tc_gemm<48, 1><<<dim3(2, 128), 256, GEMM_SMEM>>>(
        asp, 1536, wbp, 1536, bias, zp, 512, zsp);

    // S ~= z @ E^T : A'=[16384,1024], B'=[1024,1024] -> approx fp32 S
    tc_gemm<32, 0><<<dim3(4, 128), 256, GEMM_SMEM>>>(
        zsp, 1024, ebp, 1024, nullptr, Sp, 1024, nullptr);

    topk_kernel<<<NROWS / 8, 256>>>(embed, out);
    finalize_kernel<<<1, 256>>>(out);
}

// round 8
// speedup vs baseline: 2.4021x; 1.3721x over previous
#include <cuda_runtime.h>
#include <cuda_bf16.h>
#include <math.h>
#include <float.h>
#include <stdint.h>

// Problem constants (fixed by the dataset)
#define NROWS 16384   // B*K = 256*64
#define D_IN  256
#define DB    512
#define NC    1024
#define KTOP  8
#define KSEL  12      // refine candidates
#define TEMP  0.1f

// ---------------- scratch (static device globals; no allocation) -------------
// GEMM1 (z = slots@W): 3-way split, 6 terms -> K' = 1536 (fp32-faithful z)
// GEMM2 (d2 ~= ||z-e||^2): single term z_hi . e_hi, K = 512 (selection only)
__device__ __align__(1024) __nv_bfloat16 g_as[(size_t)NROWS * 1536];
__device__ __align__(1024) __nv_bfloat16 g_wb[(size_t)DB * 1536];
__device__ __align__(1024) __nv_bfloat16 g_zs[(size_t)NROWS * 512];  // z_hi
__device__ __align__(1024) __nv_bfloat16 g_eb[(size_t)NC * 512];     // e_hi
__device__ __align__(1024) float g_z[(size_t)NROWS * DB];   // fp32 z
__device__ __align__(1024) float g_D2[(size_t)NROWS * NC];  // approx d^2
__device__ float g_zn[NROWS];
__device__ float g_enorm[NC];
__device__ float g_usage[NC];
__device__ float g_vq;

// ---------------- helpers -----------------------------------------------------
__device__ __forceinline__ void cp16(void* dst, const void* src) {
    uint32_t d = (uint32_t)__cvta_generic_to_shared(dst);
    asm volatile("cp.async.cg.shared.global [%0], [%1], 16;" :: "r"(d), "l"(src));
}
__device__ __forceinline__ void cp_commit() {
    asm volatile("cp.async.commit_group;" ::: "memory");
}
__device__ __forceinline__ void split2(float v, __nv_bfloat16& hi, __nv_bfloat16& lo) {
    hi = __float2bfloat16(v);
    lo = __float2bfloat16(v - __bfloat162float(hi));
}
__device__ __forceinline__ void split3(float v, __nv_bfloat16& hi, __nv_bfloat16& mid,
                                       __nv_bfloat16& lo) {
    hi = __float2bfloat16(v);
    float r1 = v - __bfloat162float(hi);
    mid = __float2bfloat16(r1);
    lo = __float2bfloat16(r1 - __bfloat162float(mid));
}
__device__ __forceinline__ void mma16816(float* c, const uint32_t* a,
                                         uint32_t b0, uint32_t b1) {
    asm volatile(
        "mma.sync.aligned.m16n8k16.row.col.f32.bf16.bf16.f32 "
        "{%0,%1,%2,%3}, {%4,%5,%6,%7}, {%8,%9}, {%0,%1,%2,%3};"
        : "+f"(c[0]), "+f"(c[1]), "+f"(c[2]), "+f"(c[3])
        : "r"(a[0]), "r"(a[1]), "r"(a[2]), "r"(a[3]), "r"(b0), "r"(b1));
}
__device__ __forceinline__ void ldsm4(uint32_t* r, uint32_t addr) {
    asm volatile("ldmatrix.sync.aligned.m8n8.x4.shared.b16 {%0,%1,%2,%3}, [%4];"
        : "=r"(r[0]), "=r"(r[1]), "=r"(r[2]), "=r"(r[3]) : "r"(addr));
}

// ---------------- pre-kernels: splits + norms ---------------------------------
__global__ void split_slots_kernel(const float* __restrict__ slots) {
    int idx = blockIdx.x * 256 + threadIdx.x;       // < NROWS*D_IN
    int row = idx >> 8, k = idx & 255;
    __nv_bfloat16 hi, mid, lo;
    split3(slots[idx], hi, mid, lo);
    __nv_bfloat16* dst = g_as + (size_t)row * 1536;
    dst[k] = hi;  dst[256 + k] = hi;  dst[512 + k] = mid;
    dst[768 + k] = hi;  dst[1024 + k] = mid;  dst[1280 + k] = lo;
}

__global__ void split_w_kernel(const float* __restrict__ W) {
    int idx = blockIdx.x * 256 + threadIdx.x;       // < D_IN*DB
    int k = idx >> 9, n = idx & 511;                // W[k,n] row-major
    __nv_bfloat16 hi, mid, lo;
    split3(W[idx], hi, mid, lo);
    __nv_bfloat16* dst = g_wb + (size_t)n * 1536;
    dst[k] = hi;  dst[256 + k] = mid;  dst[512 + k] = hi;
    dst[768 + k] = lo;  dst[1024 + k] = mid;  dst[1280 + k] = hi;
}

__global__ void init_kernel(const float* __restrict__ embed) {
    int w = threadIdx.x >> 5, lane = threadIdx.x & 31;
    int code = blockIdx.x * 8 + w;
    if (code < NC) {
        const float* e = embed + (size_t)code * DB;
        __nv_bfloat16* dst = g_eb + (size_t)code * 512;
        float s = 0.f;
        #pragma unroll
        for (int i = lane; i < DB; i += 32) {
            float v = e[i];
            s += v * v;
            dst[i] = __float2bfloat16(v);
        }
        #pragma unroll
        for (int o = 16; o; o >>= 1) s += __shfl_down_sync(0xffffffffu, s, o);
        if (lane == 0) g_enorm[code] = s;
    }
    if (blockIdx.x == 0) {
        for (int i = threadIdx.x; i < NC; i += blockDim.x) g_usage[i] = 0.f;
        if (threadIdx.x == 0) g_vq = 0.f;
    }
}

// row norms of fp32 z (feeds GEMM2's d2 epilogue)
__global__ void znorm_kernel() {
    int w = threadIdx.x >> 5, lane = threadIdx.x & 31;
    int r = blockIdx.x * 8 + w;
    const float4* zr4 = (const float4*)(g_z + (size_t)r * DB);
    float s = 0.f;
    #pragma unroll
    for (int i = 0; i < 4; i++) {
        float4 v = zr4[lane + 32 * i];
        s += v.x * v.x + v.y * v.y + v.z * v.z + v.w * v.w;
    }
    #pragma unroll
    for (int o = 16; o; o >>= 1) s += __shfl_down_sync(0xffffffffu, s, o);
    if (lane == 0) g_zn[r] = s;
}

// ---------------- bf16 mma.sync GEMM: C[M,N] = A[M,K] * B[N,K]^T ---------------
// Block 128x256, 8 warps (2m x 4n), warp tile 64x64, K-chunk 32, double buffer.
// EPI=1: +bias, fp32 C, bf16 hi rows into Csplit.
// EPI=2: write approx d2 = zn[row] + enorm[col] - 2*acc into C.
#define SM_PITCH 40
#define A_BYTES  (128 * SM_PITCH * 2)    // 10240
#define B_BYTES  (256 * SM_PITCH * 2)    // 20480
#define STAGE    (A_BYTES + B_BYTES)     // 30720
#define GEMM_SMEM (2 * STAGE)            // 61440

template<int KCH, int EPI>
__global__ void __launch_bounds__(256)
tc_gemm(const __nv_bfloat16* __restrict__ A, int lda,
        const __nv_bfloat16* __restrict__ B, int ldb,
        const float* __restrict__ bias,
        float* __restrict__ C, int ldc,
        __nv_bfloat16* __restrict__ Csplit,
        const float* __restrict__ zn) {
    extern __shared__ __align__(128) char smem[];
    const uint32_t sbase = (uint32_t)__cvta_generic_to_shared(smem);
    const int tid  = threadIdx.x;
    const int wid  = tid >> 5;
    const int lane = tid & 31;
    const int g    = lane >> 2;      // 0..7
    const int t    = lane & 3;       // 0..3
    const int wm   = wid & 1;        // 0..1 (M: 2 x 64)
    const int wn   = wid >> 1;       // 0..3 (N: 4 x 64)
    const int row0 = blockIdx.y * 128;
    const int col0 = blockIdx.x * 256;
    const int r8   = lane & 7;       // ldmatrix row within atom
    const int sub  = lane >> 3;      // ldmatrix atom id 0..3

    float acc[4][8][4];
    #pragma unroll
    for (int mi = 0; mi < 4; mi++)
        #pragma unroll
        for (int nj = 0; nj < 8; nj++)
            #pragma unroll
            for (int q = 0; q < 4; q++) acc[mi][nj][q] = 0.f;

    auto do_copy = [&](int c, int s) {
        char* sA = smem + s * STAGE;
        char* sB = sA + A_BYTES;
        const int k0 = c * 32;
        #pragma unroll
        for (int i = 0; i < 6; i++) {
            int tt = tid + 256 * i;
            if (tt < 512) {                       // A: 128 rows x 4 x 16B
                int r = tt >> 2, kc = tt & 3;
                cp16(sA + r * (SM_PITCH * 2) + kc * 16,
                     A + (size_t)(row0 + r) * lda + k0 + kc * 8);
            } else {                              // B: 256 rows x 4 x 16B
                int u = tt - 512;
                int r = u >> 2, kc = u & 3;
                cp16(sB + r * (SM_PITCH * 2) + kc * 16,
                     B + (size_t)(col0 + r) * ldb + k0 + kc * 8);
            }
        }
        cp_commit();
    };

    do_copy(0, 0);
    for (int c = 0; c < KCH; c++) {
        const int s = c & 1;
        if (c + 1 < KCH) {
            do_copy(c + 1, s ^ 1);
            asm volatile("cp.async.wait_group 1;" ::: "memory");
        } else {
            asm volatile("cp.async.wait_group 0;" ::: "memory");
        }
        __syncthreads();

        const uint32_t sAu = sbase + s * STAGE;
        const uint32_t sBu = sAu + A_BYTES;
        #pragma unroll
        for (int k16 = 0; k16 < 2; k16++) {
            uint32_t af[4][4];
            {
                int arow = wm * 64 + (sub & 1) * 8 + r8;
                int akc  = k16 * 16 + (sub >> 1) * 8;
                #pragma unroll
                for (int mi = 0; mi < 4; mi++)
                    ldsm4(af[mi], sAu + ((arow + mi * 16) * SM_PITCH + akc) * 2);
            }
            uint32_t bf[4][4];
            {
                int bn  = wn * 64 + (sub >> 1) * 8 + r8;
                int bkc = k16 * 16 + (sub & 1) * 8;
                #pragma unroll
                for (int nj2 = 0; nj2 < 4; nj2++)
                    ldsm4(bf[nj2], sBu + ((bn + nj2 * 16) * SM_PITCH + bkc) * 2);
            }
            #pragma unroll
            for (int nj2 = 0; nj2 < 4; nj2++) {
                #pragma unroll
                for (int mi = 0; mi < 4; mi++) {
                    mma16816(acc[mi][2 * nj2],     af[mi], bf[nj2][0], bf[nj2][1]);
                    mma16816(acc[mi][2 * nj2 + 1], af[mi], bf[nj2][2], bf[nj2][3]);
                }
            }
        }
        __syncthreads();
    }

    // epilogue
    if (EPI == 2) {
        float znr[4][2];
        #pragma unroll
        for (int mi = 0; mi < 4; mi++) {
            int row = row0 + wm * 64 + mi * 16 + g;
            znr[mi][0] = __ldg(&zn[row]);
            znr[mi][1] = __ldg(&zn[row + 8]);
        }
        float en0[8], en1[8];
        #pragma unroll
        for (int nj = 0; nj < 8; nj++) {
            int col = col0 + wn * 64 + nj * 8 + t * 2;
            en0[nj] = g_enorm[col];
            en1[nj] = g_enorm[col + 1];
        }
        #pragma unroll
        for (int mi = 0; mi < 4; mi++) {
            #pragma unroll
            for (int nj = 0; nj < 8; nj++) {
                const float* cr = acc[mi][nj];
                int row = row0 + wm * 64 + mi * 16 + g;
                int col = col0 + wn * 64 + nj * 8 + t * 2;
                *(float2*)(C + (size_t)row * ldc + col) =
                    make_float2(znr[mi][0] + en0[nj] - 2.f * cr[0],
                                znr[mi][0] + en1[nj] - 2.f * cr[1]);
                *(float2*)(C + (size_t)(row + 8) * ldc + col) =
                    make_float2(znr[mi][1] + en0[nj] - 2.f * cr[2],
                                znr[mi][1] + en1[nj] - 2.f * cr[3]);
            }
        }
    } else {
        #pragma unroll
        for (int mi = 0; mi < 4; mi++) {
            #pragma unroll
            for (int nj = 0; nj < 8; nj++) {
                const float* cr = acc[mi][nj];
                int row = row0 + wm * 64 + mi * 16 + g;
                int col = col0 + wn * 64 + nj * 8 + t * 2;
                float bx = bias[col], by = bias[col + 1];
                float v0 = cr[0] + bx, v1 = cr[1] + by;
                float v2 = cr[2] + bx, v3 = cr[3] + by;
                *(float2*)(C + (size_t)row * ldc + col)       = make_float2(v0, v1);
                *(float2*)(C + (size_t)(row + 8) * ldc + col) = make_float2(v2, v3);
                __nv_bfloat162 hp0 = {__float2bfloat16(v0), __float2bfloat16(v1)};
                __nv_bfloat162 hp1 = {__float2bfloat16(v2), __float2bfloat16(v3)};
                *(__nv_bfloat162*)(Csplit + (size_t)row * 512 + col)       = hp0;
                *(__nv_bfloat162*)(Csplit + (size_t)(row + 8) * 512 + col) = hp1;
            }
        }
    }
}

// ---------------- per-row: approx select -> exact refine -> outputs ------------
__global__ void __launch_bounds__(256)
topk_kernel(const float* __restrict__ embed, float* __restrict__ out) {
    int w = threadIdx.x >> 5, lane = threadIdx.x & 31;
    int r = blockIdx.x * 8 + w;

    const float4* zr4 = (const float4*)(g_z + (size_t)r * DB);
    float4 zreg[4];
    float zn = 0.f;
    #pragma unroll
    for (int i = 0; i < 4; i++) {
        float4 v = zr4[lane + 32 * i];
        zreg[i] = v;
        zn += v.x * v.x + v.y * v.y + v.z * v.z + v.w * v.w;
    }
    #pragma unroll
    for (int o = 16; o; o >>= 1) zn += __shfl_xor_sync(0xffffffffu, zn, o);

    // --- approx per-lane top-KSEL; u32 key = (f32bits(d2) & ~1023) | idx ---
    uint32_t td[KSEL];
    #pragma unroll
    for (int j = 0; j < KSEL; j++) td[j] = 0xFFFFFFFFu;

    auto insert = [&](float dv, int iv) {
        uint32_t key = (__float_as_uint(fmaxf(dv, 0.f)) & 0xFFFFFC00u) | (unsigned)iv;
        if (key < td[KSEL - 1]) {
            #pragma unroll
            for (int j = KSEL - 1; j >= 0; j--) {
                bool shift = (j > 0) && (td[j - 1] > key);
                if (shift) td[j] = td[j - 1];
                else       { td[j] = key; break; }
            }
        }
    };

    const float4* Dr4 = (const float4*)(g_D2 + (size_t)r * NC);
    #pragma unroll
    for (int it = 0; it < 8; it++) {
        int idx = lane + 32 * it;
        float4 d4 = Dr4[idx];
        int c0 = idx * 4;
        insert(d4.x, c0 + 0);
        insert(d4.y, c0 + 1);
        insert(d4.z, c0 + 2);
        insert(d4.w, c0 + 3);
    }

    // --- warp merge: 12 rounds of u32 min (keys unique via idx bits) ---
    int ci[KSEL];
    int pos = 0;
    #pragma unroll
    for (int j = 0; j < KSEL; j++) {
        uint32_t cur = (pos < KSEL) ? td[pos] : 0xFFFFFFFFu;
        uint32_t best = cur;
        #pragma unroll
        for (int o = 16; o; o >>= 1)
            best = min(best, __shfl_xor_sync(0xffffffffu, best, o));
        ci[j] = (int)(best & 1023u);
        if (cur == best) pos++;
    }

    // --- exact fp32 refine: accumulate all 12 dots, then reduce (12-way ILP) ---
    float dot[KSEL];
    #pragma unroll
    for (int j = 0; j < KSEL; j++) dot[j] = 0.f;
    #pragma unroll
    for (int i = 0; i < 4; i++) {
        int c4 = lane + 32 * i;
        float4 zv = zreg[i];
        #pragma unroll
        for (int j = 0; j < KSEL; j++) {
            float4 f = ((const float4*)(embed + (size_t)ci[j] * DB))[c4];
            dot[j] += zv.x * f.x + zv.y * f.y + zv.z * f.z + zv.w * f.w;
        }
    }
    #pragma unroll
    for (int o = 16; o; o >>= 1) {
        #pragma unroll
        for (int j = 0; j < KSEL; j++)
            dot[j] += __shfl_xor_sync(0xffffffffu, dot[j], o);
    }
    float xd[KSEL];
    #pragma unroll
    for (int j = 0; j < KSEL; j++) xd[j] = zn + g_enorm[ci[j]] - 2.f * dot[j];

    // --- bubble sort (all lanes identical; tie -> smaller index) ---
    #pragma unroll
    for (int a = 0; a < KSEL - 1; a++) {
        #pragma unroll
        for (int b = 0; b < KSEL - 1 - a; b++) {
            bool sw = (xd[b + 1] < xd[b]) ||
                      (xd[b + 1] == xd[b] && ci[b + 1] < ci[b]);
            if (sw) {
                float tf = xd[b]; xd[b] = xd[b + 1]; xd[b + 1] = tf;
                int   tn = ci[b]; ci[b] = ci[b + 1]; ci[b + 1] = tn;
            }
        }
    }

    // --- softmax over exact sqrt(d2) of top-8 ---
    float wj[KTOP];
    float vmin = sqrtf(fmaxf(xd[0], 0.f));
    float wsum = 0.f;
    #pragma unroll
    for (int j = 0; j < KTOP; j++) {
        float v = sqrtf(fmaxf(xd[j], 0.f));
        wj[j] = expf(-(v - vmin) / TEMP);
        wsum += wj[j];
    }
    float inv = 1.f / wsum;
    #pragma unroll
    for (int j = 0; j < KTOP; j++) wj[j] *= inv;

    // --- q gather + vq partial ---
    float vql = 0.f;
    #pragma unroll
    for (int i = 0; i < 4; i++) {
        int c4 = lane + 32 * i;
        float4 a = make_float4(0.f, 0.f, 0.f, 0.f);
        #pragma unroll
        for (int j = 0; j < KTOP; j++) {
            const float4* ev = (const float4*)(embed + (size_t)ci[j] * DB);
            float4 f = ev[c4];
            a.x += wj[j] * f.x; a.y += wj[j] * f.y;
            a.z += wj[j] * f.z; a.w += wj[j] * f.w;
        }
        ((float4*)(out + (size_t)r * DB))[c4] = a;
        float dx = zreg[i].x - a.x, dy = zreg[i].y - a.y;
        float dz = zreg[i].z - a.z, dw = zreg[i].w - a.w;
        vql += dx * dx + dy * dy + dz * dz + dw * dw;
    }
    #pragma unroll
    for (int o = 16; o; o >>= 1) vql += __shfl_down_sync(0xffffffffu, vql, o);
    if (lane == 0) atomicAdd(&g_vq, vql);
    if (lane < KTOP) atomicAdd(&g_usage[ci[lane]], wj[lane]);
    if (lane == 0) out[(size_t)NROWS * DB + r] = (float)ci[0];
}

// ---------------- finalize scalars --------------------------------------------
__global__ void finalize_kernel(float* __restrict__ out) {
    __shared__ float sh[256];
    float s = 0.f;
    for (int c = threadIdx.x; c < NC; c += 256) {
        float u = g_usage[c] * (1.f / (float)NROWS);
        s += u * logf(u + 1e-8f);
    }
    sh[threadIdx.x] = s;
    __syncthreads();
    for (int o = 128; o; o >>= 1) {
        if (threadIdx.x < o) sh[threadIdx.x] += sh[threadIdx.x + o];
        __syncthreads();
    }
    if (threadIdx.x == 0) {
        size_t base = (size_t)NROWS * DB + NROWS;
        out[base + 0] = g_vq * (1.f / (float)((size_t)NROWS * DB));
        out[base + 1] = -sh[0];
    }
}

// ---------------- launch --------------------------------------------------------
extern "C" void kernel_launch(void* const* d_in, const int* in_sizes, int n_in,
                              void* d_out, int out_size) {
    const float* slots = (const float*)d_in[0];
    const float* W     = (const float*)d_in[1];
    const float* bias  = (const float*)d_in[2];
    const float* embed = (const float*)d_in[3];
    float* out = (float*)d_out;

    float *zp = nullptr, *Dp = nullptr, *znp = nullptr;
    __nv_bfloat16 *asp = nullptr, *wbp = nullptr, *zsp = nullptr, *ebp = nullptr;
    cudaGetSymbolAddress((void**)&zp,  g_z);
    cudaGetSymbolAddress((void**)&Dp,  g_D2);
    cudaGetSymbolAddress((void**)&znp, g_zn);
    cudaGetSymbolAddress((void**)&asp, g_as);
    cudaGetSymbolAddress((void**)&wbp, g_wb);
    cudaGetSymbolAddress((void**)&zsp, g_zs);
    cudaGetSymbolAddress((void**)&ebp, g_eb);

    cudaFuncSetAttribute(tc_gemm<48, 1>,
                         cudaFuncAttributeMaxDynamicSharedMemorySize, GEMM_SMEM);
    cudaFuncSetAttribute(tc_gemm<16, 2>,
                         cudaFuncAttributeMaxDynamicSharedMemorySize, GEMM_SMEM);

    split_slots_kernel<<<(NROWS * D_IN) / 256, 256>>>(slots);
    split_w_kernel<<<(D_IN * DB) / 256, 256>>>(W);
    init_kernel<<<128, 256>>>(embed);

    // z = slots @ W + b : A'=[16384,1536], B'=[512,1536] -> fp32 z + bf16 z_hi
    tc_gemm<48, 1><<<dim3(2, 128), 256, GEMM_SMEM>>>(
        asp, 1536, wbp, 1536, bias, zp, 512, zsp, nullptr);

    znorm_kernel<<<NROWS / 8, 256>>>();

    // approx d2 = zn + enorm - 2 * (z_hi . e_hi) : K = 512
    tc_gemm<16, 2><<<dim3(4, 128), 256, GEMM_SMEM>>>(
        zsp, 512, ebp, 512, nullptr, Dp, 1024, nullptr, znp);

    topk_kernel<<<NROWS / 8, 256>>>(embed, out);
    finalize_kernel<<<1, 256>>>(out);
}

// round 9
// speedup vs baseline: 2.4469x; 1.0186x over previous
#include <cuda_runtime.h>
#include <cuda_bf16.h>
#include <cuda_fp16.h>
#include <math.h>
#include <float.h>
#include <stdint.h>

// Problem constants (fixed by the dataset)
#define NROWS 16384   // B*K = 256*64
#define D_IN  256
#define DB    512
#define NC    1024
#define KTOP  8
#define KSEL  12      // refine candidates
#define TEMP  0.1f

// ---------------- scratch (static device globals; no allocation) -------------
// GEMM1 (z = slots@W): compact 3-way split [hi|mid|lo], 6 term-pairs mapped in-kernel
// GEMM2 (selection key): single term z_hi . e_hi, fp16 keys (row-offset dropped)
__device__ __align__(1024) __nv_bfloat16 g_as[(size_t)NROWS * 768];
__device__ __align__(1024) __nv_bfloat16 g_wb[(size_t)DB * 768];
__device__ __align__(1024) __nv_bfloat16 g_zs[(size_t)NROWS * 512];  // z_hi
__device__ __align__(1024) __nv_bfloat16 g_eb[(size_t)NC * 512];     // e_hi
__device__ __align__(1024) float  g_z[(size_t)NROWS * DB];   // fp32 z
__device__ __align__(1024) __half g_Dk[(size_t)NROWS * NC];  // fp16 selection keys
__device__ float g_enorm[NC];
__device__ float g_usage[NC];
__device__ float g_vq;

// ---------------- helpers -----------------------------------------------------
__device__ __forceinline__ void cp16(void* dst, const void* src) {
    uint32_t d = (uint32_t)__cvta_generic_to_shared(dst);
    asm volatile("cp.async.cg.shared.global [%0], [%1], 16;" :: "r"(d), "l"(src));
}
__device__ __forceinline__ void cp_commit() {
    asm volatile("cp.async.commit_group;" ::: "memory");
}
__device__ __forceinline__ void split3(float v, __nv_bfloat16& hi, __nv_bfloat16& mid,
                                       __nv_bfloat16& lo) {
    hi = __float2bfloat16(v);
    float r1 = v - __bfloat162float(hi);
    mid = __float2bfloat16(r1);
    lo = __float2bfloat16(r1 - __bfloat162float(mid));
}
__device__ __forceinline__ void mma16816(float* c, const uint32_t* a,
                                         uint32_t b0, uint32_t b1) {
    asm volatile(
        "mma.sync.aligned.m16n8k16.row.col.f32.bf16.bf16.f32 "
        "{%0,%1,%2,%3}, {%4,%5,%6,%7}, {%8,%9}, {%0,%1,%2,%3};"
        : "+f"(c[0]), "+f"(c[1]), "+f"(c[2]), "+f"(c[3])
        : "r"(a[0]), "r"(a[1]), "r"(a[2]), "r"(a[3]), "r"(b0), "r"(b1));
}
__device__ __forceinline__ void ldsm4(uint32_t* r, uint32_t addr) {
    asm volatile("ldmatrix.sync.aligned.m8n8.x4.shared.b16 {%0,%1,%2,%3}, [%4];"
        : "=r"(r[0]), "=r"(r[1]), "=r"(r[2]), "=r"(r[3]) : "r"(addr));
}

// ---------------- pre-kernels: splits + norms ---------------------------------
__global__ void split_slots_kernel(const float* __restrict__ slots) {
    int idx = blockIdx.x * 256 + threadIdx.x;       // < NROWS*D_IN
    int row = idx >> 8, k = idx & 255;
    __nv_bfloat16 hi, mid, lo;
    split3(slots[idx], hi, mid, lo);
    __nv_bfloat16* dst = g_as + (size_t)row * 768;
    dst[k] = hi;  dst[256 + k] = mid;  dst[512 + k] = lo;
}

__global__ void split_w_kernel(const float* __restrict__ W) {
    int idx = blockIdx.x * 256 + threadIdx.x;       // < D_IN*DB
    int k = idx >> 9, n = idx & 511;                // W[k,n] row-major
    __nv_bfloat16 hi, mid, lo;
    split3(W[idx], hi, mid, lo);
    __nv_bfloat16* dst = g_wb + (size_t)n * 768;
    dst[k] = hi;  dst[256 + k] = mid;  dst[512 + k] = lo;
}

__global__ void init_kernel(const float* __restrict__ embed) {
    int w = threadIdx.x >> 5, lane = threadIdx.x & 31;
    int code = blockIdx.x * 8 + w;
    if (code < NC) {
        const float* e = embed + (size_t)code * DB;
        __nv_bfloat16* dst = g_eb + (size_t)code * 512;
        float s = 0.f;
        #pragma unroll
        for (int i = lane; i < DB; i += 32) {
            float v = e[i];
            s += v * v;
            dst[i] = __float2bfloat16(v);
        }
        #pragma unroll
        for (int o = 16; o; o >>= 1) s += __shfl_down_sync(0xffffffffu, s, o);
        if (lane == 0) g_enorm[code] = s;
    }
    if (blockIdx.x == 0) {
        for (int i = threadIdx.x; i < NC; i += blockDim.x) g_usage[i] = 0.f;
        if (threadIdx.x == 0) g_vq = 0.f;
    }
}

// ---------------- bf16 mma.sync GEMM: C[M,N] = A[M,K'] * B[N,K']^T --------------
// Block 128x256, 8 warps (2m x 4n), warp tile 64x64, K-chunk 32, double buffer.
// EPI=1: 6-term split GEMM via chunk->block mapping; +bias; fp32 C + bf16 z_hi.
// EPI=2: linear K; write fp16 key = enorm[col] - 2*acc - 170 (row-term dropped).
#define SM_PITCH 40
#define A_BYTES  (128 * SM_PITCH * 2)    // 10240
#define B_BYTES  (256 * SM_PITCH * 2)    // 20480
#define STAGE    (A_BYTES + B_BYTES)     // 30720
#define GEMM_SMEM (2 * STAGE)            // 61440

template<int KCH, int EPI>
__global__ void __launch_bounds__(256)
tc_gemm(const __nv_bfloat16* __restrict__ A, int lda,
        const __nv_bfloat16* __restrict__ B, int ldb,
        const float* __restrict__ bias,
        float* __restrict__ C, int ldc,
        __nv_bfloat16* __restrict__ Csplit) {
    extern __shared__ __align__(128) char smem[];
    const uint32_t sbase = (uint32_t)__cvta_generic_to_shared(smem);
    const int tid  = threadIdx.x;
    const int wid  = tid >> 5;
    const int lane = tid & 31;
    const int g    = lane >> 2;      // 0..7
    const int t    = lane & 3;       // 0..3
    const int wm   = wid & 1;        // 0..1 (M: 2 x 64)
    const int wn   = wid >> 1;       // 0..3 (N: 4 x 64)
    const int row0 = blockIdx.y * 128;
    const int col0 = blockIdx.x * 256;
    const int r8   = lane & 7;       // ldmatrix row within atom
    const int sub  = lane >> 3;      // ldmatrix atom id 0..3

    float acc[4][8][4];
    #pragma unroll
    for (int mi = 0; mi < 4; mi++)
        #pragma unroll
        for (int nj = 0; nj < 8; nj++)
            #pragma unroll
            for (int q = 0; q < 4; q++) acc[mi][nj][q] = 0.f;

    auto do_copy = [&](int c, int s) {
        char* sA = smem + s * STAGE;
        char* sB = sA + A_BYTES;
        int ak, bk;
        if (EPI == 1) {   // 6 term-pairs over compact [hi|mid|lo] blocks
            constexpr int ABLK[6] = {0, 0, 1, 0, 1, 2};
            constexpr int BBLK[6] = {0, 1, 0, 2, 1, 0};
            int term = c >> 3, j = c & 7;
            ak = ABLK[term] * 256 + j * 32;
            bk = BBLK[term] * 256 + j * 32;
        } else {
            ak = c * 32; bk = c * 32;
        }
        #pragma unroll
        for (int i = 0; i < 6; i++) {
            int tt = tid + 256 * i;
            if (tt < 512) {                       // A: 128 rows x 4 x 16B
                int r = tt >> 2, kc = tt & 3;
                cp16(sA + r * (SM_PITCH * 2) + kc * 16,
                     A + (size_t)(row0 + r) * lda + ak + kc * 8);
            } else {                              // B: 256 rows x 4 x 16B
                int u = tt - 512;
                int r = u >> 2, kc = u & 3;
                cp16(sB + r * (SM_PITCH * 2) + kc * 16,
                     B + (size_t)(col0 + r) * ldb + bk + kc * 8);
            }
        }
        cp_commit();
    };

    do_copy(0, 0);
    for (int c = 0; c < KCH; c++) {
        const int s = c & 1;
        if (c + 1 < KCH) {
            do_copy(c + 1, s ^ 1);
            asm volatile("cp.async.wait_group 1;" ::: "memory");
        } else {
            asm volatile("cp.async.wait_group 0;" ::: "memory");
        }
        __syncthreads();

        const uint32_t sAu = sbase + s * STAGE;
        const uint32_t sBu = sAu + A_BYTES;
        #pragma unroll
        for (int k16 = 0; k16 < 2; k16++) {
            uint32_t af[4][4];
            {
                int arow = wm * 64 + (sub & 1) * 8 + r8;
                int akc  = k16 * 16 + (sub >> 1) * 8;
                #pragma unroll
                for (int mi = 0; mi < 4; mi++)
                    ldsm4(af[mi], sAu + ((arow + mi * 16) * SM_PITCH + akc) * 2);
            }
            uint32_t bf[4][4];
            {
                int bn  = wn * 64 + (sub >> 1) * 8 + r8;
                int bkc = k16 * 16 + (sub & 1) * 8;
                #pragma unroll
                for (int nj2 = 0; nj2 < 4; nj2++)
                    ldsm4(bf[nj2], sBu + ((bn + nj2 * 16) * SM_PITCH + bkc) * 2);
            }
            #pragma unroll
            for (int nj2 = 0; nj2 < 4; nj2++) {
                #pragma unroll
                for (int mi = 0; mi < 4; mi++) {
                    mma16816(acc[mi][2 * nj2],     af[mi], bf[nj2][0], bf[nj2][1]);
                    mma16816(acc[mi][2 * nj2 + 1], af[mi], bf[nj2][2], bf[nj2][3]);
                }
            }
        }
        __syncthreads();
    }

    // epilogue
    if (EPI == 2) {
        __half* Ck = (__half*)C;
        float en0[8], en1[8];
        #pragma unroll
        for (int nj = 0; nj < 8; nj++) {
            int col = col0 + wn * 64 + nj * 8 + t * 2;
            en0[nj] = g_enorm[col] - 170.f;
            en1[nj] = g_enorm[col + 1] - 170.f;
        }
        #pragma unroll
        for (int mi = 0; mi < 4; mi++) {
            #pragma unroll
            for (int nj = 0; nj < 8; nj++) {
                const float* cr = acc[mi][nj];
                int row = row0 + wm * 64 + mi * 16 + g;
                int col = col0 + wn * 64 + nj * 8 + t * 2;
                *(__half2*)(Ck + (size_t)row * ldc + col) =
                    __floats2half2_rn(en0[nj] - 2.f * cr[0], en1[nj] - 2.f * cr[1]);
                *(__half2*)(Ck + (size_t)(row + 8) * ldc + col) =
                    __floats2half2_rn(en0[nj] - 2.f * cr[2], en1[nj] - 2.f * cr[3]);
            }
        }
    } else {
        #pragma unroll
        for (int mi = 0; mi < 4; mi++) {
            #pragma unroll
            for (int nj = 0; nj < 8; nj++) {
                const float* cr = acc[mi][nj];
                int row = row0 + wm * 64 + mi * 16 + g;
                int col = col0 + wn * 64 + nj * 8 + t * 2;
                float bx = bias[col], by = bias[col + 1];
                float v0 = cr[0] + bx, v1 = cr[1] + by;
                float v2 = cr[2] + bx, v3 = cr[3] + by;
                *(float2*)(C + (size_t)row * ldc + col)       = make_float2(v0, v1);
                *(float2*)(C + (size_t)(row + 8) * ldc + col) = make_float2(v2, v3);
                __nv_bfloat162 hp0 = {__float2bfloat16(v0), __float2bfloat16(v1)};
                __nv_bfloat162 hp1 = {__float2bfloat16(v2), __float2bfloat16(v3)};
                *(__nv_bfloat162*)(Csplit + (size_t)row * 512 + col)       = hp0;
                *(__nv_bfloat162*)(Csplit + (size_t)(row + 8) * 512 + col) = hp1;
            }
        }
    }
}

// ---------------- per-row: approx select -> exact refine -> outputs ------------
__global__ void __launch_bounds__(256)
topk_kernel(const float* __restrict__ embed, float* __restrict__ out) {
    int w = threadIdx.x >> 5, lane = threadIdx.x & 31;
    int r = blockIdx.x * 8 + w;

    const float4* zr4 = (const float4*)(g_z + (size_t)r * DB);
    float4 zreg[4];
    float zn = 0.f;
    #pragma unroll
    for (int i = 0; i < 4; i++) {
        float4 v = zr4[lane + 32 * i];
        zreg[i] = v;
        zn += v.x * v.x + v.y * v.y + v.z * v.z + v.w * v.w;
    }
    #pragma unroll
    for (int o = 16; o; o >>= 1) zn += __shfl_xor_sync(0xffffffffu, zn, o);

    // --- approx per-lane top-KSEL over fp16 keys; u32 key pack ---
    uint32_t td[KSEL];
    #pragma unroll
    for (int j = 0; j < KSEL; j++) td[j] = 0xFFFFFFFFu;

    auto insert = [&](float kv, int iv) {
        // kv ~ N(512, 27) after +512 -> positive; pack: truncated f32 bits | idx
        uint32_t key = (__float_as_uint(fmaxf(kv, 0.f)) & 0xFFFFFC00u) | (unsigned)iv;
        if (key < td[KSEL - 1]) {
            #pragma unroll
            for (int j = KSEL - 1; j >= 0; j--) {
                bool shift = (j > 0) && (td[j - 1] > key);
                if (shift) td[j] = td[j - 1];
                else       { td[j] = key; break; }
            }
        }
    };

    const uint4* Dr = (const uint4*)(g_Dk + (size_t)r * NC);
    #pragma unroll
    for (int it = 0; it < 4; it++) {
        uint4 v = Dr[lane + 32 * it];
        int c0 = (lane + 32 * it) * 8;
        float2 f0 = __half22float2(*reinterpret_cast<__half2*>(&v.x));
        float2 f1 = __half22float2(*reinterpret_cast<__half2*>(&v.y));
        float2 f2 = __half22float2(*reinterpret_cast<__half2*>(&v.z));
        float2 f3 = __half22float2(*reinterpret_cast<__half2*>(&v.w));
        insert(f0.x + 512.f, c0 + 0); insert(f0.y + 512.f, c0 + 1);
        insert(f1.x + 512.f, c0 + 2); insert(f1.y + 512.f, c0 + 3);
        insert(f2.x + 512.f, c0 + 4); insert(f2.y + 512.f, c0 + 5);
        insert(f3.x + 512.f, c0 + 6); insert(f3.y + 512.f, c0 + 7);
    }

    // --- warp merge: 12 rounds of u32 min (keys unique via idx bits) ---
    int ci[KSEL];
    int pos = 0;
    #pragma unroll
    for (int j = 0; j < KSEL; j++) {
        uint32_t cur = (pos < KSEL) ? td[pos] : 0xFFFFFFFFu;
        uint32_t best = cur;
        #pragma unroll
        for (int o = 16; o; o >>= 1)
            best = min(best, __shfl_xor_sync(0xffffffffu, best, o));
        ci[j] = (int)(best & 1023u);
        if (cur == best) pos++;
    }

    // --- exact fp32 refine: accumulate all 12 dots, then reduce (12-way ILP) ---
    float dot[KSEL];
    #pragma unroll
    for (int j = 0; j < KSEL; j++) dot[j] = 0.f;
    #pragma unroll
    for (int i = 0; i < 4; i++) {
        int c4 = lane + 32 * i;
        float4 zv = zreg[i];
        #pragma unroll
        for (int j = 0; j < KSEL; j++) {
            float4 f = ((const float4*)(embed + (size_t)ci[j] * DB))[c4];
            dot[j] += zv.x * f.x + zv.y * f.y + zv.z * f.z + zv.w * f.w;
        }
    }
    #pragma unroll
    for (int o = 16; o; o >>= 1) {
        #pragma unroll
        for (int j = 0; j < KSEL; j++)
            dot[j] += __shfl_xor_sync(0xffffffffu, dot[j], o);
    }
    float xd[KSEL];
    #pragma unroll
    for (int j = 0; j < KSEL; j++) xd[j] = zn + g_enorm[ci[j]] - 2.f * dot[j];

    // --- bubble sort (all lanes identical; tie -> smaller index) ---
    #pragma unroll
    for (int a = 0; a < KSEL - 1; a++) {
        #pragma unroll
        for (int b = 0; b < KSEL - 1 - a; b++) {
            bool sw = (xd[b + 1] < xd[b]) ||
                      (xd[b + 1] == xd[b] && ci[b + 1] < ci[b]);
            if (sw) {
                float tf = xd[b]; xd[b] = xd[b + 1]; xd[b + 1] = tf;
                int   tn = ci[b]; ci[b] = ci[b + 1]; ci[b + 1] = tn;
            }
        }
    }

    // --- softmax over exact sqrt(d2) of top-8 ---
    float wj[KTOP];
    float vmin = sqrtf(fmaxf(xd[0], 0.f));
    float wsum = 0.f;
    #pragma unroll
    for (int j = 0; j < KTOP; j++) {
        float v = sqrtf(fmaxf(xd[j], 0.f));
        wj[j] = expf(-(v - vmin) / TEMP);
        wsum += wj[j];
    }
    float inv = 1.f / wsum;
    #pragma unroll
    for (int j = 0; j < KTOP; j++) wj[j] *= inv;

    // --- q gather + vq partial ---
    float vql = 0.f;
    #pragma unroll
    for (int i = 0; i < 4; i++) {
        int c4 = lane + 32 * i;
        float4 a = make_float4(0.f, 0.f, 0.f, 0.f);
        #pragma unroll
        for (int j = 0; j < KTOP; j++) {
            const float4* ev = (const float4*)(embed + (size_t)ci[j] * DB);
            float4 f = ev[c4];
            a.x += wj[j] * f.x; a.y += wj[j] * f.y;
            a.z += wj[j] * f.z; a.w += wj[j] * f.w;
        }
        ((float4*)(out + (size_t)r * DB))[c4] = a;
        float dx = zreg[i].x - a.x, dy = zreg[i].y - a.y;
        float dz = zreg[i].z - a.z, dw = zreg[i].w - a.w;
        vql += dx * dx + dy * dy + dz * dz + dw * dw;
    }
    #pragma unroll
    for (int o = 16; o; o >>= 1) vql += __shfl_down_sync(0xffffffffu, vql, o);
    if (lane == 0) atomicAdd(&g_vq, vql);
    if (lane < KTOP) atomicAdd(&g_usage[ci[lane]], wj[lane]);
    if (lane == 0) out[(size_t)NROWS * DB + r] = (float)ci[0];
}

// ---------------- finalize scalars --------------------------------------------
__global__ void finalize_kernel(float* __restrict__ out) {
    __shared__ float sh[256];
    float s = 0.f;
    for (int c = threadIdx.x; c < NC; c += 256) {
        float u = g_usage[c] * (1.f / (float)NROWS);
        s += u * logf(u + 1e-8f);
    }
    sh[threadIdx.x] = s;
    __syncthreads();
    for (int o = 128; o; o >>= 1) {
        if (threadIdx.x < o) sh[threadIdx.x] += sh[threadIdx.x + o];
        __syncthreads();
    }
    if (threadIdx.x == 0) {
        size_t base = (size_t)NROWS * DB + NROWS;
        out[base + 0] = g_vq * (1.f / (float)((size_t)NROWS * DB));
        out[base + 1] = -sh[0];
    }
}

// ---------------- launch --------------------------------------------------------
extern "C" void kernel_launch(void* const* d_in, const int* in_sizes, int n_in,
                              void* d_out, int out_size) {
    const float* slots = (const float*)d_in[0];
    const float* W     = (const float*)d_in[1];
    const float* bias  = (const float*)d_in[2];
    const float* embed = (const float*)d_in[3];
    float* out = (float*)d_out;

    float* zp = nullptr;
    __half* dkp = nullptr;
    __nv_bfloat16 *asp = nullptr, *wbp = nullptr, *zsp = nullptr, *ebp = nullptr;
    cudaGetSymbolAddress((void**)&zp,  g_z);
    cudaGetSymbolAddress((void**)&dkp, g_Dk);
    cudaGetSymbolAddress((void**)&asp, g_as);
    cudaGetSymbolAddress((void**)&wbp, g_wb);
    cudaGetSymbolAddress((void**)&zsp, g_zs);
    cudaGetSymbolAddress((void**)&ebp, g_eb);

    cudaFuncSetAttribute(tc_gemm<48, 1>,
                         cudaFuncAttributeMaxDynamicSharedMemorySize, GEMM_SMEM);
    cudaFuncSetAttribute(tc_gemm<16, 2>,
                         cudaFuncAttributeMaxDynamicSharedMemorySize, GEMM_SMEM);

    split_slots_kernel<<<(NROWS * D_IN) / 256, 256>>>(slots);
    split_w_kernel<<<(D_IN * DB) / 256, 256>>>(W);
    init_kernel<<<128, 256>>>(embed);

    // z = slots @ W + b : 6-term mapped split over [hi|mid|lo] -> fp32 z + bf16 z_hi
    tc_gemm<48, 1><<<dim3(2, 128), 256, GEMM_SMEM>>>(
        asp, 768, wbp, 768, bias, zp, 512, zsp);

    // fp16 selection keys = enorm - 2*(z_hi . e_hi) - 170 : K = 512
    tc_gemm<16, 2><<<dim3(4, 128), 256, GEMM_SMEM>>>(
        zsp, 512, ebp, 512, nullptr, (float*)dkp, 1024, nullptr);

    topk_kernel<<<NROWS / 8, 256>>>(embed, out);
    finalize_kernel<<<1, 256>>>(out);
}

// round 10
// speedup vs baseline: 2.5080x; 1.0249x over previous
#include <cuda_runtime.h>
#include <cuda_bf16.h>
#include <cuda_fp16.h>
#include <math.h>
#include <float.h>
#include <stdint.h>

// Problem constants (fixed by the dataset)
#define NROWS 16384   // B*K = 256*64
#define D_IN  256
#define DB    512
#define NC    1024
#define KTOP  8
#define KSEL  12      // refine candidates
#define TEMP  0.1f

// ---------------- scratch (static device globals; no allocation) -------------
__device__ __align__(1024) __nv_bfloat16 g_as[(size_t)NROWS * 768];   // [hi|mid|lo]
__device__ __align__(1024) __nv_bfloat16 g_wb[(size_t)DB * 768];      // [hi|mid|lo]
__device__ __align__(1024) __nv_bfloat16 g_zs[(size_t)NROWS * 512];   // z_hi
__device__ __align__(1024) __nv_bfloat16 g_eb[(size_t)NC * 512];      // e_hi
__device__ __align__(1024) float  g_z[(size_t)NROWS * DB];   // fp32 z
__device__ __align__(1024) __half g_Dk[(size_t)NROWS * NC];  // fp16 selection keys
__device__ float g_enorm[NC];
__device__ float g_usage[NC];
__device__ float g_vq;

// ---------------- helpers -----------------------------------------------------
__device__ __forceinline__ void cp16(void* dst, const void* src) {
    uint32_t d = (uint32_t)__cvta_generic_to_shared(dst);
    asm volatile("cp.async.cg.shared.global [%0], [%1], 16;" :: "r"(d), "l"(src));
}
__device__ __forceinline__ void cp_commit() {
    asm volatile("cp.async.commit_group;" ::: "memory");
}
__device__ __forceinline__ void split3(float v, __nv_bfloat16& hi, __nv_bfloat16& mid,
                                       __nv_bfloat16& lo) {
    hi = __float2bfloat16(v);
    float r1 = v - __bfloat162float(hi);
    mid = __float2bfloat16(r1);
    lo = __float2bfloat16(r1 - __bfloat162float(mid));
}
__device__ __forceinline__ void mma16816(float* c, const uint32_t* a,
                                         uint32_t b0, uint32_t b1) {
    asm volatile(
        "mma.sync.aligned.m16n8k16.row.col.f32.bf16.bf16.f32 "
        "{%0,%1,%2,%3}, {%4,%5,%6,%7}, {%8,%9}, {%0,%1,%2,%3};"
        : "+f"(c[0]), "+f"(c[1]), "+f"(c[2]), "+f"(c[3])
        : "r"(a[0]), "r"(a[1]), "r"(a[2]), "r"(a[3]), "r"(b0), "r"(b1));
}
__device__ __forceinline__ void ldsm4(uint32_t* r, uint32_t addr) {
    asm volatile("ldmatrix.sync.aligned.m8n8.x4.shared.b16 {%0,%1,%2,%3}, [%4];"
        : "=r"(r[0]), "=r"(r[1]), "=r"(r[2]), "=r"(r[3]) : "r"(addr));
}
// monotone u16 map of an fp16 bit pattern (order-preserving total order)
__device__ __forceinline__ uint32_t h2key(uint32_t h16) {
    uint32_t neg = h16 >> 15;                 // 0 or 1
    return h16 ^ (0x8000u | (neg * 0x7FFFu)); // pos: +0x8000, neg: ^0xFFFF
}

// ---------------- pre-kernels: splits + norms ---------------------------------
__global__ void split_slots_kernel(const float* __restrict__ slots) {
    int idx = blockIdx.x * 256 + threadIdx.x;       // < NROWS*D_IN
    int row = idx >> 8, k = idx & 255;
    __nv_bfloat16 hi, mid, lo;
    split3(slots[idx], hi, mid, lo);
    __nv_bfloat16* dst = g_as + (size_t)row * 768;
    dst[k] = hi;  dst[256 + k] = mid;  dst[512 + k] = lo;
}

__global__ void split_w_kernel(const float* __restrict__ W) {
    int idx = blockIdx.x * 256 + threadIdx.x;       // < D_IN*DB
    int k = idx >> 9, n = idx & 511;                // W[k,n] row-major
    __nv_bfloat16 hi, mid, lo;
    split3(W[idx], hi, mid, lo);
    __nv_bfloat16* dst = g_wb + (size_t)n * 768;
    dst[k] = hi;  dst[256 + k] = mid;  dst[512 + k] = lo;
}

__global__ void init_kernel(const float* __restrict__ embed) {
    int w = threadIdx.x >> 5, lane = threadIdx.x & 31;
    int code = blockIdx.x * 8 + w;
    if (code < NC) {
        const float* e = embed + (size_t)code * DB;
        __nv_bfloat16* dst = g_eb + (size_t)code * 512;
        float s = 0.f;
        #pragma unroll
        for (int i = lane; i < DB; i += 32) {
            float v = e[i];
            s += v * v;
            dst[i] = __float2bfloat16(v);
        }
        #pragma unroll
        for (int o = 16; o; o >>= 1) s += __shfl_down_sync(0xffffffffu, s, o);
        if (lane == 0) g_enorm[code] = s;
    }
    if (blockIdx.x == 0) {
        for (int i = threadIdx.x; i < NC; i += blockDim.x) g_usage[i] = 0.f;
        if (threadIdx.x == 0) g_vq = 0.f;
    }
}

// ---------------- bf16 mma.sync GEMM: C[M,N] = A[M,K'] * B[N,K']^T --------------
// Block 128x256, 8 warps (2m x 4n), warp tile 64x64, K-chunk 32, double buffer.
// EPI=1: 6-term split GEMM via nibble-mapped chunk offsets; +bias; fp32 C + z_hi.
// EPI=2: linear K; write fp16 key = enorm[col] - 2*acc - 170 (row-term dropped).
#define SM_PITCH 40
#define A_BYTES  (128 * SM_PITCH * 2)    // 10240
#define B_BYTES  (256 * SM_PITCH * 2)    // 20480
#define STAGE    (A_BYTES + B_BYTES)     // 30720
#define GEMM_SMEM (2 * STAGE)            // 61440

template<int KCH, int EPI>
__global__ void __launch_bounds__(256)
tc_gemm(const __nv_bfloat16* __restrict__ A, int lda,
        const __nv_bfloat16* __restrict__ B, int ldb,
        const float* __restrict__ bias,
        float* __restrict__ C, int ldc,
        __nv_bfloat16* __restrict__ Csplit) {
    extern __shared__ __align__(128) char smem[];
    const uint32_t sbase = (uint32_t)__cvta_generic_to_shared(smem);
    const int tid  = threadIdx.x;
    const int wid  = tid >> 5;
    const int lane = tid & 31;
    const int g    = lane >> 2;      // 0..7
    const int t    = lane & 3;       // 0..3
    const int wm   = wid & 1;        // 0..1 (M: 2 x 64)
    const int wn   = wid >> 1;       // 0..3 (N: 4 x 64)
    const int row0 = blockIdx.y * 128;
    const int col0 = blockIdx.x * 256;
    const int r8   = lane & 7;       // ldmatrix row within atom
    const int sub  = lane >> 3;      // ldmatrix atom id 0..3

    float acc[4][8][4];
    #pragma unroll
    for (int mi = 0; mi < 4; mi++)
        #pragma unroll
        for (int nj = 0; nj < 8; nj++)
            #pragma unroll
            for (int q = 0; q < 4; q++) acc[mi][nj][q] = 0.f;

    auto do_copy = [&](int c, int s) {
        char* sA = smem + s * STAGE;
        char* sB = sA + A_BYTES;
        int ak, bk;
        if (EPI == 1) {   // 6 term-pairs over compact [hi|mid|lo] blocks
            // A blocks per term: 0,0,1,0,1,2  B blocks: 0,1,0,2,1,0 (nibble-packed)
            int term = c >> 3, j = c & 7;
            ak = (int)((0x210100u >> (term * 4)) & 15u) * 256 + j * 32;
            bk = (int)((0x012010u >> (term * 4)) & 15u) * 256 + j * 32;
        } else {
            ak = c * 32; bk = c * 32;
        }
        #pragma unroll
        for (int i = 0; i < 6; i++) {
            int tt = tid + 256 * i;
            if (tt < 512) {                       // A: 128 rows x 4 x 16B
                int r = tt >> 2, kc = tt & 3;
                cp16(sA + r * (SM_PITCH * 2) + kc * 16,
                     A + (size_t)(row0 + r) * lda + ak + kc * 8);
            } else {                              // B: 256 rows x 4 x 16B
                int u = tt - 512;
                int r = u >> 2, kc = u & 3;
                cp16(sB + r * (SM_PITCH * 2) + kc * 16,
                     B + (size_t)(col0 + r) * ldb + bk + kc * 8);
            }
        }
        cp_commit();
    };

    do_copy(0, 0);
    for (int c = 0; c < KCH; c++) {
        const int s = c & 1;
        if (c + 1 < KCH) {
            do_copy(c + 1, s ^ 1);
            asm volatile("cp.async.wait_group 1;" ::: "memory");
        } else {
            asm volatile("cp.async.wait_group 0;" ::: "memory");
        }
        __syncthreads();

        const uint32_t sAu = sbase + s * STAGE;
        const uint32_t sBu = sAu + A_BYTES;
        #pragma unroll
        for (int k16 = 0; k16 < 2; k16++) {
            uint32_t af[4][4];
            {
                int arow = wm * 64 + (sub & 1) * 8 + r8;
                int akc  = k16 * 16 + (sub >> 1) * 8;
                #pragma unroll
                for (int mi = 0; mi < 4; mi++)
                    ldsm4(af[mi], sAu + ((arow + mi * 16) * SM_PITCH + akc) * 2);
            }
            uint32_t bf[4][4];
            {
                int bn  = wn * 64 + (sub >> 1) * 8 + r8;
                int bkc = k16 * 16 + (sub & 1) * 8;
                #pragma unroll
                for (int nj2 = 0; nj2 < 4; nj2++)
                    ldsm4(bf[nj2], sBu + ((bn + nj2 * 16) * SM_PITCH + bkc) * 2);
            }
            #pragma unroll
            for (int nj2 = 0; nj2 < 4; nj2++) {
                #pragma unroll
                for (int mi = 0; mi < 4; mi++) {
                    mma16816(acc[mi][2 * nj2],     af[mi], bf[nj2][0], bf[nj2][1]);
                    mma16816(acc[mi][2 * nj2 + 1], af[mi], bf[nj2][2], bf[nj2][3]);
                }
            }
        }
        __syncthreads();
    }

    // epilogue
    if (EPI == 2) {
        __half* Ck = (__half*)C;
        float en0[8], en1[8];
        #pragma unroll
        for (int nj = 0; nj < 8; nj++) {
            int col = col0 + wn * 64 + nj * 8 + t * 2;
            en0[nj] = g_enorm[col] - 170.f;
            en1[nj] = g_enorm[col + 1] - 170.f;
        }
        #pragma unroll
        for (int mi = 0; mi < 4; mi++) {
            #pragma unroll
            for (int nj = 0; nj < 8; nj++) {
                const float* cr = acc[mi][nj];
                int row = row0 + wm * 64 + mi * 16 + g;
                int col = col0 + wn * 64 + nj * 8 + t * 2;
                *(__half2*)(Ck + (size_t)row * ldc + col) =
                    __floats2half2_rn(en0[nj] - 2.f * cr[0], en1[nj] - 2.f * cr[1]);
                *(__half2*)(Ck + (size_t)(row + 8) * ldc + col) =
                    __floats2half2_rn(en0[nj] - 2.f * cr[2], en1[nj] - 2.f * cr[3]);
            }
        }
    } else {
        #pragma unroll
        for (int mi = 0; mi < 4; mi++) {
            #pragma unroll
            for (int nj = 0; nj < 8; nj++) {
                const float* cr = acc[mi][nj];
                int row = row0 + wm * 64 + mi * 16 + g;
                int col = col0 + wn * 64 + nj * 8 + t * 2;
                float bx = bias[col], by = bias[col + 1];
                float v0 = cr[0] + bx, v1 = cr[1] + by;
                float v2 = cr[2] + bx, v3 = cr[3] + by;
                *(float2*)(C + (size_t)row * ldc + col)       = make_float2(v0, v1);
                *(float2*)(C + (size_t)(row + 8) * ldc + col) = make_float2(v2, v3);
                __nv_bfloat162 hp0 = {__float2bfloat16(v0), __float2bfloat16(v1)};
                __nv_bfloat162 hp1 = {__float2bfloat16(v2), __float2bfloat16(v3)};
                *(__nv_bfloat162*)(Csplit + (size_t)row * 512 + col)       = hp0;
                *(__nv_bfloat162*)(Csplit + (size_t)(row + 8) * 512 + col) = hp1;
            }
        }
    }
}

// ---------------- per-row: approx select -> exact refine -> outputs ------------
__global__ void __launch_bounds__(256)
topk_kernel(const float* __restrict__ embed, float* __restrict__ out) {
    int w = threadIdx.x >> 5, lane = threadIdx.x & 31;
    int r = blockIdx.x * 8 + w;

    const float4* zr4 = (const float4*)(g_z + (size_t)r * DB);
    float4 zreg[4];
    float zn = 0.f;
    #pragma unroll
    for (int i = 0; i < 4; i++) {
        float4 v = zr4[lane + 32 * i];
        zreg[i] = v;
        zn += v.x * v.x + v.y * v.y + v.z * v.z + v.w * v.w;
    }
    #pragma unroll
    for (int o = 16; o; o >>= 1) zn += __shfl_xor_sync(0xffffffffu, zn, o);

    // --- approx per-lane top-KSEL over fp16 keys; integer-only path ---
    // key = (monotone_u16(fp16 bits) << 10) | idx  (lossless ordering, 26 bits)
    uint32_t td[KSEL];
    #pragma unroll
    for (int j = 0; j < KSEL; j++) td[j] = 0xFFFFFFFFu;

    auto insert = [&](uint32_t key) {
        if (key < td[KSEL - 1]) {
            #pragma unroll
            for (int j = KSEL - 1; j >= 0; j--) {
                bool shift = (j > 0) && (td[j - 1] > key);
                if (shift) td[j] = td[j - 1];
                else       { td[j] = key; break; }
            }
        }
    };

    const uint4* Dr = (const uint4*)(g_Dk + (size_t)r * NC);
    #pragma unroll
    for (int it = 0; it < 4; it++) {
        uint4 v = Dr[lane + 32 * it];
        uint32_t c0 = (uint32_t)(lane + 32 * it) * 8;
        insert((h2key(v.x & 0xFFFFu) << 10) | (c0 + 0));
        insert((h2key(v.x >> 16)     << 10) | (c0 + 1));
        insert((h2key(v.y & 0xFFFFu) << 10) | (c0 + 2));
        insert((h2key(v.y >> 16)     << 10) | (c0 + 3));
        insert((h2key(v.z & 0xFFFFu) << 10) | (c0 + 4));
        insert((h2key(v.z >> 16)     << 10) | (c0 + 5));
        insert((h2key(v.w & 0xFFFFu) << 10) | (c0 + 6));
        insert((h2key(v.w >> 16)     << 10) | (c0 + 7));
    }

    // --- warp merge: 12 rounds of u32 min (keys unique via idx bits) ---
    int ci[KSEL];
    int pos = 0;
    #pragma unroll
    for (int j = 0; j < KSEL; j++) {
        uint32_t cur = (pos < KSEL) ? td[pos] : 0xFFFFFFFFu;
        uint32_t best = cur;
        #pragma unroll
        for (int o = 16; o; o >>= 1)
            best = min(best, __shfl_xor_sync(0xffffffffu, best, o));
        ci[j] = (int)(best & 1023u);
        if (cur == best) pos++;
    }

    // --- exact fp32 refine: accumulate all 12 dots, then reduce (12-way ILP) ---
    float dot[KSEL];
    #pragma unroll
    for (int j = 0; j < KSEL; j++) dot[j] = 0.f;
    #pragma unroll
    for (int i = 0; i < 4; i++) {
        int c4 = lane + 32 * i;
        float4 zv = zreg[i];
        #pragma unroll
        for (int j = 0; j < KSEL; j++) {
            float4 f = ((const float4*)(embed + (size_t)ci[j] * DB))[c4];
            dot[j] += zv.x * f.x + zv.y * f.y + zv.z * f.z + zv.w * f.w;
        }
    }
    #pragma unroll
    for (int o = 16; o; o >>= 1) {
        #pragma unroll
        for (int j = 0; j < KSEL; j++)
            dot[j] += __shfl_xor_sync(0xffffffffu, dot[j], o);
    }
    float xd[KSEL];
    #pragma unroll
    for (int j = 0; j < KSEL; j++) xd[j] = zn + g_enorm[ci[j]] - 2.f * dot[j];

    // --- bubble sort (all lanes identical; tie -> smaller index) ---
    #pragma unroll
    for (int a = 0; a < KSEL - 1; a++) {
        #pragma unroll
        for (int b = 0; b < KSEL - 1 - a; b++) {
            bool sw = (xd[b + 1] < xd[b]) ||
                      (xd[b + 1] == xd[b] && ci[b + 1] < ci[b]);
            if (sw) {
                float tf = xd[b]; xd[b] = xd[b + 1]; xd[b + 1] = tf;
                int   tn = ci[b]; ci[b] = ci[b + 1]; ci[b + 1] = tn;
            }
        }
    }

    // --- softmax over exact sqrt(d2) of top-8 ---
    float wj[KTOP];
    float vmin = sqrtf(fmaxf(xd[0], 0.f));
    float wsum = 0.f;
    #pragma unroll
    for (int j = 0; j < KTOP; j++) {
        float v = sqrtf(fmaxf(xd[j], 0.f));
        wj[j] = expf(-(v - vmin) / TEMP);
        wsum += wj[j];
    }
    float inv = 1.f / wsum;
    #pragma unroll
    for (int j = 0; j < KTOP; j++) wj[j] *= inv;

    // --- q gather + vq partial ---
    float vql = 0.f;
    #pragma unroll
    for (int i = 0; i < 4; i++) {
        int c4 = lane + 32 * i;
        float4 a = make_float4(0.f, 0.f, 0.f, 0.f);
        #pragma unroll
        for (int j = 0; j < KTOP; j++) {
            const float4* ev = (const float4*)(embed + (size_t)ci[j] * DB);
            float4 f = ev[c4];
            a.x += wj[j] * f.x; a.y += wj[j] * f.y;
            a.z += wj[j] * f.z; a.w += wj[j] * f.w;
        }
        ((float4*)(out + (size_t)r * DB))[c4] = a;
        float dx = zreg[i].x - a.x, dy = zreg[i].y - a.y;
        float dz = zreg[i].z - a.z, dw = zreg[i].w - a.w;
        vql += dx * dx + dy * dy + dz * dz + dw * dw;
    }
    #pragma unroll
    for (int o = 16; o; o >>= 1) vql += __shfl_down_sync(0xffffffffu, vql, o);
    if (lane == 0) atomicAdd(&g_vq, vql);
    if (lane < KTOP) atomicAdd(&g_usage[ci[lane]], wj[lane]);
    if (lane == 0) out[(size_t)NROWS * DB + r] = (float)ci[0];
}

// ---------------- finalize scalars --------------------------------------------
__global__ void finalize_kernel(float* __restrict__ out) {
    __shared__ float sh[256];
    float s = 0.f;
    for (int c = threadIdx.x; c < NC; c += 256) {
        float u = g_usage[c] * (1.f / (float)NROWS);
        s += u * logf(u + 1e-8f);
    }
    sh[threadIdx.x] = s;
    __syncthreads();
    for (int o = 128; o; o >>= 1) {
        if (threadIdx.x < o) sh[threadIdx.x] += sh[threadIdx.x + o];
        __syncthreads();
    }
    if (threadIdx.x == 0) {
        size_t base = (size_t)NROWS * DB + NROWS;
        out[base + 0] = g_vq * (1.f / (float)((size_t)NROWS * DB));
        out[base + 1] = -sh[0];
    }
}

// ---------------- launch --------------------------------------------------------
extern "C" void kernel_launch(void* const* d_in, const int* in_sizes, int n_in,
                              void* d_out, int out_size) {
    const float* slots = (const float*)d_in[0];
    const float* W     = (const float*)d_in[1];
    const float* bias  = (const float*)d_in[2];
    const float* embed = (const float*)d_in[3];
    float* out = (float*)d_out;

    float* zp = nullptr;
    __half* dkp = nullptr;
    __nv_bfloat16 *asp = nullptr, *wbp = nullptr, *zsp = nullptr, *ebp = nullptr;
    cudaGetSymbolAddress((void**)&zp,  g_z);
    cudaGetSymbolAddress((void**)&dkp, g_Dk);
    cudaGetSymbolAddress((void**)&asp, g_as);
    cudaGetSymbolAddress((void**)&wbp, g_wb);
    cudaGetSymbolAddress((void**)&zsp, g_zs);
    cudaGetSymbolAddress((void**)&ebp, g_eb);

    cudaFuncSetAttribute(tc_gemm<48, 1>,
                         cudaFuncAttributeMaxDynamicSharedMemorySize, GEMM_SMEM);
    cudaFuncSetAttribute(tc_gemm<16, 2>,
                         cudaFuncAttributeMaxDynamicSharedMemorySize, GEMM_SMEM);

    split_slots_kernel<<<(NROWS * D_IN) / 256, 256>>>(slots);
    split_w_kernel<<<(D_IN * DB) / 256, 256>>>(W);
    init_kernel<<<128, 256>>>(embed);

    // z = slots @ W + b : 6-term mapped split over [hi|mid|lo] -> fp32 z + bf16 z_hi
    tc_gemm<48, 1><<<dim3(2, 128), 256, GEMM_SMEM>>>(
        asp, 768, wbp, 768, bias, zp, 512, zsp);

    // fp16 selection keys = enorm - 2*(z_hi . e_hi) - 170 : K = 512
    tc_gemm<16, 2><<<dim3(4, 128), 256, GEMM_SMEM>>>(
        zsp, 512, ebp, 512, nullptr, (float*)dkp, 1024, nullptr);

    topk_kernel<<<NROWS / 8, 256>>>(embed, out);
    finalize_kernel<<<1, 256>>>(out);
}

// round 11
// speedup vs baseline: 2.7606x; 1.1007x over previous
#include <cuda_runtime.h>
#include <cuda_bf16.h>
#include <cuda_fp16.h>
#include <math.h>
#include <float.h>
#include <stdint.h>

// Problem constants (fixed by the dataset)
#define NROWS 16384   // B*K = 256*64
#define D_IN  256
#define DB    512
#define NC    1024
#define KTOP  8
#define KSEL  12      // refine candidates
#define TEMP  0.1f

// ---------------- scratch (static device globals; no allocation) -------------
__device__ __align__(1024) __nv_bfloat16 g_as[(size_t)NROWS * 768];   // [hi|mid|lo]
__device__ __align__(1024) __nv_bfloat16 g_wb[(size_t)DB * 768];      // [hi|mid|lo]
__device__ __align__(1024) __nv_bfloat16 g_zs[(size_t)NROWS * 512];   // z_hi
__device__ __align__(1024) __nv_bfloat16 g_eb[(size_t)NC * 512];      // e_hi
__device__ __align__(1024) float  g_z[(size_t)NROWS * DB];   // fp32 z
__device__ __align__(1024) __half g_Dk[(size_t)NROWS * NC];  // fp16 selection keys
__device__ float g_enorm[NC];
__device__ float g_usage[NC];
__device__ float g_vq;

// ---------------- helpers -----------------------------------------------------
__device__ __forceinline__ void cp16(void* dst, const void* src) {
    uint32_t d = (uint32_t)__cvta_generic_to_shared(dst);
    asm volatile("cp.async.cg.shared.global [%0], [%1], 16;" :: "r"(d), "l"(src));
}
__device__ __forceinline__ void cp_commit() {
    asm volatile("cp.async.commit_group;" ::: "memory");
}
__device__ __forceinline__ void split3(float v, __nv_bfloat16& hi, __nv_bfloat16& mid,
                                       __nv_bfloat16& lo) {
    hi = __float2bfloat16(v);
    float r1 = v - __bfloat162float(hi);
    mid = __float2bfloat16(r1);
    lo = __float2bfloat16(r1 - __bfloat162float(mid));
}
__device__ __forceinline__ void mma16816(float* c, const uint32_t* a,
                                         uint32_t b0, uint32_t b1) {
    asm volatile(
        "mma.sync.aligned.m16n8k16.row.col.f32.bf16.bf16.f32 "
        "{%0,%1,%2,%3}, {%4,%5,%6,%7}, {%8,%9}, {%0,%1,%2,%3};"
        : "+f"(c[0]), "+f"(c[1]), "+f"(c[2]), "+f"(c[3])
        : "r"(a[0]), "r"(a[1]), "r"(a[2]), "r"(a[3]), "r"(b0), "r"(b1));
}
__device__ __forceinline__ void ldsm4(uint32_t* r, uint32_t addr) {
    asm volatile("ldmatrix.sync.aligned.m8n8.x4.shared.b16 {%0,%1,%2,%3}, [%4];"
        : "=r"(r[0]), "=r"(r[1]), "=r"(r[2]), "=r"(r[3]) : "r"(addr));
}
// monotone u16 map of an fp16 bit pattern (order-preserving total order)
__device__ __forceinline__ uint32_t h2key(uint32_t h16) {
    uint32_t neg = h16 >> 15;                 // 0 or 1
    return h16 ^ (0x8000u | (neg * 0x7FFFu)); // pos: +0x8000, neg: ^0xFFFF
}

// ---------------- pre-kernels: splits + norms ---------------------------------
__global__ void split_slots_kernel(const float* __restrict__ slots) {
    int idx = blockIdx.x * 256 + threadIdx.x;       // < NROWS*D_IN
    int row = idx >> 8, k = idx & 255;
    __nv_bfloat16 hi, mid, lo;
    split3(slots[idx], hi, mid, lo);
    __nv_bfloat16* dst = g_as + (size_t)row * 768;
    dst[k] = hi;  dst[256 + k] = mid;  dst[512 + k] = lo;
}

__global__ void split_w_kernel(const float* __restrict__ W) {
    int idx = blockIdx.x * 256 + threadIdx.x;       // < D_IN*DB
    int k = idx >> 9, n = idx & 511;                // W[k,n] row-major
    __nv_bfloat16 hi, mid, lo;
    split3(W[idx], hi, mid, lo);
    __nv_bfloat16* dst = g_wb + (size_t)n * 768;
    dst[k] = hi;  dst[256 + k] = mid;  dst[512 + k] = lo;
}

__global__ void init_kernel(const float* __restrict__ embed) {
    int w = threadIdx.x >> 5, lane = threadIdx.x & 31;
    int code = blockIdx.x * 8 + w;
    if (code < NC) {
        const float* e = embed + (size_t)code * DB;
        __nv_bfloat16* dst = g_eb + (size_t)code * 512;
        float s = 0.f;
        #pragma unroll
        for (int i = lane; i < DB; i += 32) {
            float v = e[i];
            s += v * v;
            dst[i] = __float2bfloat16(v);
        }
        #pragma unroll
        for (int o = 16; o; o >>= 1) s += __shfl_down_sync(0xffffffffu, s, o);
        if (lane == 0) g_enorm[code] = s;
    }
    if (blockIdx.x == 0) {
        for (int i = threadIdx.x; i < NC; i += blockDim.x) g_usage[i] = 0.f;
        if (threadIdx.x == 0) g_vq = 0.f;
    }
}

// ---------------- bf16 mma.sync GEMM: C[M,N] = A[M,K'] * B[N,K']^T --------------
// Block 128x256, 8 warps (2m x 4n), warp tile 64x64, K-chunk 32, double buffer.
// EPI=1: 6-term split GEMM via nibble-mapped chunk offsets; +bias; fp32 C + z_hi.
// EPI=2: linear K; write fp16 key = enorm[col] - 2*acc - 170 (row-term dropped).
#define SM_PITCH 40
#define A_BYTES  (128 * SM_PITCH * 2)    // 10240
#define B_BYTES  (256 * SM_PITCH * 2)    // 20480
#define STAGE    (A_BYTES + B_BYTES)     // 30720
#define GEMM_SMEM (2 * STAGE)            // 61440

template<int KCH, int EPI>
__global__ void __launch_bounds__(256)
tc_gemm(const __nv_bfloat16* __restrict__ A, int lda,
        const __nv_bfloat16* __restrict__ B, int ldb,
        const float* __restrict__ bias,
        float* __restrict__ C, int ldc,
        __nv_bfloat16* __restrict__ Csplit) {
    extern __shared__ __align__(128) char smem[];
    const uint32_t sbase = (uint32_t)__cvta_generic_to_shared(smem);
    const int tid  = threadIdx.x;
    const int wid  = tid >> 5;
    const int lane = tid & 31;
    const int g    = lane >> 2;      // 0..7
    const int t    = lane & 3;       // 0..3
    const int wm   = wid & 1;        // 0..1 (M: 2 x 64)
    const int wn   = wid >> 1;       // 0..3 (N: 4 x 64)
    const int row0 = blockIdx.y * 128;
    const int col0 = blockIdx.x * 256;
    const int r8   = lane & 7;       // ldmatrix row within atom
    const int sub  = lane >> 3;      // ldmatrix atom id 0..3

    float acc[4][8][4];
    #pragma unroll
    for (int mi = 0; mi < 4; mi++)
        #pragma unroll
        for (int nj = 0; nj < 8; nj++)
            #pragma unroll
            for (int q = 0; q < 4; q++) acc[mi][nj][q] = 0.f;

    auto do_copy = [&](int c, int s) {
        char* sA = smem + s * STAGE;
        char* sB = sA + A_BYTES;
        int ak, bk;
        if (EPI == 1) {   // 6 term-pairs over compact [hi|mid|lo] blocks
            // A blocks per term: 0,0,1,0,1,2  B blocks: 0,1,0,2,1,0 (nibble-packed)
            int term = c >> 3, j = c & 7;
            ak = (int)((0x210100u >> (term * 4)) & 15u) * 256 + j * 32;
            bk = (int)((0x012010u >> (term * 4)) & 15u) * 256 + j * 32;
        } else {
            ak = c * 32; bk = c * 32;
        }
        #pragma unroll
        for (int i = 0; i < 6; i++) {
            int tt = tid + 256 * i;
            if (tt < 512) {                       // A: 128 rows x 4 x 16B
                int r = tt >> 2, kc = tt & 3;
                cp16(sA + r * (SM_PITCH * 2) + kc * 16,
                     A + (size_t)(row0 + r) * lda + ak + kc * 8);
            } else {                              // B: 256 rows x 4 x 16B
                int u = tt - 512;
                int r = u >> 2, kc = u & 3;
                cp16(sB + r * (SM_PITCH * 2) + kc * 16,
                     B + (size_t)(col0 + r) * ldb + bk + kc * 8);
            }
        }
        cp_commit();
    };

    do_copy(0, 0);
    for (int c = 0; c < KCH; c++) {
        const int s = c & 1;
        if (c + 1 < KCH) {
            do_copy(c + 1, s ^ 1);
            asm volatile("cp.async.wait_group 1;" ::: "memory");
        } else {
            asm volatile("cp.async.wait_group 0;" ::: "memory");
        }
        __syncthreads();

        const uint32_t sAu = sbase + s * STAGE;
        const uint32_t sBu = sAu + A_BYTES;
        #pragma unroll
        for (int k16 = 0; k16 < 2; k16++) {
            uint32_t af[4][4];
            {
                int arow = wm * 64 + (sub & 1) * 8 + r8;
                int akc  = k16 * 16 + (sub >> 1) * 8;
                #pragma unroll
                for (int mi = 0; mi < 4; mi++)
                    ldsm4(af[mi], sAu + ((arow + mi * 16) * SM_PITCH + akc) * 2);
            }
            uint32_t bf[4][4];
            {
                int bn  = wn * 64 + (sub >> 1) * 8 + r8;
                int bkc = k16 * 16 + (sub & 1) * 8;
                #pragma unroll
                for (int nj2 = 0; nj2 < 4; nj2++)
                    ldsm4(bf[nj2], sBu + ((bn + nj2 * 16) * SM_PITCH + bkc) * 2);
            }
            #pragma unroll
            for (int nj2 = 0; nj2 < 4; nj2++) {
                #pragma unroll
                for (int mi = 0; mi < 4; mi++) {
                    mma16816(acc[mi][2 * nj2],     af[mi], bf[nj2][0], bf[nj2][1]);
                    mma16816(acc[mi][2 * nj2 + 1], af[mi], bf[nj2][2], bf[nj2][3]);
                }
            }
        }
        __syncthreads();
    }

    // epilogue
    if (EPI == 2) {
        __half* Ck = (__half*)C;
        float en0[8], en1[8];
        #pragma unroll
        for (int nj = 0; nj < 8; nj++) {
            int col = col0 + wn * 64 + nj * 8 + t * 2;
            en0[nj] = g_enorm[col] - 170.f;
            en1[nj] = g_enorm[col + 1] - 170.f;
        }
        #pragma unroll
        for (int mi = 0; mi < 4; mi++) {
            #pragma unroll
            for (int nj = 0; nj < 8; nj++) {
                const float* cr = acc[mi][nj];
                int row = row0 + wm * 64 + mi * 16 + g;
                int col = col0 + wn * 64 + nj * 8 + t * 2;
                *(__half2*)(Ck + (size_t)row * ldc + col) =
                    __floats2half2_rn(en0[nj] - 2.f * cr[0], en1[nj] - 2.f * cr[1]);
                *(__half2*)(Ck + (size_t)(row + 8) * ldc + col) =
                    __floats2half2_rn(en0[nj] - 2.f * cr[2], en1[nj] - 2.f * cr[3]);
            }
        }
    } else {
        #pragma unroll
        for (int mi = 0; mi < 4; mi++) {
            #pragma unroll
            for (int nj = 0; nj < 8; nj++) {
                const float* cr = acc[mi][nj];
                int row = row0 + wm * 64 + mi * 16 + g;
                int col = col0 + wn * 64 + nj * 8 + t * 2;
                float bx = bias[col], by = bias[col + 1];
                float v0 = cr[0] + bx, v1 = cr[1] + by;
                float v2 = cr[2] + bx, v3 = cr[3] + by;
                *(float2*)(C + (size_t)row * ldc + col)       = make_float2(v0, v1);
                *(float2*)(C + (size_t)(row + 8) * ldc + col) = make_float2(v2, v3);
                __nv_bfloat162 hp0 = {__float2bfloat16(v0), __float2bfloat16(v1)};
                __nv_bfloat162 hp1 = {__float2bfloat16(v2), __float2bfloat16(v3)};
                *(__nv_bfloat162*)(Csplit + (size_t)row * 512 + col)       = hp0;
                *(__nv_bfloat162*)(Csplit + (size_t)(row + 8) * 512 + col) = hp1;
            }
        }
    }
}

// ---------------- per-row: approx select -> exact refine -> outputs ------------
__global__ void __launch_bounds__(256)
topk_kernel(const float* __restrict__ embed, float* __restrict__ out) {
    int w = threadIdx.x >> 5, lane = threadIdx.x & 31;
    int r = blockIdx.x * 8 + w;

    const float4* zr4 = (const float4*)(g_z + (size_t)r * DB);
    float4 zreg[4];
    float zn = 0.f;
    #pragma unroll
    for (int i = 0; i < 4; i++) {
        float4 v = zr4[lane + 32 * i];
        zreg[i] = v;
        zn += v.x * v.x + v.y * v.y + v.z * v.z + v.w * v.w;
    }
    #pragma unroll
    for (int o = 16; o; o >>= 1) zn += __shfl_xor_sync(0xffffffffu, zn, o);

    // --- pass 1: load keys to regs, per-lane min of packed keys ---
    // packed key = (monotone_u16(fp16) << 10) | idx  (lossless order, unique)
    const uint4* Dr = (const uint4*)(g_Dk + (size_t)r * NC);
    uint4 kv[4];
    uint32_t pmin = 0xFFFFFFFFu;
    #pragma unroll
    for (int it = 0; it < 4; it++) {
        kv[it] = Dr[lane + 32 * it];
        uint32_t c0 = (uint32_t)(lane + 32 * it) * 8;
        uint32_t p;
        p = (h2key(kv[it].x & 0xFFFFu) << 10) | (c0 + 0); pmin = min(pmin, p);
        p = (h2key(kv[it].x >> 16)     << 10) | (c0 + 1); pmin = min(pmin, p);
        p = (h2key(kv[it].y & 0xFFFFu) << 10) | (c0 + 2); pmin = min(pmin, p);
        p = (h2key(kv[it].y >> 16)     << 10) | (c0 + 3); pmin = min(pmin, p);
        p = (h2key(kv[it].z & 0xFFFFu) << 10) | (c0 + 4); pmin = min(pmin, p);
        p = (h2key(kv[it].z >> 16)     << 10) | (c0 + 5); pmin = min(pmin, p);
        p = (h2key(kv[it].w & 0xFFFFu) << 10) | (c0 + 6); pmin = min(pmin, p);
        p = (h2key(kv[it].w >> 16)     << 10) | (c0 + 7); pmin = min(pmin, p);
    }

    // --- threshold T = 12th smallest lane-min (>= 12th smallest item) ---
    uint32_t m = pmin, T = 0;
    #pragma unroll
    for (int j = 0; j < KSEL; j++) {
        uint32_t best = m;
        #pragma unroll
        for (int o = 16; o; o >>= 1)
            best = min(best, __shfl_xor_sync(0xffffffffu, best, o));
        T = best;
        if (m == best) m = 0xFFFFFFFFu;
    }

    // --- pass 2: collect items <= T into per-lane sorted list (cold path) ---
    uint32_t td[KSEL];
    #pragma unroll
    for (int j = 0; j < KSEL; j++) td[j] = 0xFFFFFFFFu;

    auto insert = [&](uint32_t key) {
        if (key <= T && key < td[KSEL - 1]) {
            #pragma unroll
            for (int j = KSEL - 1; j >= 0; j--) {
                bool shift = (j > 0) && (td[j - 1] > key);
                if (shift) td[j] = td[j - 1];
                else       { td[j] = key; break; }
            }
        }
    };

    #pragma unroll
    for (int it = 0; it < 4; it++) {
        uint32_t c0 = (uint32_t)(lane + 32 * it) * 8;
        insert((h2key(kv[it].x & 0xFFFFu) << 10) | (c0 + 0));
        insert((h2key(kv[it].x >> 16)     << 10) | (c0 + 1));
        insert((h2key(kv[it].y & 0xFFFFu) << 10) | (c0 + 2));
        insert((h2key(kv[it].y >> 16)     << 10) | (c0 + 3));
        insert((h2key(kv[it].z & 0xFFFFu) << 10) | (c0 + 4));
        insert((h2key(kv[it].z >> 16)     << 10) | (c0 + 5));
        insert((h2key(kv[it].w & 0xFFFFu) << 10) | (c0 + 6));
        insert((h2key(kv[it].w >> 16)     << 10) | (c0 + 7));
    }

    // --- warp merge: 12 rounds of u32 min (keys unique via idx bits) ---
    int ci[KSEL];
    int pos = 0;
    #pragma unroll
    for (int j = 0; j < KSEL; j++) {
        uint32_t cur = (pos < KSEL) ? td[pos] : 0xFFFFFFFFu;
        uint32_t best = cur;
        #pragma unroll
        for (int o = 16; o; o >>= 1)
            best = min(best, __shfl_xor_sync(0xffffffffu, best, o));
        ci[j] = (int)(best & 1023u);
        if (cur == best) pos++;
    }

    // --- exact fp32 refine: accumulate all 12 dots, then reduce (12-way ILP) ---
    float dot[KSEL];
    #pragma unroll
    for (int j = 0; j < KSEL; j++) dot[j] = 0.f;
    #pragma unroll
    for (int i = 0; i < 4; i++) {
        int c4 = lane + 32 * i;
        float4 zv = zreg[i];
        #pragma unroll
        for (int j = 0; j < KSEL; j++) {
            float4 f = ((const float4*)(embed + (size_t)ci[j] * DB))[c4];
            dot[j] += zv.x * f.x + zv.y * f.y + zv.z * f.z + zv.w * f.w;
        }
    }
    #pragma unroll
    for (int o = 16; o; o >>= 1) {
        #pragma unroll
        for (int j = 0; j < KSEL; j++)
            dot[j] += __shfl_xor_sync(0xffffffffu, dot[j], o);
    }
    float xd[KSEL];
    #pragma unroll
    for (int j = 0; j < KSEL; j++) xd[j] = zn + g_enorm[ci[j]] - 2.f * dot[j];

    // --- bubble sort (all lanes identical; tie -> smaller index) ---
    #pragma unroll
    for (int a = 0; a < KSEL - 1; a++) {
        #pragma unroll
        for (int b = 0; b < KSEL - 1 - a; b++) {
            bool sw = (xd[b + 1] < xd[b]) ||
                      (xd[b + 1] == xd[b] && ci[b + 1] < ci[b]);
            if (sw) {
                float tf = xd[b]; xd[b] = xd[b + 1]; xd[b + 1] = tf;
                int   tn = ci[b]; ci[b] = ci[b + 1]; ci[b + 1] = tn;
            }
        }
    }

    // --- softmax over exact sqrt(d2) of top-8 ---
    float wj[KTOP];
    float vmin = sqrtf(fmaxf(xd[0], 0.f));
    float wsum = 0.f;
    #pragma unroll
    for (int j = 0; j < KTOP; j++) {
        float v = sqrtf(fmaxf(xd[j], 0.f));
        wj[j] = expf(-(v - vmin) / TEMP);
        wsum += wj[j];
    }
    float inv = 1.f / wsum;
    #pragma unroll
    for (int j = 0; j < KTOP; j++) wj[j] *= inv;

    // --- q gather + vq partial ---
    float vql = 0.f;
    #pragma unroll
    for (int i = 0; i < 4; i++) {
        int c4 = lane + 32 * i;
        float4 a = make_float4(0.f, 0.f, 0.f, 0.f);
        #pragma unroll
        for (int j = 0; j < KTOP; j++) {
            const float4* ev = (const float4*)(embed + (size_t)ci[j] * DB);
            float4 f = ev[c4];
            a.x += wj[j] * f.x; a.y += wj[j] * f.y;
            a.z += wj[j] * f.z; a.w += wj[j] * f.w;
        }
        ((float4*)(out + (size_t)r * DB))[c4] = a;
        float dx = zreg[i].x - a.x, dy = zreg[i].y - a.y;
        float dz = zreg[i].z - a.z, dw = zreg[i].w - a.w;
        vql += dx * dx + dy * dy + dz * dz + dw * dw;
    }
    #pragma unroll
    for (int o = 16; o; o >>= 1) vql += __shfl_down_sync(0xffffffffu, vql, o);
    if (lane == 0) atomicAdd(&g_vq, vql);
    if (lane < KTOP) atomicAdd(&g_usage[ci[lane]], wj[lane]);
    if (lane == 0) out[(size_t)NROWS * DB + r] = (float)ci[0];
}

// ---------------- finalize scalars --------------------------------------------
__global__ void finalize_kernel(float* __restrict__ out) {
    __shared__ float sh[256];
    float s = 0.f;
    for (int c = threadIdx.x; c < NC; c += 256) {
        float u = g_usage[c] * (1.f / (float)NROWS);
        s += u * logf(u + 1e-8f);
    }
    sh[threadIdx.x] = s;
    __syncthreads();
    for (int o = 128; o; o >>= 1) {
        if (threadIdx.x < o) sh[threadIdx.x] += sh[threadIdx.x + o];
        __syncthreads();
    }
    if (threadIdx.x == 0) {
        size_t base = (size_t)NROWS * DB + NROWS;
        out[base + 0] = g_vq * (1.f / (float)((size_t)NROWS * DB));
        out[base + 1] = -sh[0];
    }
}

// ---------------- launch --------------------------------------------------------
extern "C" void kernel_launch(void* const* d_in, const int* in_sizes, int n_in,
                              void* d_out, int out_size) {
    const float* slots = (const float*)d_in[0];
    const float* W     = (const float*)d_in[1];
    const float* bias  = (const float*)d_in[2];
    const float* embed = (const float*)d_in[3];
    float* out = (float*)d_out;

    float* zp = nullptr;
    __half* dkp = nullptr;
    __nv_bfloat16 *asp = nullptr, *wbp = nullptr, *zsp = nullptr, *ebp = nullptr;
    cudaGetSymbolAddress((void**)&zp,  g_z);
    cudaGetSymbolAddress((void**)&dkp, g_Dk);
    cudaGetSymbolAddress((void**)&asp, g_as);
    cudaGetSymbolAddress((void**)&wbp, g_wb);
    cudaGetSymbolAddress((void**)&zsp, g_zs);
    cudaGetSymbolAddress((void**)&ebp, g_eb);

    cudaFuncSetAttribute(tc_gemm<48, 1>,
                         cudaFuncAttributeMaxDynamicSharedMemorySize, GEMM_SMEM);
    cudaFuncSetAttribute(tc_gemm<16, 2>,
                         cudaFuncAttributeMaxDynamicSharedMemorySize, GEMM_SMEM);

    split_slots_kernel<<<(NROWS * D_IN) / 256, 256>>>(slots);
    split_w_kernel<<<(D_IN * DB) / 256, 256>>>(W);
    init_kernel<<<128, 256>>>(embed);

    // z = slots @ W + b : 6-term mapped split over [hi|mid|lo] -> fp32 z + bf16 z_hi
    tc_gemm<48, 1><<<dim3(2, 128), 256, GEMM_SMEM>>>(
        asp, 768, wbp, 768, bias, zp, 512, zsp);

    // fp16 selection keys = enorm - 2*(z_hi . e_hi) - 170 : K = 512
    tc_gemm<16, 2><<<dim3(4, 128), 256, GEMM_SMEM>>>(
        zsp, 512, ebp, 512, nullptr, (float*)dkp, 1024, nullptr);

    topk_kernel<<<NROWS / 8, 256>>>(embed, out);
    finalize_kernel<<<1, 256>>>(out);
}

// round 12
// speedup vs baseline: 2.8573x; 1.0351x over previous
#include <cuda_runtime.h>
#include <cuda_bf16.h>
#include <cuda_fp16.h>
#include <math.h>
#include <float.h>
#include <stdint.h>

// Problem constants (fixed by the dataset)
#define NROWS 16384   // B*K = 256*64
#define D_IN  256
#define DB    512
#define NC    1024
#define KTOP  8
#define KSEL  12      // refine candidates
#define TEMP  0.1f

// ---------------- scratch (static device globals; no allocation) -------------
__device__ __align__(1024) __nv_bfloat16 g_as[(size_t)NROWS * 768];   // [hi|mid|lo]
__device__ __align__(1024) __nv_bfloat16 g_wb[(size_t)DB * 768];      // [hi|mid|lo]
__device__ __align__(1024) __nv_bfloat16 g_zs[(size_t)NROWS * 512];   // z_hi
__device__ __align__(1024) __nv_bfloat16 g_eb[(size_t)NC * 512];      // e_hi
__device__ __align__(1024) float  g_z[(size_t)NROWS * DB];   // fp32 z
__device__ __align__(1024) __half g_Dk[(size_t)NROWS * NC];  // fp16 selection keys
__device__ float g_enorm[NC];
__device__ float g_usage[NC];
__device__ float g_vq;

// ---------------- helpers -----------------------------------------------------
__device__ __forceinline__ void cp16(void* dst, const void* src) {
    uint32_t d = (uint32_t)__cvta_generic_to_shared(dst);
    asm volatile("cp.async.cg.shared.global [%0], [%1], 16;" :: "r"(d), "l"(src));
}
__device__ __forceinline__ void cp_commit() {
    asm volatile("cp.async.commit_group;" ::: "memory");
}
__device__ __forceinline__ void split3(float v, __nv_bfloat16& hi, __nv_bfloat16& mid,
                                       __nv_bfloat16& lo) {
    hi = __float2bfloat16(v);
    float r1 = v - __bfloat162float(hi);
    mid = __float2bfloat16(r1);
    lo = __float2bfloat16(r1 - __bfloat162float(mid));
}
__device__ __forceinline__ void mma16816(float* c, const uint32_t* a,
                                         uint32_t b0, uint32_t b1) {
    asm volatile(
        "mma.sync.aligned.m16n8k16.row.col.f32.bf16.bf16.f32 "
        "{%0,%1,%2,%3}, {%4,%5,%6,%7}, {%8,%9}, {%0,%1,%2,%3};"
        : "+f"(c[0]), "+f"(c[1]), "+f"(c[2]), "+f"(c[3])
        : "r"(a[0]), "r"(a[1]), "r"(a[2]), "r"(a[3]), "r"(b0), "r"(b1));
}
__device__ __forceinline__ void ldsm4(uint32_t* r, uint32_t addr) {
    asm volatile("ldmatrix.sync.aligned.m8n8.x4.shared.b16 {%0,%1,%2,%3}, [%4];"
        : "=r"(r[0]), "=r"(r[1]), "=r"(r[2]), "=r"(r[3]) : "r"(addr));
}
// monotone u16 map of an fp16 bit pattern (order-preserving total order)
__device__ __forceinline__ uint32_t h2key(uint32_t h16) {
    uint32_t neg = h16 >> 15;                 // 0 or 1
    return h16 ^ (0x8000u | (neg * 0x7FFFu)); // pos: +0x8000, neg: ^0xFFFF
}
// inverse of h2key: u16 key -> fp16 bits
__device__ __forceinline__ uint32_t key2h(uint32_t k16) {
    uint32_t pos = k16 >> 15;                 // 1 if original was >= 0
    return k16 ^ (pos ? 0x8000u : 0xFFFFu);
}

// ---------------- pre-kernels: splits + norms ---------------------------------
__global__ void split_slots_kernel(const float* __restrict__ slots) {
    int idx = blockIdx.x * 256 + threadIdx.x;       // < NROWS*D_IN
    int row = idx >> 8, k = idx & 255;
    __nv_bfloat16 hi, mid, lo;
    split3(slots[idx], hi, mid, lo);
    __nv_bfloat16* dst = g_as + (size_t)row * 768;
    dst[k] = hi;  dst[256 + k] = mid;  dst[512 + k] = lo;
}

__global__ void split_w_kernel(const float* __restrict__ W) {
    int idx = blockIdx.x * 256 + threadIdx.x;       // < D_IN*DB
    int k = idx >> 9, n = idx & 511;                // W[k,n] row-major
    __nv_bfloat16 hi, mid, lo;
    split3(W[idx], hi, mid, lo);
    __nv_bfloat16* dst = g_wb + (size_t)n * 768;
    dst[k] = hi;  dst[256 + k] = mid;  dst[512 + k] = lo;
}

__global__ void init_kernel(const float* __restrict__ embed) {
    int w = threadIdx.x >> 5, lane = threadIdx.x & 31;
    int code = blockIdx.x * 8 + w;
    if (code < NC) {
        const float* e = embed + (size_t)code * DB;
        __nv_bfloat16* dst = g_eb + (size_t)code * 512;
        float s = 0.f;
        #pragma unroll
        for (int i = lane; i < DB; i += 32) {
            float v = e[i];
            s += v * v;
            dst[i] = __float2bfloat16(v);
        }
        #pragma unroll
        for (int o = 16; o; o >>= 1) s += __shfl_down_sync(0xffffffffu, s, o);
        if (lane == 0) g_enorm[code] = s;
    }
    if (blockIdx.x == 0) {
        for (int i = threadIdx.x; i < NC; i += blockDim.x) g_usage[i] = 0.f;
        if (threadIdx.x == 0) g_vq = 0.f;
    }
}

// ---------------- bf16 mma.sync GEMM: C[M,N] = A[M,K'] * B[N,K']^T --------------
// Block 128x256, 8 warps (2m x 4n), warp tile 64x64, K-chunk 32, double buffer.
// EPI=1: 6-term split GEMM via nibble-mapped chunk offsets; +bias; fp32 C + z_hi.
// EPI=2: linear K; write fp16 key = enorm[col] - 2*acc - 170 (row-term dropped).
#define SM_PITCH 40
#define A_BYTES  (128 * SM_PITCH * 2)    // 10240
#define B_BYTES  (256 * SM_PITCH * 2)    // 20480
#define STAGE    (A_BYTES + B_BYTES)     // 30720
#define GEMM_SMEM (2 * STAGE)            // 61440

template<int KCH, int EPI>
__global__ void __launch_bounds__(256)
tc_gemm(const __nv_bfloat16* __restrict__ A, int lda,
        const __nv_bfloat16* __restrict__ B, int ldb,
        const float* __restrict__ bias,
        float* __restrict__ C, int ldc,
        __nv_bfloat16* __restrict__ Csplit) {
    extern __shared__ __align__(128) char smem[];
    const uint32_t sbase = (uint32_t)__cvta_generic_to_shared(smem);
    const int tid  = threadIdx.x;
    const int wid  = tid >> 5;
    const int lane = tid & 31;
    const int g    = lane >> 2;      // 0..7
    const int t    = lane & 3;       // 0..3
    const int wm   = wid & 1;        // 0..1 (M: 2 x 64)
    const int wn   = wid >> 1;       // 0..3 (N: 4 x 64)
    const int row0 = blockIdx.y * 128;
    const int col0 = blockIdx.x * 256;
    const int r8   = lane & 7;       // ldmatrix row within atom
    const int sub  = lane >> 3;      // ldmatrix atom id 0..3

    float acc[4][8][4];
    #pragma unroll
    for (int mi = 0; mi < 4; mi++)
        #pragma unroll
        for (int nj = 0; nj < 8; nj++)
            #pragma unroll
            for (int q = 0; q < 4; q++) acc[mi][nj][q] = 0.f;

    auto do_copy = [&](int c, int s) {
        char* sA = smem + s * STAGE;
        char* sB = sA + A_BYTES;
        int ak, bk;
        if (EPI == 1) {   // 6 term-pairs over compact [hi|mid|lo] blocks
            // A blocks per term: 0,0,1,0,1,2  B blocks: 0,1,0,2,1,0 (nibble-packed)
            int term = c >> 3, j = c & 7;
            ak = (int)((0x210100u >> (term * 4)) & 15u) * 256 + j * 32;
            bk = (int)((0x012010u >> (term * 4)) & 15u) * 256 + j * 32;
        } else {
            ak = c * 32; bk = c * 32;
        }
        #pragma unroll
        for (int i = 0; i < 6; i++) {
            int tt = tid + 256 * i;
            if (tt < 512) {                       // A: 128 rows x 4 x 16B
                int r = tt >> 2, kc = tt & 3;
                cp16(sA + r * (SM_PITCH * 2) + kc * 16,
                     A + (size_t)(row0 + r) * lda + ak + kc * 8);
            } else {                              // B: 256 rows x 4 x 16B
                int u = tt - 512;
                int r = u >> 2, kc = u & 3;
                cp16(sB + r * (SM_PITCH * 2) + kc * 16,
                     B + (size_t)(col0 + r) * ldb + bk + kc * 8);
            }
        }
        cp_commit();
    };

    do_copy(0, 0);
    for (int c = 0; c < KCH; c++) {
        const int s = c & 1;
        if (c + 1 < KCH) {
            do_copy(c + 1, s ^ 1);
            asm volatile("cp.async.wait_group 1;" ::: "memory");
        } else {
            asm volatile("cp.async.wait_group 0;" ::: "memory");
        }
        __syncthreads();

        const uint32_t sAu = sbase + s * STAGE;
        const uint32_t sBu = sAu + A_BYTES;
        #pragma unroll
        for (int k16 = 0; k16 < 2; k16++) {
            uint32_t af[4][4];
            {
                int arow = wm * 64 + (sub & 1) * 8 + r8;
                int akc  = k16 * 16 + (sub >> 1) * 8;
                #pragma unroll
                for (int mi = 0; mi < 4; mi++)
                    ldsm4(af[mi], sAu + ((arow + mi * 16) * SM_PITCH + akc) * 2);
            }
            uint32_t bf[4][4];
            {
                int bn  = wn * 64 + (sub >> 1) * 8 + r8;
                int bkc = k16 * 16 + (sub & 1) * 8;
                #pragma unroll
                for (int nj2 = 0; nj2 < 4; nj2++)
                    ldsm4(bf[nj2], sBu + ((bn + nj2 * 16) * SM_PITCH + bkc) * 2);
            }
            #pragma unroll
            for (int nj2 = 0; nj2 < 4; nj2++) {
                #pragma unroll
                for (int mi = 0; mi < 4; mi++) {
                    mma16816(acc[mi][2 * nj2],     af[mi], bf[nj2][0], bf[nj2][1]);
                    mma16816(acc[mi][2 * nj2 + 1], af[mi], bf[nj2][2], bf[nj2][3]);
                }
            }
        }
        __syncthreads();
    }

    // epilogue
    if (EPI == 2) {
        __half* Ck = (__half*)C;
        float en0[8], en1[8];
        #pragma unroll
        for (int nj = 0; nj < 8; nj++) {
            int col = col0 + wn * 64 + nj * 8 + t * 2;
            en0[nj] = g_enorm[col] - 170.f;
            en1[nj] = g_enorm[col + 1] - 170.f;
        }
        #pragma unroll
        for (int mi = 0; mi < 4; mi++) {
            #pragma unroll
            for (int nj = 0; nj < 8; nj++) {
                const float* cr = acc[mi][nj];
                int row = row0 + wm * 64 + mi * 16 + g;
                int col = col0 + wn * 64 + nj * 8 + t * 2;
                *(__half2*)(Ck + (size_t)row * ldc + col) =
                    __floats2half2_rn(en0[nj] - 2.f * cr[0], en1[nj] - 2.f * cr[1]);
                *(__half2*)(Ck + (size_t)(row + 8) * ldc + col) =
                    __floats2half2_rn(en0[nj] - 2.f * cr[2], en1[nj] - 2.f * cr[3]);
            }
        }
    } else {
        #pragma unroll
        for (int mi = 0; mi < 4; mi++) {
            #pragma unroll
            for (int nj = 0; nj < 8; nj++) {
                const float* cr = acc[mi][nj];
                int row = row0 + wm * 64 + mi * 16 + g;
                int col = col0 + wn * 64 + nj * 8 + t * 2;
                float bx = bias[col], by = bias[col + 1];
                float v0 = cr[0] + bx, v1 = cr[1] + by;
                float v2 = cr[2] + bx, v3 = cr[3] + by;
                *(float2*)(C + (size_t)row * ldc + col)       = make_float2(v0, v1);
                *(float2*)(C + (size_t)(row + 8) * ldc + col) = make_float2(v2, v3);
                __nv_bfloat162 hp0 = {__float2bfloat16(v0), __float2bfloat16(v1)};
                __nv_bfloat162 hp1 = {__float2bfloat16(v2), __float2bfloat16(v3)};
                *(__nv_bfloat162*)(Csplit + (size_t)row * 512 + col)       = hp0;
                *(__nv_bfloat162*)(Csplit + (size_t)(row + 8) * 512 + col) = hp1;
            }
        }
    }
}

// ---------------- per-row: approx select -> exact refine -> outputs ------------
__global__ void __launch_bounds__(256)
topk_kernel(const float* __restrict__ embed, float* __restrict__ out) {
    int w = threadIdx.x >> 5, lane = threadIdx.x & 31;
    int r = blockIdx.x * 8 + w;

    const float4* zr4 = (const float4*)(g_z + (size_t)r * DB);
    float4 zreg[4];
    float zn = 0.f;
    #pragma unroll
    for (int i = 0; i < 4; i++) {
        float4 v = zr4[lane + 32 * i];
        zreg[i] = v;
        zn += v.x * v.x + v.y * v.y + v.z * v.z + v.w * v.w;
    }
    #pragma unroll
    for (int o = 16; o; o >>= 1) zn += __shfl_xor_sync(0xffffffffu, zn, o);

    // --- pass 1: load keys; per-lane min VALUE via hmin2 tree (branch-free) ---
    const uint4* Dr = (const uint4*)(g_Dk + (size_t)r * NC);
    uint4 kv[4];
    #pragma unroll
    for (int it = 0; it < 4; it++) kv[it] = Dr[lane + 32 * it];

    __half2 m2 = *reinterpret_cast<__half2*>(&kv[0].x);
    #pragma unroll
    for (int it = 0; it < 4; it++) {
        __half2 a = *reinterpret_cast<__half2*>(&kv[it].x);
        __half2 b = *reinterpret_cast<__half2*>(&kv[it].y);
        __half2 c = *reinterpret_cast<__half2*>(&kv[it].z);
        __half2 d = *reinterpret_cast<__half2*>(&kv[it].w);
        m2 = __hmin2(m2, __hmin2(__hmin2(a, b), __hmin2(c, d)));
    }
    __half mv = __hmin(__low2half(m2), __high2half(m2));
    uint32_t laneKey = (h2key((uint32_t)__half_as_ushort(mv)) << 5) | (uint32_t)lane;

    // --- threshold: T16 = u16-key of 12th smallest lane-min ---
    uint32_t m = laneKey, T = 0;
    #pragma unroll
    for (int j = 0; j < KSEL; j++) {
        uint32_t best = m;
        #pragma unroll
        for (int o = 16; o; o >>= 1)
            best = min(best, __shfl_xor_sync(0xffffffffu, best, o));
        T = best;
        if (m == best) m = 0xFFFFFFFFu;
    }
    const uint32_t T16 = T >> 5;
    const uint32_t Tfull = (T16 << 10) | 1023u;
    const __half Th = __ushort_as_half((unsigned short)key2h(T16));

    // --- pass 2: group-filtered collect (8 items per hmin2 probe) ---
    uint32_t td[KSEL];
    #pragma unroll
    for (int j = 0; j < KSEL; j++) td[j] = 0xFFFFFFFFu;

    auto insert = [&](uint32_t key) {
        if (key <= Tfull && key < td[KSEL - 1]) {
            #pragma unroll
            for (int j = KSEL - 1; j >= 0; j--) {
                bool shift = (j > 0) && (td[j - 1] > key);
                if (shift) td[j] = td[j - 1];
                else       { td[j] = key; break; }
            }
        }
    };

    #pragma unroll
    for (int it = 0; it < 4; it++) {
        __half2 a = *reinterpret_cast<__half2*>(&kv[it].x);
        __half2 b = *reinterpret_cast<__half2*>(&kv[it].y);
        __half2 c = *reinterpret_cast<__half2*>(&kv[it].z);
        __half2 d = *reinterpret_cast<__half2*>(&kv[it].w);
        __half2 gm2 = __hmin2(__hmin2(a, b), __hmin2(c, d));
        __half gm = __hmin(__low2half(gm2), __high2half(gm2));
        if (__hle(gm, Th)) {                       // rare: group holds a candidate
            uint32_t c0 = (uint32_t)(lane + 32 * it) * 8;
            insert((h2key(kv[it].x & 0xFFFFu) << 10) | (c0 + 0));
            insert((h2key(kv[it].x >> 16)     << 10) | (c0 + 1));
            insert((h2key(kv[it].y & 0xFFFFu) << 10) | (c0 + 2));
            insert((h2key(kv[it].y >> 16)     << 10) | (c0 + 3));
            insert((h2key(kv[it].z & 0xFFFFu) << 10) | (c0 + 4));
            insert((h2key(kv[it].z >> 16)     << 10) | (c0 + 5));
            insert((h2key(kv[it].w & 0xFFFFu) << 10) | (c0 + 6));
            insert((h2key(kv[it].w >> 16)     << 10) | (c0 + 7));
        }
    }

    // --- warp merge: 12 rounds of u32 min (keys unique via idx bits) ---
    int ci[KSEL];
    int pos = 0;
    #pragma unroll
    for (int j = 0; j < KSEL; j++) {
        uint32_t cur = (pos < KSEL) ? td[pos] : 0xFFFFFFFFu;
        uint32_t best = cur;
        #pragma unroll
        for (int o = 16; o; o >>= 1)
            best = min(best, __shfl_xor_sync(0xffffffffu, best, o));
        ci[j] = (int)(best & 1023u);
        if (cur == best) pos++;
    }

    // --- exact fp32 refine: accumulate all 12 dots, then reduce (12-way ILP) ---
    float dot[KSEL];
    #pragma unroll
    for (int j = 0; j < KSEL; j++) dot[j] = 0.f;
    #pragma unroll
    for (int i = 0; i < 4; i++) {
        int c4 = lane + 32 * i;
        float4 zv = zreg[i];
        #pragma unroll
        for (int j = 0; j < KSEL; j++) {
            float4 f = ((const float4*)(embed + (size_t)ci[j] * DB))[c4];
            dot[j] += zv.x * f.x + zv.y * f.y + zv.z * f.z + zv.w * f.w;
        }
    }
    #pragma unroll
    for (int o = 16; o; o >>= 1) {
        #pragma unroll
        for (int j = 0; j < KSEL; j++)
            dot[j] += __shfl_xor_sync(0xffffffffu, dot[j], o);
    }
    float xd[KSEL];
    #pragma unroll
    for (int j = 0; j < KSEL; j++) xd[j] = zn + g_enorm[ci[j]] - 2.f * dot[j];

    // --- bubble sort (all lanes identical; tie -> smaller index) ---
    #pragma unroll
    for (int a = 0; a < KSEL - 1; a++) {
        #pragma unroll
        for (int b = 0; b < KSEL - 1 - a; b++) {
            bool sw = (xd[b + 1] < xd[b]) ||
                      (xd[b + 1] == xd[b] && ci[b + 1] < ci[b]);
            if (sw) {
                float tf = xd[b]; xd[b] = xd[b + 1]; xd[b + 1] = tf;
                int   tn = ci[b]; ci[b] = ci[b + 1]; ci[b + 1] = tn;
            }
        }
    }

    // --- softmax over exact sqrt(d2) of top-8 ---
    float wj[KTOP];
    float vmin = sqrtf(fmaxf(xd[0], 0.f));
    float wsum = 0.f;
    #pragma unroll
    for (int j = 0; j < KTOP; j++) {
        float v = sqrtf(fmaxf(xd[j], 0.f));
        wj[j] = expf(-(v - vmin) / TEMP);
        wsum += wj[j];
    }
    float inv = 1.f / wsum;
    #pragma unroll
    for (int j = 0; j < KTOP; j++) wj[j] *= inv;

    // --- q gather + vq partial ---
    float vql = 0.f;
    #pragma unroll
    for (int i = 0; i < 4; i++) {
        int c4 = lane + 32 * i;
        float4 a = make_float4(0.f, 0.f, 0.f, 0.f);
        #pragma unroll
        for (int j = 0; j < KTOP; j++) {
            const float4* ev = (const float4*)(embed + (size_t)ci[j] * DB);
            float4 f = ev[c4];
            a.x += wj[j] * f.x; a.y += wj[j] * f.y;
            a.z += wj[j] * f.z; a.w += wj[j] * f.w;
        }
        ((float4*)(out + (size_t)r * DB))[c4] = a;
        float dx = zreg[i].x - a.x, dy = zreg[i].y - a.y;
        float dz = zreg[i].z - a.z, dw = zreg[i].w - a.w;
        vql += dx * dx + dy * dy + dz * dz + dw * dw;
    }
    #pragma unroll
    for (int o = 16; o; o >>= 1) vql += __shfl_down_sync(0xffffffffu, vql, o);
    if (lane == 0) atomicAdd(&g_vq, vql);
    if (lane < KTOP) atomicAdd(&g_usage[ci[lane]], wj[lane]);
    if (lane == 0) out[(size_t)NROWS * DB + r] = (float)ci[0];
}

// ---------------- finalize scalars --------------------------------------------
__global__ void finalize_kernel(float* __restrict__ out) {
    __shared__ float sh[256];
    float s = 0.f;
    for (int c = threadIdx.x; c < NC; c += 256) {
        float u = g_usage[c] * (1.f / (float)NROWS);
        s += u * logf(u + 1e-8f);
    }
    sh[threadIdx.x] = s;
    __syncthreads();
    for (int o = 128; o; o >>= 1) {
        if (threadIdx.x < o) sh[threadIdx.x] += sh[threadIdx.x + o];
        __syncthreads();
    }
    if (threadIdx.x == 0) {
        size_t base = (size_t)NROWS * DB + NROWS;
        out[base + 0] = g_vq * (1.f / (float)((size_t)NROWS * DB));
        out[base + 1] = -sh[0];
    }
}

// ---------------- launch --------------------------------------------------------
extern "C" void kernel_launch(void* const* d_in, const int* in_sizes, int n_in,
                              void* d_out, int out_size) {
    const float* slots = (const float*)d_in[0];
    const float* W     = (const float*)d_in[1];
    const float* bias  = (const float*)d_in[2];
    const float* embed = (const float*)d_in[3];
    float* out = (float*)d_out;

    float* zp = nullptr;
    __half* dkp = nullptr;
    __nv_bfloat16 *asp = nullptr, *wbp = nullptr, *zsp = nullptr, *ebp = nullptr;
    cudaGetSymbolAddress((void**)&zp,  g_z);
    cudaGetSymbolAddress((void**)&dkp, g_Dk);
    cudaGetSymbolAddress((void**)&asp, g_as);
    cudaGetSymbolAddress((void**)&wbp, g_wb);
    cudaGetSymbolAddress((void**)&zsp, g_zs);
    cudaGetSymbolAddress((void**)&ebp, g_eb);

    cudaFuncSetAttribute(tc_gemm<48, 1>,
                         cudaFuncAttributeMaxDynamicSharedMemorySize, GEMM_SMEM);
    cudaFuncSetAttribute(tc_gemm<16, 2>,
                         cudaFuncAttributeMaxDynamicSharedMemorySize, GEMM_SMEM);

    split_slots_kernel<<<(NROWS * D_IN) / 256, 256>>>(slots);
    split_w_kernel<<<(D_IN * DB) / 256, 256>>>(W);
    init_kernel<<<128, 256>>>(embed);

    // z = slots @ W + b : 6-term mapped split over [hi|mid|lo] -> fp32 z + bf16 z_hi
    tc_gemm<48, 1><<<dim3(2, 128), 256, GEMM_SMEM>>>(
        asp, 768, wbp, 768, bias, zp, 512, zsp);

    // fp16 selection keys = enorm - 2*(z_hi . e_hi) - 170 : K = 512
    tc_gemm<16, 2><<<dim3(4, 128), 256, GEMM_SMEM>>>(
        zsp, 512, ebp, 512, nullptr, (float*)dkp, 1024, nullptr);

    topk_kernel<<<NROWS / 8, 256>>>(embed, out);
    finalize_kernel<<<1, 256>>>(out);
}

// round 13
// speedup vs baseline: 3.0551x; 1.0692x over previous
#include <cuda_runtime.h>
#include <cuda_bf16.h>
#include <cuda_fp16.h>
#include <math.h>
#include <float.h>
#include <stdint.h>

// Problem constants (fixed by the dataset)
#define NROWS 16384   // B*K = 256*64
#define D_IN  256
#define DB    512
#define NC    1024
#define KTOP  8
#define KSEL  12      // refine candidates
#define TEMP  0.1f

// ---------------- scratch (static device globals; no allocation) -------------
__device__ __align__(1024) __nv_bfloat16 g_as[(size_t)NROWS * 768];   // [hi|mid|lo]
__device__ __align__(1024) __nv_bfloat16 g_wb[(size_t)DB * 768];      // [hi|mid|lo]
__device__ __align__(1024) __nv_bfloat16 g_zs[(size_t)NROWS * 512];   // z_hi
__device__ __align__(1024) __nv_bfloat16 g_eb[(size_t)NC * 512];      // e_hi
__device__ __align__(1024) float  g_z[(size_t)NROWS * DB];   // fp32 z
__device__ __align__(1024) __half g_Dk[(size_t)NROWS * NC];  // fp16 selection keys
__device__ __align__(1024) uint2  g_sel[(size_t)NROWS * KTOP]; // (w bits, idx)
__device__ float g_enorm[NC];
__device__ float g_usage[NC];
__device__ float g_vq;

// ---------------- helpers -----------------------------------------------------
__device__ __forceinline__ void cp16(void* dst, const void* src) {
    uint32_t d = (uint32_t)__cvta_generic_to_shared(dst);
    asm volatile("cp.async.cg.shared.global [%0], [%1], 16;" :: "r"(d), "l"(src));
}
__device__ __forceinline__ void cp_commit() {
    asm volatile("cp.async.commit_group;" ::: "memory");
}
__device__ __forceinline__ void split3(float v, __nv_bfloat16& hi, __nv_bfloat16& mid,
                                       __nv_bfloat16& lo) {
    hi = __float2bfloat16(v);
    float r1 = v - __bfloat162float(hi);
    mid = __float2bfloat16(r1);
    lo = __float2bfloat16(r1 - __bfloat162float(mid));
}
__device__ __forceinline__ void mma16816(float* c, const uint32_t* a,
                                         uint32_t b0, uint32_t b1) {
    asm volatile(
        "mma.sync.aligned.m16n8k16.row.col.f32.bf16.bf16.f32 "
        "{%0,%1,%2,%3}, {%4,%5,%6,%7}, {%8,%9}, {%0,%1,%2,%3};"
        : "+f"(c[0]), "+f"(c[1]), "+f"(c[2]), "+f"(c[3])
        : "r"(a[0]), "r"(a[1]), "r"(a[2]), "r"(a[3]), "r"(b0), "r"(b1));
}
__device__ __forceinline__ void ldsm4(uint32_t* r, uint32_t addr) {
    asm volatile("ldmatrix.sync.aligned.m8n8.x4.shared.b16 {%0,%1,%2,%3}, [%4];"
        : "=r"(r[0]), "=r"(r[1]), "=r"(r[2]), "=r"(r[3]) : "r"(addr));
}
// monotone u16 map of an fp16 bit pattern (order-preserving total order)
__device__ __forceinline__ uint32_t h2key(uint32_t h16) {
    uint32_t neg = h16 >> 15;
    return h16 ^ (0x8000u | (neg * 0x7FFFu));
}
// inverse of h2key: u16 key -> fp16 bits
__device__ __forceinline__ uint32_t key2h(uint32_t k16) {
    uint32_t pos = k16 >> 15;
    return k16 ^ (pos ? 0x8000u : 0xFFFFu);
}

// ---------------- pre-kernels: splits + norms ---------------------------------
__global__ void split_slots_kernel(const float* __restrict__ slots) {
    int idx = blockIdx.x * 256 + threadIdx.x;
    int row = idx >> 8, k = idx & 255;
    __nv_bfloat16 hi, mid, lo;
    split3(slots[idx], hi, mid, lo);
    __nv_bfloat16* dst = g_as + (size_t)row * 768;
    dst[k] = hi;  dst[256 + k] = mid;  dst[512 + k] = lo;
}

__global__ void split_w_kernel(const float* __restrict__ W) {
    int idx = blockIdx.x * 256 + threadIdx.x;
    int k = idx >> 9, n = idx & 511;
    __nv_bfloat16 hi, mid, lo;
    split3(W[idx], hi, mid, lo);
    __nv_bfloat16* dst = g_wb + (size_t)n * 768;
    dst[k] = hi;  dst[256 + k] = mid;  dst[512 + k] = lo;
}

__global__ void init_kernel(const float* __restrict__ embed) {
    int w = threadIdx.x >> 5, lane = threadIdx.x & 31;
    int code = blockIdx.x * 8 + w;
    if (code < NC) {
        const float* e = embed + (size_t)code * DB;
        __nv_bfloat16* dst = g_eb + (size_t)code * 512;
        float s = 0.f;
        #pragma unroll
        for (int i = lane; i < DB; i += 32) {
            float v = e[i];
            s += v * v;
            dst[i] = __float2bfloat16(v);
        }
        #pragma unroll
        for (int o = 16; o; o >>= 1) s += __shfl_down_sync(0xffffffffu, s, o);
        if (lane == 0) g_enorm[code] = s;
    }
    if (blockIdx.x == 0) {
        for (int i = threadIdx.x; i < NC; i += blockDim.x) g_usage[i] = 0.f;
        if (threadIdx.x == 0) g_vq = 0.f;
    }
}

// ---------------- bf16 mma.sync GEMM: C[M,N] = A[M,K'] * B[N,K']^T --------------
#define SM_PITCH 40
#define A_BYTES  (128 * SM_PITCH * 2)
#define B_BYTES  (256 * SM_PITCH * 2)
#define STAGE    (A_BYTES + B_BYTES)
#define GEMM_SMEM (2 * STAGE)

template<int KCH, int EPI>
__global__ void __launch_bounds__(256)
tc_gemm(const __nv_bfloat16* __restrict__ A, int lda,
        const __nv_bfloat16* __restrict__ B, int ldb,
        const float* __restrict__ bias,
        float* __restrict__ C, int ldc,
        __nv_bfloat16* __restrict__ Csplit) {
    extern __shared__ __align__(128) char smem[];
    const uint32_t sbase = (uint32_t)__cvta_generic_to_shared(smem);
    const int tid  = threadIdx.x;
    const int wid  = tid >> 5;
    const int lane = tid & 31;
    const int g    = lane >> 2;
    const int t    = lane & 3;
    const int wm   = wid & 1;
    const int wn   = wid >> 1;
    const int row0 = blockIdx.y * 128;
    const int col0 = blockIdx.x * 256;
    const int r8   = lane & 7;
    const int sub  = lane >> 3;

    float acc[4][8][4];
    #pragma unroll
    for (int mi = 0; mi < 4; mi++)
        #pragma unroll
        for (int nj = 0; nj < 8; nj++)
            #pragma unroll
            for (int q = 0; q < 4; q++) acc[mi][nj][q] = 0.f;

    auto do_copy = [&](int c, int s) {
        char* sA = smem + s * STAGE;
        char* sB = sA + A_BYTES;
        int ak, bk;
        if (EPI == 1) {
            int term = c >> 3, j = c & 7;
            ak = (int)((0x210100u >> (term * 4)) & 15u) * 256 + j * 32;
            bk = (int)((0x012010u >> (term * 4)) & 15u) * 256 + j * 32;
        } else {
            ak = c * 32; bk = c * 32;
        }
        #pragma unroll
        for (int i = 0; i < 6; i++) {
            int tt = tid + 256 * i;
            if (tt < 512) {
                int r = tt >> 2, kc = tt & 3;
                cp16(sA + r * (SM_PITCH * 2) + kc * 16,
                     A + (size_t)(row0 + r) * lda + ak + kc * 8);
            } else {
                int u = tt - 512;
                int r = u >> 2, kc = u & 3;
                cp16(sB + r * (SM_PITCH * 2) + kc * 16,
                     B + (size_t)(col0 + r) * ldb + bk + kc * 8);
            }
        }
        cp_commit();
    };

    do_copy(0, 0);
    for (int c = 0; c < KCH; c++) {
        const int s = c & 1;
        if (c + 1 < KCH) {
            do_copy(c + 1, s ^ 1);
            asm volatile("cp.async.wait_group 1;" ::: "memory");
        } else {
            asm volatile("cp.async.wait_group 0;" ::: "memory");
        }
        __syncthreads();

        const uint32_t sAu = sbase + s * STAGE;
        const uint32_t sBu = sAu + A_BYTES;
        #pragma unroll
        for (int k16 = 0; k16 < 2; k16++) {
            uint32_t af[4][4];
            {
                int arow = wm * 64 + (sub & 1) * 8 + r8;
                int akc  = k16 * 16 + (sub >> 1) * 8;
                #pragma unroll
                for (int mi = 0; mi < 4; mi++)
                    ldsm4(af[mi], sAu + ((arow + mi * 16) * SM_PITCH + akc) * 2);
            }
            uint32_t bf[4][4];
            {
                int bn  = wn * 64 + (sub >> 1) * 8 + r8;
                int bkc = k16 * 16 + (sub & 1) * 8;
                #pragma unroll
                for (int nj2 = 0; nj2 < 4; nj2++)
                    ldsm4(bf[nj2], sBu + ((bn + nj2 * 16) * SM_PITCH + bkc) * 2);
            }
            #pragma unroll
            for (int nj2 = 0; nj2 < 4; nj2++) {
                #pragma unroll
                for (int mi = 0; mi < 4; mi++) {
                    mma16816(acc[mi][2 * nj2],     af[mi], bf[nj2][0], bf[nj2][1]);
                    mma16816(acc[mi][2 * nj2 + 1], af[mi], bf[nj2][2], bf[nj2][3]);
                }
            }
        }
        __syncthreads();
    }

    if (EPI == 2) {
        __half* Ck = (__half*)C;
        float en0[8], en1[8];
        #pragma unroll
        for (int nj = 0; nj < 8; nj++) {
            int col = col0 + wn * 64 + nj * 8 + t * 2;
            en0[nj] = g_enorm[col] - 170.f;
            en1[nj] = g_enorm[col + 1] - 170.f;
        }
        #pragma unroll
        for (int mi = 0; mi < 4; mi++) {
            #pragma unroll
            for (int nj = 0; nj < 8; nj++) {
                const float* cr = acc[mi][nj];
                int row = row0 + wm * 64 + mi * 16 + g;
                int col = col0 + wn * 64 + nj * 8 + t * 2;
                *(__half2*)(Ck + (size_t)row * ldc + col) =
                    __floats2half2_rn(en0[nj] - 2.f * cr[0], en1[nj] - 2.f * cr[1]);
                *(__half2*)(Ck + (size_t)(row + 8) * ldc + col) =
                    __floats2half2_rn(en0[nj] - 2.f * cr[2], en1[nj] - 2.f * cr[3]);
            }
        }
    } else {
        #pragma unroll
        for (int mi = 0; mi < 4; mi++) {
            #pragma unroll
            for (int nj = 0; nj < 8; nj++) {
                const float* cr = acc[mi][nj];
                int row = row0 + wm * 64 + mi * 16 + g;
                int col = col0 + wn * 64 + nj * 8 + t * 2;
                float bx = bias[col], by = bias[col + 1];
                float v0 = cr[0] + bx, v1 = cr[1] + by;
                float v2 = cr[2] + bx, v3 = cr[3] + by;
                *(float2*)(C + (size_t)row * ldc + col)       = make_float2(v0, v1);
                *(float2*)(C + (size_t)(row + 8) * ldc + col) = make_float2(v2, v3);
                __nv_bfloat162 hp0 = {__float2bfloat16(v0), __float2bfloat16(v1)};
                __nv_bfloat162 hp1 = {__float2bfloat16(v2), __float2bfloat16(v3)};
                *(__nv_bfloat162*)(Csplit + (size_t)row * 512 + col)       = hp0;
                *(__nv_bfloat162*)(Csplit + (size_t)(row + 8) * 512 + col) = hp1;
            }
        }
    }
}

// ---------------- kernel A: select -> exact refine -> sort -> weights ----------
__global__ void __launch_bounds__(256)
select_kernel(const float* __restrict__ embed, float* __restrict__ out) {
    int w = threadIdx.x >> 5, lane = threadIdx.x & 31;
    int r = blockIdx.x * 8 + w;

    const float4* zr4 = (const float4*)(g_z + (size_t)r * DB);
    float4 zreg[4];
    float zn = 0.f;
    #pragma unroll
    for (int i = 0; i < 4; i++) {
        float4 v = zr4[lane + 32 * i];
        zreg[i] = v;
        zn += v.x * v.x + v.y * v.y + v.z * v.z + v.w * v.w;
    }
    #pragma unroll
    for (int o = 16; o; o >>= 1) zn += __shfl_xor_sync(0xffffffffu, zn, o);

    // pass 1: per-lane min via hmin2 tree
    const uint4* Dr = (const uint4*)(g_Dk + (size_t)r * NC);
    uint4 kv[4];
    #pragma unroll
    for (int it = 0; it < 4; it++) kv[it] = Dr[lane + 32 * it];

    __half2 m2 = *reinterpret_cast<__half2*>(&kv[0].x);
    #pragma unroll
    for (int it = 0; it < 4; it++) {
        __half2 a = *reinterpret_cast<__half2*>(&kv[it].x);
        __half2 b = *reinterpret_cast<__half2*>(&kv[it].y);
        __half2 c = *reinterpret_cast<__half2*>(&kv[it].z);
        __half2 d = *reinterpret_cast<__half2*>(&kv[it].w);
        m2 = __hmin2(m2, __hmin2(__hmin2(a, b), __hmin2(c, d)));
    }
    __half mv = __hmin(__low2half(m2), __high2half(m2));
    uint32_t laneKey = (h2key((uint32_t)__half_as_ushort(mv)) << 5) | (uint32_t)lane;

    // threshold T16 = u16-key of 12th smallest lane-min
    uint32_t m = laneKey, T = 0;
    #pragma unroll
    for (int j = 0; j < KSEL; j++) {
        uint32_t best = m;
        #pragma unroll
        for (int o = 16; o; o >>= 1)
            best = min(best, __shfl_xor_sync(0xffffffffu, best, o));
        T = best;
        if (m == best) m = 0xFFFFFFFFu;
    }
    const uint32_t T16 = T >> 5;
    const uint32_t Tfull = (T16 << 10) | 1023u;
    const __half Th = __ushort_as_half((unsigned short)key2h(T16));

    // pass 2: group-filtered collect
    uint32_t td[KSEL];
    #pragma unroll
    for (int j = 0; j < KSEL; j++) td[j] = 0xFFFFFFFFu;

    auto insert = [&](uint32_t key) {
        if (key <= Tfull && key < td[KSEL - 1]) {
            #pragma unroll
            for (int j = KSEL - 1; j >= 0; j--) {
                bool shift = (j > 0) && (td[j - 1] > key);
                if (shift) td[j] = td[j - 1];
                else       { td[j] = key; break; }
            }
        }
    };

    #pragma unroll
    for (int it = 0; it < 4; it++) {
        __half2 a = *reinterpret_cast<__half2*>(&kv[it].x);
        __half2 b = *reinterpret_cast<__half2*>(&kv[it].y);
        __half2 c = *reinterpret_cast<__half2*>(&kv[it].z);
        __half2 d = *reinterpret_cast<__half2*>(&kv[it].w);
        __half2 gm2 = __hmin2(__hmin2(a, b), __hmin2(c, d));
        __half gm = __hmin(__low2half(gm2), __high2half(gm2));
        if (__hle(gm, Th)) {
            uint32_t c0 = (uint32_t)(lane + 32 * it) * 8;
            insert((h2key(kv[it].x & 0xFFFFu) << 10) | (c0 + 0));
            insert((h2key(kv[it].x >> 16)     << 10) | (c0 + 1));
            insert((h2key(kv[it].y & 0xFFFFu) << 10) | (c0 + 2));
            insert((h2key(kv[it].y >> 16)     << 10) | (c0 + 3));
            insert((h2key(kv[it].z & 0xFFFFu) << 10) | (c0 + 4));
            insert((h2key(kv[it].z >> 16)     << 10) | (c0 + 5));
            insert((h2key(kv[it].w & 0xFFFFu) << 10) | (c0 + 6));
            insert((h2key(kv[it].w >> 16)     << 10) | (c0 + 7));
        }
    }

    // warp merge
    int ci[KSEL];
    int pos = 0;
    #pragma unroll
    for (int j = 0; j < KSEL; j++) {
        uint32_t cur = (pos < KSEL) ? td[pos] : 0xFFFFFFFFu;
        uint32_t best = cur;
        #pragma unroll
        for (int o = 16; o; o >>= 1)
            best = min(best, __shfl_xor_sync(0xffffffffu, best, o));
        ci[j] = (int)(best & 1023u);
        if (cur == best) pos++;
    }

    // exact fp32 refine
    float dot[KSEL];
    #pragma unroll
    for (int j = 0; j < KSEL; j++) dot[j] = 0.f;
    #pragma unroll
    for (int i = 0; i < 4; i++) {
        int c4 = lane + 32 * i;
        float4 zv = zreg[i];
        #pragma unroll
        for (int j = 0; j < KSEL; j++) {
            float4 f = ((const float4*)(embed + (size_t)ci[j] * DB))[c4];
            dot[j] += zv.x * f.x + zv.y * f.y + zv.z * f.z + zv.w * f.w;
        }
    }
    #pragma unroll
    for (int o = 16; o; o >>= 1) {
        #pragma unroll
        for (int j = 0; j < KSEL; j++)
            dot[j] += __shfl_xor_sync(0xffffffffu, dot[j], o);
    }
    float xd[KSEL];
    #pragma unroll
    for (int j = 0; j < KSEL; j++) xd[j] = zn + g_enorm[ci[j]] - 2.f * dot[j];

    // bubble sort (all lanes identical; tie -> smaller index)
    #pragma unroll
    for (int a = 0; a < KSEL - 1; a++) {
        #pragma unroll
        for (int b = 0; b < KSEL - 1 - a; b++) {
            bool sw = (xd[b + 1] < xd[b]) ||
                      (xd[b + 1] == xd[b] && ci[b + 1] < ci[b]);
            if (sw) {
                float tf = xd[b]; xd[b] = xd[b + 1]; xd[b + 1] = tf;
                int   tn = ci[b]; ci[b] = ci[b + 1]; ci[b + 1] = tn;
            }
        }
    }

    // softmax over exact sqrt(d2) of top-8
    float wj[KTOP];
    float vmin = sqrtf(fmaxf(xd[0], 0.f));
    float wsum = 0.f;
    #pragma unroll
    for (int j = 0; j < KTOP; j++) {
        float v = sqrtf(fmaxf(xd[j], 0.f));
        wj[j] = expf(-(v - vmin) / TEMP);
        wsum += wj[j];
    }
    float inv = 1.f / wsum;
    #pragma unroll
    for (int j = 0; j < KTOP; j++) wj[j] *= inv;

    // lane j<8 emits (w_j, idx_j); usage atomics; top-1 index
    float wv = wj[0]; int iv = ci[0];
    #pragma unroll
    for (int j = 1; j < KTOP; j++) {
        if (lane == j) { wv = wj[j]; iv = ci[j]; }
    }
    if (lane < KTOP) {
        g_sel[(size_t)r * KTOP + lane] = make_uint2(__float_as_uint(wv), (uint32_t)iv);
        atomicAdd(&g_usage[iv], wv);
    }
    if (lane == 0) out[(size_t)NROWS * DB + r] = (float)ci[0];
}

// ---------------- kernel B: q gather + vq --------------------------------------
__global__ void __launch_bounds__(256)
gather_kernel(const float* __restrict__ embed, float* __restrict__ out) {
    int w = threadIdx.x >> 5, lane = threadIdx.x & 31;
    int r = blockIdx.x * 8 + w;

    uint2 p = make_uint2(0, 0);
    if (lane < KTOP) p = g_sel[(size_t)r * KTOP + lane];
    float wv = __uint_as_float(p.x);
    int   iv = (int)p.y;

    float w8[KTOP]; int i8[KTOP];
    #pragma unroll
    for (int j = 0; j < KTOP; j++) {
        w8[j] = __shfl_sync(0xffffffffu, wv, j);
        i8[j] = __shfl_sync(0xffffffffu, iv, j);
    }

    const float4* zr4 = (const float4*)(g_z + (size_t)r * DB);
    float vql = 0.f;
    #pragma unroll
    for (int i = 0; i < 4; i++) {
        int c4 = lane + 32 * i;
        float4 a = make_float4(0.f, 0.f, 0.f, 0.f);
        #pragma unroll
        for (int j = 0; j < KTOP; j++) {
            float4 f = ((const float4*)(embed + (size_t)i8[j] * DB))[c4];
            a.x += w8[j] * f.x; a.y += w8[j] * f.y;
            a.z += w8[j] * f.z; a.w += w8[j] * f.w;
        }
        ((float4*)(out + (size_t)r * DB))[c4] = a;
        float4 zv = zr4[c4];
        float dx = zv.x - a.x, dy = zv.y - a.y;
        float dz = zv.z - a.z, dw = zv.w - a.w;
        vql += dx * dx + dy * dy + dz * dz + dw * dw;
    }
    #pragma unroll
    for (int o = 16; o; o >>= 1) vql += __shfl_down_sync(0xffffffffu, vql, o);
    if (lane == 0) atomicAdd(&g_vq, vql);
}

// ---------------- finalize scalars --------------------------------------------
__global__ void finalize_kernel(float* __restrict__ out) {
    __shared__ float sh[256];
    float s = 0.f;
    for (int c = threadIdx.x; c < NC; c += 256) {
        float u = g_usage[c] * (1.f / (float)NROWS);
        s += u * logf(u + 1e-8f);
    }
    sh[threadIdx.x] = s;
    __syncthreads();
    for (int o = 128; o; o >>= 1) {
        if (threadIdx.x < o) sh[threadIdx.x] += sh[threadIdx.x + o];
        __syncthreads();
    }
    if (threadIdx.x == 0) {
        size_t base = (size_t)NROWS * DB + NROWS;
        out[base + 0] = g_vq * (1.f / (float)((size_t)NROWS * DB));
        out[base + 1] = -sh[0];
    }
}

// ---------------- launch --------------------------------------------------------
extern "C" void kernel_launch(void* const* d_in, const int* in_sizes, int n_in,
                              void* d_out, int out_size) {
    const float* slots = (const float*)d_in[0];
    const float* W     = (const float*)d_in[1];
    const float* bias  = (const float*)d_in[2];
    const float* embed = (const float*)d_in[3];
    float* out = (float*)d_out;

    float* zp = nullptr;
    __half* dkp = nullptr;
    __nv_bfloat16 *asp = nullptr, *wbp = nullptr, *zsp = nullptr, *ebp = nullptr;
    cudaGetSymbolAddress((void**)&zp,  g_z);
    cudaGetSymbolAddress((void**)&dkp, g_Dk);
    cudaGetSymbolAddress((void**)&asp, g_as);
    cudaGetSymbolAddress((void**)&wbp, g_wb);
    cudaGetSymbolAddress((void**)&zsp, g_zs);
    cudaGetSymbolAddress((void**)&ebp, g_eb);

    cudaFuncSetAttribute(tc_gemm<48, 1>,
                         cudaFuncAttributeMaxDynamicSharedMemorySize, GEMM_SMEM);
    cudaFuncSetAttribute(tc_gemm<16, 2>,
                         cudaFuncAttributeMaxDynamicSharedMemorySize, GEMM_SMEM);

    split_slots_kernel<<<(NROWS * D_IN) / 256, 256>>>(slots);
    split_w_kernel<<<(D_IN * DB) / 256, 256>>>(W);
    init_kernel<<<128, 256>>>(embed);

    // z = slots @ W + b : 6-term mapped split over [hi|mid|lo] -> fp32 z + bf16 z_hi
    tc_gemm<48, 1><<<dim3(2, 128), 256, GEMM_SMEM>>>(
        asp, 768, wbp, 768, bias, zp, 512, zsp);

    // fp16 selection keys = enorm - 2*(z_hi . e_hi) - 170 : K = 512
    tc_gemm<16, 2><<<dim3(4, 128), 256, GEMM_SMEM>>>(
        zsp, 512, ebp, 512, nullptr, (float*)dkp, 1024, nullptr);

    select_kernel<<<NROWS / 8, 256>>>(embed, out);
    gather_kernel<<<NROWS / 8, 256>>>(embed, out);
    finalize_kernel<<<1, 256>>>(out);
}